// round 1
// baseline (speedup 1.0000x reference)
#include <cuda_runtime.h>
#include <math.h>

#define NS 100     // stocks
#define ND 20      // days
#define NT 30      // texts per day
#define HH 64      // hidden
#define GG 192     // 3*H
#define NHD 8      // GAT heads
#define FT 512     // text feature
#define FP 3       // price feature
#define MROWS 600  // ND*NT

// ---------------- scratch (device globals; no runtime allocation) ----------------
__device__ float g_gi[(size_t)NS * MROWS * GG];   // text GRU input projections [S,600,192] (~46MB)
__device__ float g_news[NS * ND * HH];            // per-day text vectors
__device__ float g_pvec[NS * HH];                 // price_vec
__device__ float g_tvec[NS * HH];                 // text_vec
__device__ float g_feat[NS * HH];                 // bilinear feature
__device__ float g_hgat[NHD * NS * HH];           // GAT head projections
__device__ float g_f1[NHD * NS];
__device__ float g_f2[NHD * NS];
__device__ float g_x2[NS * NHD * HH];             // concat of heads [S, 512]

__device__ __forceinline__ float sigmoidf_(float x) { return 1.f / (1.f + expf(-x)); }

// ============================================================================
// Kernel 1: batched GEMM   g_gi[s,m,g] = text[s,m,:] . tg_Wih[s,g,:] + tg_bih[s,g]
//   A: [S, 600, 512] row-major (K contiguous), W: [S, 192, 512] (K contiguous)
//   64x64 tile, ktile=16, 256 threads, 4x4 micro-tile, smem stored [k][mn] for LDS.128
// ============================================================================
__global__ __launch_bounds__(256) void k_text_gemm(
    const float* __restrict__ A, const float* __restrict__ W,
    const float* __restrict__ bih)
{
    const int s  = blockIdx.z;
    const int m0 = blockIdx.x * 64;   // 10 blocks over 600
    const int n0 = blockIdx.y * 64;   // 3 blocks over 192
    const float* Ab = A + (size_t)s * MROWS * FT;
    const float* Wb = W + (size_t)s * GG * FT;

    __shared__ float As[16][68];
    __shared__ float Bs[16][68];

    const int tid  = threadIdx.x;
    const int tx   = tid & 15;
    const int ty   = tid >> 4;
    const int lrow = tid >> 2;          // 0..63
    const int lk   = (tid & 3) * 4;     // 0,4,8,12

    float acc[4][4];
#pragma unroll
    for (int i = 0; i < 4; i++)
#pragma unroll
        for (int j = 0; j < 4; j++) acc[i][j] = 0.f;

    for (int k0 = 0; k0 < FT; k0 += 16) {
        const int am = m0 + lrow;
        float4 av = make_float4(0.f, 0.f, 0.f, 0.f);
        if (am < MROWS) av = *(const float4*)(Ab + (size_t)am * FT + k0 + lk);
        As[lk + 0][lrow] = av.x; As[lk + 1][lrow] = av.y;
        As[lk + 2][lrow] = av.z; As[lk + 3][lrow] = av.w;

        const float4 bv = *(const float4*)(Wb + (size_t)(n0 + lrow) * FT + k0 + lk);
        Bs[lk + 0][lrow] = bv.x; Bs[lk + 1][lrow] = bv.y;
        Bs[lk + 2][lrow] = bv.z; Bs[lk + 3][lrow] = bv.w;
        __syncthreads();

#pragma unroll
        for (int kk = 0; kk < 16; kk++) {
            const float4 a4 = *(const float4*)&As[kk][ty * 4];
            const float4 b4 = *(const float4*)&Bs[kk][tx * 4];
            const float aa[4] = { a4.x, a4.y, a4.z, a4.w };
            const float bb[4] = { b4.x, b4.y, b4.z, b4.w };
#pragma unroll
            for (int i = 0; i < 4; i++)
#pragma unroll
                for (int j = 0; j < 4; j++) acc[i][j] = fmaf(aa[i], bb[j], acc[i][j]);
        }
        __syncthreads();
    }

#pragma unroll
    for (int i = 0; i < 4; i++) {
        const int m = m0 + ty * 4 + i;
        if (m < MROWS) {
#pragma unroll
            for (int j = 0; j < 4; j++) {
                const int n = n0 + tx * 4 + j;
                g_gi[((size_t)s * MROWS + m) * GG + n] = acc[i][j] + bih[s * GG + n];
            }
        }
    }
}

// ============================================================================
// Attention pool (device helper): softmax_t( tanh(outs @ Wa) . h_last ) @ outs
//   block has 192 threads (6 warps). sc: smem scratch [32].
// ============================================================================
template <int STEPS>
__device__ __forceinline__ void pool_store(
    float (*outs)[HH], const float* hs, const float* __restrict__ wa,
    float* sc, float* __restrict__ dst)
{
    const int tid  = threadIdx.x;
    const int warp = tid >> 5;
    const int lane = tid & 31;
    const int nw   = blockDim.x >> 5;

    for (int t = warp; t < STEPS; t += nw) {
        float part = 0.f;
        for (int j = lane; j < HH; j += 32) {
            float a = 0.f;
#pragma unroll 8
            for (int i = 0; i < HH; i++) a = fmaf(outs[t][i], wa[i * HH + j], a);
            part = fmaf(tanhf(a), hs[j], part);
        }
#pragma unroll
        for (int o = 16; o; o >>= 1) part += __shfl_xor_sync(0xffffffffu, part, o);
        if (lane == 0) sc[t] = part;
    }
    __syncthreads();
    if (warp == 0) {
        const float v = (lane < STEPS) ? sc[lane] : -3.4e38f;
        float m = v;
#pragma unroll
        for (int o = 16; o; o >>= 1) m = fmaxf(m, __shfl_xor_sync(0xffffffffu, m, o));
        const float e = (lane < STEPS) ? expf(v - m) : 0.f;
        float su = e;
#pragma unroll
        for (int o = 16; o; o >>= 1) su += __shfl_xor_sync(0xffffffffu, su, o);
        if (lane < STEPS) sc[lane] = e / su;
    }
    __syncthreads();
    if (tid < HH) {
        float a = 0.f;
#pragma unroll
        for (int t = 0; t < STEPS; t++) a = fmaf(sc[t], outs[t][tid], a);
        dst[tid] = a;
    }
}

// ============================================================================
// Kernel 2: text GRU recurrence + pool. One block per (stock, day). 192 threads.
//   gi comes precomputed from g_gi; Whh row cached in registers.
// ============================================================================
__global__ __launch_bounds__(192) void k_text_rec(
    const float* __restrict__ Whh, const float* __restrict__ bhh,
    const float* __restrict__ Wa)
{
    const int sd = blockIdx.x;           // 0..1999
    const int s  = sd / ND;
    const int g  = threadIdx.x;          // 0..191

    __shared__ float hs[HH];
    __shared__ float outs[NT][HH];
    __shared__ float ghs[GG];
    __shared__ float sc[32];

    float wh[HH];
    const float* whp = Whh + ((size_t)s * GG + g) * HH;
#pragma unroll
    for (int i = 0; i < HH; i++) wh[i] = whp[i];
    const float bh = bhh[s * GG + g];

    if (g < HH) hs[g] = 0.f;
    __syncthreads();

    const float* gib = g_gi + (size_t)sd * NT * GG;
    for (int t = 0; t < NT; t++) {
        float a0 = 0.f, a1 = 0.f, a2 = 0.f, a3 = 0.f;
#pragma unroll
        for (int i = 0; i < HH; i += 4) {
            a0 = fmaf(wh[i + 0], hs[i + 0], a0);
            a1 = fmaf(wh[i + 1], hs[i + 1], a1);
            a2 = fmaf(wh[i + 2], hs[i + 2], a2);
            a3 = fmaf(wh[i + 3], hs[i + 3], a3);
        }
        ghs[g] = bh + ((a0 + a1) + (a2 + a3));
        __syncthreads();
        if (g < HH) {
            const float* git = gib + t * GG;
            const float r  = sigmoidf_(git[g] + ghs[g]);
            const float z  = sigmoidf_(git[HH + g] + ghs[HH + g]);
            const float n  = tanhf(git[2 * HH + g] + r * ghs[2 * HH + g]);
            const float hn = (1.f - z) * n + z * hs[g];
            hs[g] = hn;
            outs[t][g] = hn;
        }
        __syncthreads();
    }
    pool_store<NT>(outs, hs, Wa + (size_t)s * HH * HH, sc, g_news + (size_t)sd * HH);
}

// ============================================================================
// Kernel 3: generic per-stock GRU + pool (price: IN=3 from global, seq: IN=64 from g_news)
//   SRC==0 -> input xin, dst g_pvec;  SRC==1 -> input g_news, dst g_tvec
// ============================================================================
template <int IN, int STEPS, int SRC>
__global__ __launch_bounds__(192) void k_gru_pool(
    const float* __restrict__ xin,
    const float* __restrict__ Wih, const float* __restrict__ Whh,
    const float* __restrict__ bih, const float* __restrict__ bhh,
    const float* __restrict__ Wa)
{
    const int s = blockIdx.x;
    const int g = threadIdx.x;

    __shared__ float hs[HH];
    __shared__ float outs[STEPS][HH];
    __shared__ float ghs[GG];
    __shared__ float gis[GG];
    __shared__ float sc[32];

    const float* xb = (SRC == 1) ? (g_news + (size_t)s * ND * HH)
                                 : (xin + (size_t)s * STEPS * IN);
    float wh[HH];
    const float* whp = Whh + ((size_t)s * GG + g) * HH;
#pragma unroll
    for (int i = 0; i < HH; i++) wh[i] = whp[i];
    float wi[IN];
    const float* wip = Wih + ((size_t)s * GG + g) * IN;
#pragma unroll
    for (int i = 0; i < IN; i++) wi[i] = wip[i];
    const float bh = bhh[s * GG + g];
    const float bi = bih[s * GG + g];

    if (g < HH) hs[g] = 0.f;
    __syncthreads();

    for (int t = 0; t < STEPS; t++) {
        const float* xt = xb + t * IN;
        float gi = bi;
#pragma unroll
        for (int i = 0; i < IN; i++) gi = fmaf(wi[i], xt[i], gi);
        float a0 = 0.f, a1 = 0.f, a2 = 0.f, a3 = 0.f;
#pragma unroll
        for (int i = 0; i < HH; i += 4) {
            a0 = fmaf(wh[i + 0], hs[i + 0], a0);
            a1 = fmaf(wh[i + 1], hs[i + 1], a1);
            a2 = fmaf(wh[i + 2], hs[i + 2], a2);
            a3 = fmaf(wh[i + 3], hs[i + 3], a3);
        }
        gis[g] = gi;
        ghs[g] = bh + ((a0 + a1) + (a2 + a3));
        __syncthreads();
        if (g < HH) {
            const float r  = sigmoidf_(gis[g] + ghs[g]);
            const float z  = sigmoidf_(gis[HH + g] + ghs[HH + g]);
            const float n  = tanhf(gis[2 * HH + g] + r * ghs[2 * HH + g]);
            const float hn = (1.f - z) * n + z * hs[g];
            hs[g] = hn;
            outs[t][g] = hn;
        }
        __syncthreads();
    }
    float* dst = (SRC == 1 ? g_tvec : g_pvec) + s * HH;
    pool_store<STEPS>(outs, hs, Wa + (size_t)s * HH * HH, sc, dst);
}

// ============================================================================
// Kernel 4: bilinear fusion  feature[s,o] = tanh( sum_ij tv[i] B[s,o,i,j] pv[j] + b )
//   one block per (o, s); reads 105MB of bil_B coalesced (memory-bound, fine)
// ============================================================================
__global__ __launch_bounds__(128) void k_bilinear(
    const float* __restrict__ B, const float* __restrict__ bb)
{
    const int o = blockIdx.x, s = blockIdx.y;
    const int tid = threadIdx.x;
    const float* Bp = B + ((size_t)s * HH + o) * HH * HH;
    const float* tv = g_tvec + s * HH;
    const float* pv = g_pvec + s * HH;
    float acc = 0.f;
    for (int k = tid; k < HH * HH; k += 128)
        acc = fmaf(tv[k >> 6] * pv[k & 63], Bp[k], acc);
    __shared__ float red[128];
    red[tid] = acc;
    __syncthreads();
    for (int st2 = 64; st2; st2 >>= 1) {
        if (tid < st2) red[tid] += red[tid + st2];
        __syncthreads();
    }
    if (tid == 0) g_feat[s * HH + o] = tanhf(red[0] + bb[s * HH + o]);
}

// ============================================================================
// Kernel 5: GAT head projection  h = feature @ W, f1 = h.a[:64], f2 = h.a[64:]
// ============================================================================
__global__ __launch_bounds__(64) void k_gat_proj(
    const float* __restrict__ gatW, const float* __restrict__ gatA)
{
    const int s = blockIdx.x, nh = blockIdx.y;
    const int j = threadIdx.x;
    const float* Wp = gatW + (size_t)nh * HH * HH;
    const float* x  = g_feat + s * HH;
    float acc = 0.f;
#pragma unroll 8
    for (int i = 0; i < HH; i++) acc = fmaf(x[i], Wp[i * HH + j], acc);
    g_hgat[((size_t)nh * NS + s) * HH + j] = acc;

    __shared__ float r1[64], r2[64];
    r1[j] = acc * gatA[nh * 2 * HH + j];
    r2[j] = acc * gatA[nh * 2 * HH + HH + j];
    __syncthreads();
    if (j < 32) {
        float v1 = r1[j] + r1[j + 32];
        float v2 = r2[j] + r2[j + 32];
#pragma unroll
        for (int o = 16; o; o >>= 1) {
            v1 += __shfl_xor_sync(0xffffffffu, v1, o);
            v2 += __shfl_xor_sync(0xffffffffu, v2, o);
        }
        if (j == 0) { g_f1[nh * NS + s] = v1; g_f2[nh * NS + s] = v2; }
    }
}

// ============================================================================
// Kernel 6: GAT masked attention + elu, write concat into g_x2
// ============================================================================
__global__ __launch_bounds__(128) void k_gat_attn(const float* __restrict__ adj)
{
    const int s = blockIdx.x, nh = blockIdx.y;
    const int tid = threadIdx.x;
    __shared__ float att[NS];
    const float f1v = g_f1[nh * NS + s];
    if (tid < NS) {
        float v = f1v + g_f2[nh * NS + tid];
        v = (v >= 0.f) ? v : 0.2f * v;                         // leaky relu
        att[tid] = (adj[s * NS + tid] > 0.f) ? v : -9e15f;     // adjacency mask
    }
    __syncthreads();
    if (tid == 0) {
        float m = -3.4e38f;
        for (int t = 0; t < NS; t++) m = fmaxf(m, att[t]);
        float su = 0.f;
        for (int t = 0; t < NS; t++) { const float e = expf(att[t] - m); att[t] = e; su += e; }
        const float inv = 1.f / su;
        for (int t = 0; t < NS; t++) att[t] *= inv;
    }
    __syncthreads();
    if (tid < HH) {
        float acc = 0.f;
        for (int t = 0; t < NS; t++)
            acc = fmaf(att[t], g_hgat[((size_t)nh * NS + t) * HH + tid], acc);
        acc = (acc > 0.f) ? acc : expm1f(acc);                 // elu
        g_x2[(size_t)s * (NHD * HH) + nh * HH + tid] = acc;
    }
}

// ============================================================================
// Kernel 7: final — out-layer GAT, blend, double softmax, loss. One block.
// ============================================================================
__global__ __launch_bounds__(128) void k_final(
    const float* __restrict__ blW, const float* __restrict__ blb,
    const float* __restrict__ outW, const float* __restrict__ outA,
    const float* __restrict__ adj, const int* __restrict__ label,
    float* __restrict__ out, int out_size)
{
    __shared__ float h2[NS][2];
    __shared__ float f1s[NS], f2s[NS];
    __shared__ float o1[NS][2];
    __shared__ float red[128];
    const int tid = threadIdx.x;

    for (int s = tid; s < NS; s += blockDim.x) {
        const float* xr = g_x2 + (size_t)s * NHD * HH;
        float a0 = 0.f, a1 = 0.f;
        for (int k = 0; k < NHD * HH; k++) {
            a0 = fmaf(xr[k], outW[2 * k + 0], a0);
            a1 = fmaf(xr[k], outW[2 * k + 1], a1);
        }
        h2[s][0] = a0; h2[s][1] = a1;
        f1s[s] = a0 * outA[0] + a1 * outA[1];
        f2s[s] = a0 * outA[2] + a1 * outA[3];
        const float* fr = g_feat + s * HH;
        float b0 = blb[0], b1 = blb[1];
        for (int k = 0; k < HH; k++) {
            b0 = fmaf(fr[k], blW[2 * k + 0], b0);
            b1 = fmaf(fr[k], blW[2 * k + 1], b1);
        }
        o1[s][0] = tanhf(b0); o1[s][1] = tanhf(b1);
    }
    __syncthreads();

    const int off = (out_size > 200) ? (out_size - 200) : 0;
    float lsum = 0.f;
    for (int s = tid; s < NS; s += blockDim.x) {
        float m = -3.4e38f;
        for (int t = 0; t < NS; t++) {
            float v = f1s[s] + f2s[t];
            v = (v >= 0.f) ? v : 0.2f * v;
            v = (adj[s * NS + t] > 0.f) ? v : -9e15f;
            m = fmaxf(m, v);
        }
        float su = 0.f, a0 = 0.f, a1 = 0.f;
        for (int t = 0; t < NS; t++) {
            float v = f1s[s] + f2s[t];
            v = (v >= 0.f) ? v : 0.2f * v;
            v = (adj[s * NS + t] > 0.f) ? v : -9e15f;
            const float e = expf(v - m);
            su += e;
            a0 = fmaf(e, h2[t][0], a0);
            a1 = fmaf(e, h2[t][1], a1);
        }
        a0 /= su; a1 /= su;
        a0 = (a0 > 0.f) ? a0 : expm1f(a0);                     // elu
        a1 = (a1 > 0.f) ? a1 : expm1f(a1);
        const float z0 = a0 + o1[s][0];
        const float z1 = a1 + o1[s][1];
        const float zm = fmaxf(z0, z1);
        const float e0 = expf(z0 - zm), e1 = expf(z1 - zm);
        const float p0 = e0 / (e0 + e1), p1 = e1 / (e0 + e1);  // output (softmax)
        if (out_size >= 200) { out[off + 2 * s] = p0; out[off + 2 * s + 1] = p1; }
        // loss on already-softmaxed output (double-softmax bug preserved)
        const float pm  = fmaxf(p0, p1);
        const float lse = pm + logf(expf(p0 - pm) + expf(p1 - pm));
        const float chosen = (label[s] == 0) ? p0 : p1;
        lsum += (lse - chosen);
    }
    red[tid] = lsum;
    __syncthreads();
    for (int st2 = 64; st2; st2 >>= 1) {
        if (tid < st2) red[tid] += red[tid + st2];
        __syncthreads();
    }
    if (tid == 0 && (out_size == 1 || out_size > 200)) out[0] = red[0] * (1.f / NS);
}

// ============================================================================
extern "C" void kernel_launch(void* const* d_in, const int* in_sizes, int n_in,
                              void* d_out, int out_size)
{
    (void)in_sizes;
    const float* text  = (const float*)d_in[0];
    const float* price = (const float*)d_in[1];
    const int*   label = (const int*)d_in[2];
    const float* adj   = (const float*)d_in[3];
    // index base for weights: handles whether the scalar `train` is passed (n_in 28 vs 27)
    const int wb = n_in - 23;
    const float* pg_Wih = (const float*)d_in[wb + 0];
    const float* pg_Whh = (const float*)d_in[wb + 1];
    const float* pg_bih = (const float*)d_in[wb + 2];
    const float* pg_bhh = (const float*)d_in[wb + 3];
    const float* pa_W   = (const float*)d_in[wb + 4];
    const float* tg_Wih = (const float*)d_in[wb + 5];
    const float* tg_Whh = (const float*)d_in[wb + 6];
    const float* tg_bih = (const float*)d_in[wb + 7];
    const float* tg_bhh = (const float*)d_in[wb + 8];
    const float* ta_W   = (const float*)d_in[wb + 9];
    const float* sg_Wih = (const float*)d_in[wb + 10];
    const float* sg_Whh = (const float*)d_in[wb + 11];
    const float* sg_bih = (const float*)d_in[wb + 12];
    const float* sg_bhh = (const float*)d_in[wb + 13];
    const float* sa_W   = (const float*)d_in[wb + 14];
    const float* bil_B  = (const float*)d_in[wb + 15];
    const float* bil_b  = (const float*)d_in[wb + 16];
    const float* bl_W   = (const float*)d_in[wb + 17];
    const float* bl_b   = (const float*)d_in[wb + 18];
    const float* gat_W  = (const float*)d_in[wb + 19];
    const float* gat_a  = (const float*)d_in[wb + 20];
    const float* out_W  = (const float*)d_in[wb + 21];
    const float* out_a  = (const float*)d_in[wb + 22];

    // 1) big batched GEMM: text GRU input projections
    k_text_gemm<<<dim3(10, 3, NS), 256>>>(text, tg_Wih, tg_bih);
    // 2) 2000 text GRU recurrences + attention pooling -> g_news
    k_text_rec<<<NS * ND, 192>>>(tg_Whh, tg_bhh, ta_W);
    // 3) price GRU + pool -> g_pvec (independent of text path)
    k_gru_pool<FP, ND, 0><<<NS, 192>>>(price, pg_Wih, pg_Whh, pg_bih, pg_bhh, pa_W);
    // 4) day-sequence GRU over g_news + pool -> g_tvec
    k_gru_pool<HH, ND, 1><<<NS, 192>>>(nullptr, sg_Wih, sg_Whh, sg_bih, sg_bhh, sa_W);
    // 5) bilinear fusion -> g_feat
    k_bilinear<<<dim3(HH, NS), 128>>>(bil_B, bil_b);
    // 6) GAT heads
    k_gat_proj<<<dim3(NS, NHD), 64>>>(gat_W, gat_a);
    k_gat_attn<<<dim3(NS, NHD), 128>>>(adj);
    // 7) output GAT layer + blend + softmax + loss
    k_final<<<1, 128>>>(bl_W, bl_b, out_W, out_a, adj, label, (float*)d_out, out_size);
}

// round 2
// speedup vs baseline: 1.2686x; 1.2686x over previous
#include <cuda_runtime.h>
#include <math.h>

#define NS 100     // stocks
#define ND 20      // days
#define NT 30      // texts per day
#define HH 64      // hidden
#define GG 192     // 3*H
#define NHD 8      // GAT heads
#define FT 512     // text feature
#define FP 3       // price feature
#define MROWS 600  // ND*NT

// ---------------- scratch (device globals; no runtime allocation) ----------------
__device__ float g_gi[(size_t)NS * MROWS * GG];   // text GRU input projections
__device__ float g_news[NS * ND * HH];
__device__ float g_pvec[NS * HH];
__device__ float g_tvec[NS * HH];
__device__ float g_feat[NS * HH];
__device__ float g_hgat[NHD * NS * HH];
__device__ float g_f1[NHD * NS];
__device__ float g_f2[NHD * NS];
__device__ float g_x2[NS * NHD * HH];

__device__ __forceinline__ float sigmoidf_(float x) { return 1.f / (1.f + expf(-x)); }

__device__ __forceinline__ unsigned cvt_tf32(float x) {
    unsigned r;
    asm("cvt.rna.tf32.f32 %0, %1;" : "=r"(r) : "f"(x));
    return r;
}

// ============================================================================
// Kernel 1: tensor-core batched GEMM (tf32 HMMA)
//   g_gi[s,m,g] = text[s,m,:512] . tg_Wih[s,g,:512] + tg_bih[s,g]
//   block: 64x64 tile, 128 threads (4 warps, 32x32 warp tiles), ktile=32
// ============================================================================
__global__ __launch_bounds__(128) void k_text_gemm_tc(
    const float* __restrict__ A, const float* __restrict__ W,
    const float* __restrict__ bih)
{
    const int s  = blockIdx.z;
    const int m0 = blockIdx.x * 64;   // 10 tiles over 600 (last partial)
    const int n0 = blockIdx.y * 64;   // 3 tiles over 192

    __shared__ unsigned As[64][36];
    __shared__ unsigned Bs[64][36];

    const int tid  = threadIdx.x;
    const int lane = tid & 31;
    const int warp = tid >> 5;
    const int wm   = (warp >> 1) * 32;   // warp row offset in tile
    const int wn   = (warp & 1) * 32;    // warp col offset in tile

    const float* Ab = A + (size_t)s * MROWS * FT;
    const float* Wb = W + (size_t)s * GG * FT;

    const int ar = tid >> 3;          // 0..15
    const int ac = (tid & 7) * 4;     // 0..28

    float acc[2][4][4];
#pragma unroll
    for (int i = 0; i < 2; i++)
#pragma unroll
        for (int j = 0; j < 4; j++)
#pragma unroll
            for (int v = 0; v < 4; v++) acc[i][j][v] = 0.f;

    for (int k0 = 0; k0 < FT; k0 += 32) {
#pragma unroll
        for (int i = 0; i < 4; i++) {
            const int r = ar + 16 * i;
            const int m = m0 + r;
            float4 av = make_float4(0.f, 0.f, 0.f, 0.f);
            if (m < MROWS) av = *(const float4*)(Ab + (size_t)m * FT + k0 + ac);
            As[r][ac + 0] = cvt_tf32(av.x); As[r][ac + 1] = cvt_tf32(av.y);
            As[r][ac + 2] = cvt_tf32(av.z); As[r][ac + 3] = cvt_tf32(av.w);
            const float4 bv = *(const float4*)(Wb + (size_t)(n0 + r) * FT + k0 + ac);
            Bs[r][ac + 0] = cvt_tf32(bv.x); Bs[r][ac + 1] = cvt_tf32(bv.y);
            Bs[r][ac + 2] = cvt_tf32(bv.z); Bs[r][ac + 3] = cvt_tf32(bv.w);
        }
        __syncthreads();

#pragma unroll
        for (int kk = 0; kk < 4; kk++) {
            const int kb = kk * 8;
            const int arow = wm + (lane >> 2);
            const int acol = kb + (lane & 3);
            unsigned a[2][4];
#pragma unroll
            for (int i = 0; i < 2; i++) {
                a[i][0] = As[arow + i * 16 + 0][acol + 0];
                a[i][1] = As[arow + i * 16 + 8][acol + 0];
                a[i][2] = As[arow + i * 16 + 0][acol + 4];
                a[i][3] = As[arow + i * 16 + 8][acol + 4];
            }
            unsigned b[4][2];
            const int bn = wn + (lane >> 2);
            const int bk = kb + (lane & 3);
#pragma unroll
            for (int j = 0; j < 4; j++) {
                b[j][0] = Bs[bn + j * 8][bk + 0];
                b[j][1] = Bs[bn + j * 8][bk + 4];
            }
#pragma unroll
            for (int i = 0; i < 2; i++)
#pragma unroll
                for (int j = 0; j < 4; j++) {
                    asm volatile(
                        "mma.sync.aligned.m16n8k8.row.col.f32.tf32.tf32.f32 "
                        "{%0,%1,%2,%3}, {%4,%5,%6,%7}, {%8,%9}, {%0,%1,%2,%3};"
                        : "+f"(acc[i][j][0]), "+f"(acc[i][j][1]),
                          "+f"(acc[i][j][2]), "+f"(acc[i][j][3])
                        : "r"(a[i][0]), "r"(a[i][1]), "r"(a[i][2]), "r"(a[i][3]),
                          "r"(b[j][0]), "r"(b[j][1]));
                }
        }
        __syncthreads();
    }

    // epilogue: bias add + store
#pragma unroll
    for (int i = 0; i < 2; i++) {
        const int row0 = m0 + wm + i * 16 + (lane >> 2);
#pragma unroll
        for (int j = 0; j < 4; j++) {
            const int col = n0 + wn + j * 8 + (lane & 3) * 2;
            const float b0 = bih[s * GG + col];
            const float b1 = bih[s * GG + col + 1];
            if (row0 < MROWS) {
                float2 v = make_float2(acc[i][j][0] + b0, acc[i][j][1] + b1);
                *(float2*)(g_gi + ((size_t)s * MROWS + row0) * GG + col) = v;
            }
            if (row0 + 8 < MROWS) {
                float2 v = make_float2(acc[i][j][2] + b0, acc[i][j][3] + b1);
                *(float2*)(g_gi + ((size_t)s * MROWS + row0 + 8) * GG + col) = v;
            }
        }
    }
}

// ============================================================================
// Attention pool: softmax_t( tanh(outs @ Wa) . h_last ) @ outs
//   wa_s: [64*64] shared-memory copy of Wa (conflict-free by lane layout)
// ============================================================================
template <int STEPS>
__device__ __forceinline__ void pool_store(
    float (*outs)[HH], const float* hs, const float* wa_s,
    float* sc, float* __restrict__ dst)
{
    const int tid  = threadIdx.x;
    const int warp = tid >> 5;
    const int lane = tid & 31;
    const int nw   = blockDim.x >> 5;

    for (int t = warp; t < STEPS; t += nw) {
        float part = 0.f;
#pragma unroll
        for (int jj = 0; jj < HH; jj += 32) {
            const int j = jj + lane;
            float a = 0.f;
#pragma unroll
            for (int i = 0; i < HH; i++) a = fmaf(outs[t][i], wa_s[i * HH + j], a);
            part = fmaf(tanhf(a), hs[j], part);
        }
#pragma unroll
        for (int o = 16; o; o >>= 1) part += __shfl_xor_sync(0xffffffffu, part, o);
        if (lane == 0) sc[t] = part;
    }
    __syncthreads();
    if (warp == 0) {
        const float v = (lane < STEPS) ? sc[lane] : -3.4e38f;
        float m = v;
#pragma unroll
        for (int o = 16; o; o >>= 1) m = fmaxf(m, __shfl_xor_sync(0xffffffffu, m, o));
        const float e = (lane < STEPS) ? expf(v - m) : 0.f;
        float su = e;
#pragma unroll
        for (int o = 16; o; o >>= 1) su += __shfl_xor_sync(0xffffffffu, su, o);
        if (lane < STEPS) sc[lane] = e / su;
    }
    __syncthreads();
    if (tid < HH) {
        float a = 0.f;
#pragma unroll
        for (int t = 0; t < STEPS; t++) a = fmaf(sc[t], outs[t][tid], a);
        dst[tid] = a;
    }
}

// cooperative load of a [64,64] matrix into smem (float4, coalesced)
__device__ __forceinline__ void load_wa(const float* __restrict__ wa, float* wa_s)
{
    const int tid = threadIdx.x;
    for (int i = tid; i < (HH * HH) / 4; i += blockDim.x)
        ((float4*)wa_s)[i] = ((const float4*)wa)[i];
}

// ============================================================================
// Kernel 2: text GRU recurrence + pool. One block per (stock, day). 192 threads.
// ============================================================================
__global__ __launch_bounds__(192) void k_text_rec(
    const float* __restrict__ Whh, const float* __restrict__ bhh,
    const float* __restrict__ Wa)
{
    const int sd = blockIdx.x;           // 0..1999
    const int s  = sd / ND;
    const int g  = threadIdx.x;          // 0..191

    __shared__ float hs[HH];
    __shared__ float outs[NT][HH];
    __shared__ float ghs[GG];
    __shared__ float sc[32];
    __shared__ float wa_s[HH * HH];

    float wh[HH];
    const float* whp = Whh + ((size_t)s * GG + g) * HH;
#pragma unroll
    for (int i = 0; i < HH; i++) wh[i] = whp[i];
    const float bh = bhh[s * GG + g];

    load_wa(Wa + (size_t)s * HH * HH, wa_s);
    if (g < HH) hs[g] = 0.f;
    __syncthreads();

    const float* gib = g_gi + (size_t)sd * NT * GG;
    for (int t = 0; t < NT; t++) {
        float a0 = 0.f, a1 = 0.f, a2 = 0.f, a3 = 0.f;
#pragma unroll
        for (int i = 0; i < HH; i += 4) {
            a0 = fmaf(wh[i + 0], hs[i + 0], a0);
            a1 = fmaf(wh[i + 1], hs[i + 1], a1);
            a2 = fmaf(wh[i + 2], hs[i + 2], a2);
            a3 = fmaf(wh[i + 3], hs[i + 3], a3);
        }
        ghs[g] = bh + ((a0 + a1) + (a2 + a3));
        __syncthreads();
        if (g < HH) {
            const float* git = gib + t * GG;
            const float r  = sigmoidf_(git[g] + ghs[g]);
            const float z  = sigmoidf_(git[HH + g] + ghs[HH + g]);
            const float n  = tanhf(git[2 * HH + g] + r * ghs[2 * HH + g]);
            const float hn = (1.f - z) * n + z * hs[g];
            hs[g] = hn;
            outs[t][g] = hn;
        }
        __syncthreads();
    }
    pool_store<NT>(outs, hs, wa_s, sc, g_news + (size_t)sd * HH);
}

// ============================================================================
// Kernel 3: generic per-stock GRU + pool
//   SRC==0 -> input xin, dst g_pvec;  SRC==1 -> input g_news, dst g_tvec
// ============================================================================
template <int IN, int STEPS, int SRC>
__global__ __launch_bounds__(192) void k_gru_pool(
    const float* __restrict__ xin,
    const float* __restrict__ Wih, const float* __restrict__ Whh,
    const float* __restrict__ bih, const float* __restrict__ bhh,
    const float* __restrict__ Wa)
{
    const int s = blockIdx.x;
    const int g = threadIdx.x;

    __shared__ float hs[HH];
    __shared__ float outs[STEPS][HH];
    __shared__ float ghs[GG];
    __shared__ float gis[GG];
    __shared__ float sc[32];
    __shared__ float wa_s[HH * HH];

    const float* xb = (SRC == 1) ? (g_news + (size_t)s * ND * HH)
                                 : (xin + (size_t)s * STEPS * IN);
    float wh[HH];
    const float* whp = Whh + ((size_t)s * GG + g) * HH;
#pragma unroll
    for (int i = 0; i < HH; i++) wh[i] = whp[i];
    float wi[IN];
    const float* wip = Wih + ((size_t)s * GG + g) * IN;
#pragma unroll
    for (int i = 0; i < IN; i++) wi[i] = wip[i];
    const float bh = bhh[s * GG + g];
    const float bi = bih[s * GG + g];

    load_wa(Wa + (size_t)s * HH * HH, wa_s);
    if (g < HH) hs[g] = 0.f;
    __syncthreads();

    for (int t = 0; t < STEPS; t++) {
        const float* xt = xb + t * IN;
        float gi = bi;
#pragma unroll
        for (int i = 0; i < IN; i++) gi = fmaf(wi[i], xt[i], gi);
        float a0 = 0.f, a1 = 0.f, a2 = 0.f, a3 = 0.f;
#pragma unroll
        for (int i = 0; i < HH; i += 4) {
            a0 = fmaf(wh[i + 0], hs[i + 0], a0);
            a1 = fmaf(wh[i + 1], hs[i + 1], a1);
            a2 = fmaf(wh[i + 2], hs[i + 2], a2);
            a3 = fmaf(wh[i + 3], hs[i + 3], a3);
        }
        gis[g] = gi;
        ghs[g] = bh + ((a0 + a1) + (a2 + a3));
        __syncthreads();
        if (g < HH) {
            const float r  = sigmoidf_(gis[g] + ghs[g]);
            const float z  = sigmoidf_(gis[HH + g] + ghs[HH + g]);
            const float n  = tanhf(gis[2 * HH + g] + r * ghs[2 * HH + g]);
            const float hn = (1.f - z) * n + z * hs[g];
            hs[g] = hn;
            outs[t][g] = hn;
        }
        __syncthreads();
    }
    float* dst = (SRC == 1 ? g_tvec : g_pvec) + s * HH;
    pool_store<STEPS>(outs, hs, wa_s, sc, dst);
}

// ============================================================================
// Kernel 4: bilinear fusion
// ============================================================================
__global__ __launch_bounds__(128) void k_bilinear(
    const float* __restrict__ B, const float* __restrict__ bb)
{
    const int o = blockIdx.x, s = blockIdx.y;
    const int tid = threadIdx.x;
    const float* Bp = B + ((size_t)s * HH + o) * HH * HH;
    const float* tv = g_tvec + s * HH;
    const float* pv = g_pvec + s * HH;
    float acc = 0.f;
    for (int k = tid; k < HH * HH; k += 128)
        acc = fmaf(tv[k >> 6] * pv[k & 63], Bp[k], acc);
    __shared__ float red[128];
    red[tid] = acc;
    __syncthreads();
    for (int st2 = 64; st2; st2 >>= 1) {
        if (tid < st2) red[tid] += red[tid + st2];
        __syncthreads();
    }
    if (tid == 0) g_feat[s * HH + o] = tanhf(red[0] + bb[s * HH + o]);
}

// ============================================================================
// Kernel 5: GAT head projection
// ============================================================================
__global__ __launch_bounds__(64) void k_gat_proj(
    const float* __restrict__ gatW, const float* __restrict__ gatA)
{
    const int s = blockIdx.x, nh = blockIdx.y;
    const int j = threadIdx.x;
    const float* Wp = gatW + (size_t)nh * HH * HH;
    const float* x  = g_feat + s * HH;
    float acc = 0.f;
#pragma unroll 8
    for (int i = 0; i < HH; i++) acc = fmaf(x[i], Wp[i * HH + j], acc);
    g_hgat[((size_t)nh * NS + s) * HH + j] = acc;

    __shared__ float r1[64], r2[64];
    r1[j] = acc * gatA[nh * 2 * HH + j];
    r2[j] = acc * gatA[nh * 2 * HH + HH + j];
    __syncthreads();
    if (j < 32) {
        float v1 = r1[j] + r1[j + 32];
        float v2 = r2[j] + r2[j + 32];
#pragma unroll
        for (int o = 16; o; o >>= 1) {
            v1 += __shfl_xor_sync(0xffffffffu, v1, o);
            v2 += __shfl_xor_sync(0xffffffffu, v2, o);
        }
        if (j == 0) { g_f1[nh * NS + s] = v1; g_f2[nh * NS + s] = v2; }
    }
}

// ============================================================================
// Kernel 6: GAT masked attention + elu, write concat into g_x2
// ============================================================================
__global__ __launch_bounds__(128) void k_gat_attn(const float* __restrict__ adj)
{
    const int s = blockIdx.x, nh = blockIdx.y;
    const int tid = threadIdx.x;
    __shared__ float att[NS];
    const float f1v = g_f1[nh * NS + s];
    if (tid < NS) {
        float v = f1v + g_f2[nh * NS + tid];
        v = (v >= 0.f) ? v : 0.2f * v;
        att[tid] = (adj[s * NS + tid] > 0.f) ? v : -9e15f;
    }
    __syncthreads();
    if (tid == 0) {
        float m = -3.4e38f;
        for (int t = 0; t < NS; t++) m = fmaxf(m, att[t]);
        float su = 0.f;
        for (int t = 0; t < NS; t++) { const float e = expf(att[t] - m); att[t] = e; su += e; }
        const float inv = 1.f / su;
        for (int t = 0; t < NS; t++) att[t] *= inv;
    }
    __syncthreads();
    if (tid < HH) {
        float acc = 0.f;
        for (int t = 0; t < NS; t++)
            acc = fmaf(att[t], g_hgat[((size_t)nh * NS + t) * HH + tid], acc);
        acc = (acc > 0.f) ? acc : expm1f(acc);
        g_x2[(size_t)s * (NHD * HH) + nh * HH + tid] = acc;
    }
}

// ============================================================================
// Kernel 7: final — out-layer GAT, blend, double softmax, loss. One block.
// ============================================================================
__global__ __launch_bounds__(128) void k_final(
    const float* __restrict__ blW, const float* __restrict__ blb,
    const float* __restrict__ outW, const float* __restrict__ outA,
    const float* __restrict__ adj, const int* __restrict__ label,
    float* __restrict__ out, int out_size)
{
    __shared__ float h2[NS][2];
    __shared__ float f1s[NS], f2s[NS];
    __shared__ float o1[NS][2];
    __shared__ float red[128];
    const int tid = threadIdx.x;

    for (int s = tid; s < NS; s += blockDim.x) {
        const float* xr = g_x2 + (size_t)s * NHD * HH;
        float a0 = 0.f, a1 = 0.f;
        for (int k = 0; k < NHD * HH; k++) {
            a0 = fmaf(xr[k], outW[2 * k + 0], a0);
            a1 = fmaf(xr[k], outW[2 * k + 1], a1);
        }
        h2[s][0] = a0; h2[s][1] = a1;
        f1s[s] = a0 * outA[0] + a1 * outA[1];
        f2s[s] = a0 * outA[2] + a1 * outA[3];
        const float* fr = g_feat + s * HH;
        float b0 = blb[0], b1 = blb[1];
        for (int k = 0; k < HH; k++) {
            b0 = fmaf(fr[k], blW[2 * k + 0], b0);
            b1 = fmaf(fr[k], blW[2 * k + 1], b1);
        }
        o1[s][0] = tanhf(b0); o1[s][1] = tanhf(b1);
    }
    __syncthreads();

    const int off = (out_size > 200) ? (out_size - 200) : 0;
    float lsum = 0.f;
    for (int s = tid; s < NS; s += blockDim.x) {
        float m = -3.4e38f;
        for (int t = 0; t < NS; t++) {
            float v = f1s[s] + f2s[t];
            v = (v >= 0.f) ? v : 0.2f * v;
            v = (adj[s * NS + t] > 0.f) ? v : -9e15f;
            m = fmaxf(m, v);
        }
        float su = 0.f, a0 = 0.f, a1 = 0.f;
        for (int t = 0; t < NS; t++) {
            float v = f1s[s] + f2s[t];
            v = (v >= 0.f) ? v : 0.2f * v;
            v = (adj[s * NS + t] > 0.f) ? v : -9e15f;
            const float e = expf(v - m);
            su += e;
            a0 = fmaf(e, h2[t][0], a0);
            a1 = fmaf(e, h2[t][1], a1);
        }
        a0 /= su; a1 /= su;
        a0 = (a0 > 0.f) ? a0 : expm1f(a0);
        a1 = (a1 > 0.f) ? a1 : expm1f(a1);
        const float z0 = a0 + o1[s][0];
        const float z1 = a1 + o1[s][1];
        const float zm = fmaxf(z0, z1);
        const float e0 = expf(z0 - zm), e1 = expf(z1 - zm);
        const float p0 = e0 / (e0 + e1), p1 = e1 / (e0 + e1);
        if (out_size >= 200) { out[off + 2 * s] = p0; out[off + 2 * s + 1] = p1; }
        const float pm  = fmaxf(p0, p1);
        const float lse = pm + logf(expf(p0 - pm) + expf(p1 - pm));
        const float chosen = (label[s] == 0) ? p0 : p1;
        lsum += (lse - chosen);
    }
    red[tid] = lsum;
    __syncthreads();
    for (int st2 = 64; st2; st2 >>= 1) {
        if (tid < st2) red[tid] += red[tid + st2];
        __syncthreads();
    }
    if (tid == 0 && (out_size == 1 || out_size > 200)) out[0] = red[0] * (1.f / NS);
}

// ============================================================================
extern "C" void kernel_launch(void* const* d_in, const int* in_sizes, int n_in,
                              void* d_out, int out_size)
{
    (void)in_sizes;
    const float* text  = (const float*)d_in[0];
    const float* price = (const float*)d_in[1];
    const int*   label = (const int*)d_in[2];
    const float* adj   = (const float*)d_in[3];
    const int wb = n_in - 23;
    const float* pg_Wih = (const float*)d_in[wb + 0];
    const float* pg_Whh = (const float*)d_in[wb + 1];
    const float* pg_bih = (const float*)d_in[wb + 2];
    const float* pg_bhh = (const float*)d_in[wb + 3];
    const float* pa_W   = (const float*)d_in[wb + 4];
    const float* tg_Wih = (const float*)d_in[wb + 5];
    const float* tg_Whh = (const float*)d_in[wb + 6];
    const float* tg_bih = (const float*)d_in[wb + 7];
    const float* tg_bhh = (const float*)d_in[wb + 8];
    const float* ta_W   = (const float*)d_in[wb + 9];
    const float* sg_Wih = (const float*)d_in[wb + 10];
    const float* sg_Whh = (const float*)d_in[wb + 11];
    const float* sg_bih = (const float*)d_in[wb + 12];
    const float* sg_bhh = (const float*)d_in[wb + 13];
    const float* sa_W   = (const float*)d_in[wb + 14];
    const float* bil_B  = (const float*)d_in[wb + 15];
    const float* bil_b  = (const float*)d_in[wb + 16];
    const float* bl_W   = (const float*)d_in[wb + 17];
    const float* bl_b   = (const float*)d_in[wb + 18];
    const float* gat_W  = (const float*)d_in[wb + 19];
    const float* gat_a  = (const float*)d_in[wb + 20];
    const float* out_W  = (const float*)d_in[wb + 21];
    const float* out_a  = (const float*)d_in[wb + 22];

    // 1) tensor-core batched GEMM: text GRU input projections
    k_text_gemm_tc<<<dim3(10, 3, NS), 128>>>(text, tg_Wih, tg_bih);
    // 2) 2000 text GRU recurrences + attention pooling -> g_news
    k_text_rec<<<NS * ND, 192>>>(tg_Whh, tg_bhh, ta_W);
    // 3) price GRU + pool -> g_pvec
    k_gru_pool<FP, ND, 0><<<NS, 192>>>(price, pg_Wih, pg_Whh, pg_bih, pg_bhh, pa_W);
    // 4) day-sequence GRU over g_news + pool -> g_tvec
    k_gru_pool<HH, ND, 1><<<NS, 192>>>(nullptr, sg_Wih, sg_Whh, sg_bih, sg_bhh, sa_W);
    // 5) bilinear fusion -> g_feat
    k_bilinear<<<dim3(HH, NS), 128>>>(bil_B, bil_b);
    // 6) GAT heads
    k_gat_proj<<<dim3(NS, NHD), 64>>>(gat_W, gat_a);
    k_gat_attn<<<dim3(NS, NHD), 128>>>(adj);
    // 7) output GAT layer + blend + softmax + loss
    k_final<<<1, 128>>>(bl_W, bl_b, out_W, out_a, adj, label, (float*)d_out, out_size);
}

// round 3
// speedup vs baseline: 1.8095x; 1.4263x over previous
#include <cuda_runtime.h>
#include <math.h>

#define NS 100     // stocks
#define ND 20      // days
#define NT 30      // texts per day
#define HH 64      // hidden
#define GG 192     // 3*H
#define NHD 8      // GAT heads
#define FT 512     // text feature
#define FP 3       // price feature
#define MROWS 600  // ND*NT

// ---------------- scratch (device globals; no runtime allocation) ----------------
__device__ float g_gi[(size_t)NS * MROWS * GG];   // text GRU input projections
__device__ float g_news[NS * ND * HH];
__device__ float g_pvec[NS * HH];
__device__ float g_tvec[NS * HH];
__device__ float g_feat[NS * HH];
__device__ float g_hgat[NHD * NS * HH];
__device__ float g_f1[NHD * NS];
__device__ float g_f2[NHD * NS];
__device__ float g_x2[NS * NHD * HH];

#define LOG2E 1.4426950408889634f

__device__ __forceinline__ float fexp2(float x) { float r; asm("ex2.approx.f32 %0,%1;" : "=f"(r) : "f"(x)); return r; }
__device__ __forceinline__ float frcp(float x)  { float r; asm("rcp.approx.f32 %0,%1;" : "=f"(r) : "f"(x)); return r; }
__device__ __forceinline__ float fsig(float x)  { return frcp(1.f + fexp2(-LOG2E * x)); }
__device__ __forceinline__ float ftanh(float x) { return 1.f - 2.f * frcp(1.f + fexp2(2.f * LOG2E * x)); }
__device__ __forceinline__ float fexp(float x)  { return fexp2(LOG2E * x); }
__device__ __forceinline__ float felu(float x)  { return (x > 0.f) ? x : (fexp(x) - 1.f); }

__device__ __forceinline__ unsigned cvt_tf32(float x) {
    unsigned r;
    asm("cvt.rna.tf32.f32 %0, %1;" : "=r"(r) : "f"(x));
    return r;
}

// ============================================================================
// Kernel 1: tensor-core batched GEMM (tf32 HMMA)
//   g_gi[s,m,g] = text[s,m,:512] . tg_Wih[s,g,:512] + tg_bih[s,g]
// ============================================================================
__global__ __launch_bounds__(128) void k_text_gemm_tc(
    const float* __restrict__ A, const float* __restrict__ W,
    const float* __restrict__ bih)
{
    const int s  = blockIdx.z;
    const int m0 = blockIdx.x * 64;
    const int n0 = blockIdx.y * 64;

    __shared__ unsigned As[64][36];
    __shared__ unsigned Bs[64][36];

    const int tid  = threadIdx.x;
    const int lane = tid & 31;
    const int warp = tid >> 5;
    const int wm   = (warp >> 1) * 32;
    const int wn   = (warp & 1) * 32;

    const float* Ab = A + (size_t)s * MROWS * FT;
    const float* Wb = W + (size_t)s * GG * FT;

    const int ar = tid >> 3;
    const int ac = (tid & 7) * 4;

    float acc[2][4][4];
#pragma unroll
    for (int i = 0; i < 2; i++)
#pragma unroll
        for (int j = 0; j < 4; j++)
#pragma unroll
            for (int v = 0; v < 4; v++) acc[i][j][v] = 0.f;

    for (int k0 = 0; k0 < FT; k0 += 32) {
#pragma unroll
        for (int i = 0; i < 4; i++) {
            const int r = ar + 16 * i;
            const int m = m0 + r;
            float4 av = make_float4(0.f, 0.f, 0.f, 0.f);
            if (m < MROWS) av = *(const float4*)(Ab + (size_t)m * FT + k0 + ac);
            As[r][ac + 0] = cvt_tf32(av.x); As[r][ac + 1] = cvt_tf32(av.y);
            As[r][ac + 2] = cvt_tf32(av.z); As[r][ac + 3] = cvt_tf32(av.w);
            const float4 bv = *(const float4*)(Wb + (size_t)(n0 + r) * FT + k0 + ac);
            Bs[r][ac + 0] = cvt_tf32(bv.x); Bs[r][ac + 1] = cvt_tf32(bv.y);
            Bs[r][ac + 2] = cvt_tf32(bv.z); Bs[r][ac + 3] = cvt_tf32(bv.w);
        }
        __syncthreads();

#pragma unroll
        for (int kk = 0; kk < 4; kk++) {
            const int kb = kk * 8;
            const int arow = wm + (lane >> 2);
            const int acol = kb + (lane & 3);
            unsigned a[2][4];
#pragma unroll
            for (int i = 0; i < 2; i++) {
                a[i][0] = As[arow + i * 16 + 0][acol + 0];
                a[i][1] = As[arow + i * 16 + 8][acol + 0];
                a[i][2] = As[arow + i * 16 + 0][acol + 4];
                a[i][3] = As[arow + i * 16 + 8][acol + 4];
            }
            unsigned b[4][2];
            const int bn = wn + (lane >> 2);
            const int bk = kb + (lane & 3);
#pragma unroll
            for (int j = 0; j < 4; j++) {
                b[j][0] = Bs[bn + j * 8][bk + 0];
                b[j][1] = Bs[bn + j * 8][bk + 4];
            }
#pragma unroll
            for (int i = 0; i < 2; i++)
#pragma unroll
                for (int j = 0; j < 4; j++) {
                    asm volatile(
                        "mma.sync.aligned.m16n8k8.row.col.f32.tf32.tf32.f32 "
                        "{%0,%1,%2,%3}, {%4,%5,%6,%7}, {%8,%9}, {%0,%1,%2,%3};"
                        : "+f"(acc[i][j][0]), "+f"(acc[i][j][1]),
                          "+f"(acc[i][j][2]), "+f"(acc[i][j][3])
                        : "r"(a[i][0]), "r"(a[i][1]), "r"(a[i][2]), "r"(a[i][3]),
                          "r"(b[j][0]), "r"(b[j][1]));
                }
        }
        __syncthreads();
    }

#pragma unroll
    for (int i = 0; i < 2; i++) {
        const int row0 = m0 + wm + i * 16 + (lane >> 2);
#pragma unroll
        for (int j = 0; j < 4; j++) {
            const int col = n0 + wn + j * 8 + (lane & 3) * 2;
            const float b0 = bih[s * GG + col];
            const float b1 = bih[s * GG + col + 1];
            if (row0 < MROWS) {
                float2 v = make_float2(acc[i][j][0] + b0, acc[i][j][1] + b1);
                *(float2*)(g_gi + ((size_t)s * MROWS + row0) * GG + col) = v;
            }
            if (row0 + 8 < MROWS) {
                float2 v = make_float2(acc[i][j][2] + b0, acc[i][j][3] + b1);
                *(float2*)(g_gi + ((size_t)s * MROWS + row0 + 8) * GG + col) = v;
            }
        }
    }
}

// ============================================================================
// Attention pool: softmax_t( tanh(outs @ Wa) . h_last ) @ outs
// ============================================================================
template <int STEPS>
__device__ __forceinline__ void pool_store(
    float (*outs)[HH], const float* hs, const float* wa_s,
    float* sc, float* __restrict__ dst)
{
    const int tid  = threadIdx.x;
    const int warp = tid >> 5;
    const int lane = tid & 31;
    const int nw   = blockDim.x >> 5;

    for (int t = warp; t < STEPS; t += nw) {
        float part = 0.f;
#pragma unroll
        for (int jj = 0; jj < HH; jj += 32) {
            const int j = jj + lane;
            float a = 0.f;
#pragma unroll
            for (int i = 0; i < HH; i++) a = fmaf(outs[t][i], wa_s[i * HH + j], a);
            part = fmaf(ftanh(a), hs[j], part);
        }
#pragma unroll
        for (int o = 16; o; o >>= 1) part += __shfl_xor_sync(0xffffffffu, part, o);
        if (lane == 0) sc[t] = part;
    }
    __syncthreads();
    if (warp == 0) {
        const float v = (lane < STEPS) ? sc[lane] : -3.4e38f;
        float m = v;
#pragma unroll
        for (int o = 16; o; o >>= 1) m = fmaxf(m, __shfl_xor_sync(0xffffffffu, m, o));
        const float e = (lane < STEPS) ? fexp(v - m) : 0.f;
        float su = e;
#pragma unroll
        for (int o = 16; o; o >>= 1) su += __shfl_xor_sync(0xffffffffu, su, o);
        if (lane < STEPS) sc[lane] = e / su;
    }
    __syncthreads();
    if (tid < HH) {
        float a = 0.f;
#pragma unroll
        for (int t = 0; t < STEPS; t++) a = fmaf(sc[t], outs[t][tid], a);
        dst[tid] = a;
    }
}

// ============================================================================
// Kernel 2: text GRU recurrence + pool. One block per (stock, day). 192 threads.
//   All 30 steps of gi are staged into smem up-front (coalesced); after the
//   recurrence the same buffer is reused for Wa.
// ============================================================================
__global__ __launch_bounds__(192, 3) void k_text_rec(
    const float* __restrict__ Whh, const float* __restrict__ bhh,
    const float* __restrict__ Wa)
{
    const int sd = blockIdx.x;
    const int s  = sd / ND;
    const int g  = threadIdx.x;

    __shared__ float buf[NT * GG];       // gi during recurrence; Wa during pool
    __shared__ float outs[NT][HH];
    __shared__ float hs[HH];
    __shared__ float ghs[GG];
    __shared__ float sc[32];

    float wh[HH];
    const float* whp = Whh + ((size_t)s * GG + g) * HH;
#pragma unroll
    for (int i = 0; i < HH; i++) wh[i] = whp[i];
    const float bh = bhh[s * GG + g];

    // stage all gi for this (s,d) into smem (coalesced float4)
    {
        const float4* src = (const float4*)(g_gi + (size_t)sd * NT * GG);
        float4* dst4 = (float4*)buf;
        for (int i = g; i < (NT * GG) / 4; i += 192) dst4[i] = src[i];
    }
    if (g < HH) hs[g] = 0.f;
    __syncthreads();

    for (int t = 0; t < NT; t++) {
        float a0 = 0.f, a1 = 0.f, a2 = 0.f, a3 = 0.f;
#pragma unroll
        for (int i = 0; i < HH; i += 4) {
            a0 = fmaf(wh[i + 0], hs[i + 0], a0);
            a1 = fmaf(wh[i + 1], hs[i + 1], a1);
            a2 = fmaf(wh[i + 2], hs[i + 2], a2);
            a3 = fmaf(wh[i + 3], hs[i + 3], a3);
        }
        ghs[g] = bh + ((a0 + a1) + (a2 + a3));
        __syncthreads();
        if (g < HH) {
            const float* git = buf + t * GG;
            const float r  = fsig(git[g] + ghs[g]);
            const float z  = fsig(git[HH + g] + ghs[HH + g]);
            const float n  = ftanh(git[2 * HH + g] + r * ghs[2 * HH + g]);
            const float hn = (1.f - z) * n + z * hs[g];
            hs[g] = hn;
            outs[t][g] = hn;
        }
        __syncthreads();
    }

    // reuse buf for Wa
    {
        const float4* src = (const float4*)(Wa + (size_t)s * HH * HH);
        float4* dst4 = (float4*)buf;
        for (int i = g; i < (HH * HH) / 4; i += 192) dst4[i] = src[i];
    }
    __syncthreads();
    pool_store<NT>(outs, hs, buf, sc, g_news + (size_t)sd * HH);
}

// ============================================================================
// Kernel 3: generic per-stock GRU + pool, gi precomputed before recurrence
//   SRC==0 -> input xin, dst g_pvec;  SRC==1 -> input g_news, dst g_tvec
// ============================================================================
template <int IN, int STEPS, int SRC>
__global__ __launch_bounds__(192) void k_gru_pool(
    const float* __restrict__ xin,
    const float* __restrict__ Wih, const float* __restrict__ Whh,
    const float* __restrict__ bih, const float* __restrict__ bhh,
    const float* __restrict__ Wa)
{
    const int s = blockIdx.x;
    const int g = threadIdx.x;

    __shared__ float xs[STEPS * IN];
    __shared__ float gis[STEPS * GG];
    __shared__ float outs[STEPS][HH];
    __shared__ float hs[HH];
    __shared__ float ghs[GG];
    __shared__ float sc[32];
    __shared__ float wa_s[HH * HH];

    const float* xb = (SRC == 1) ? (g_news + (size_t)s * ND * HH)
                                 : (xin + (size_t)s * STEPS * IN);
    float wh[HH];
    const float* whp = Whh + ((size_t)s * GG + g) * HH;
#pragma unroll
    for (int i = 0; i < HH; i++) wh[i] = whp[i];
    float wi[IN];
    const float* wip = Wih + ((size_t)s * GG + g) * IN;
#pragma unroll
    for (int i = 0; i < IN; i++) wi[i] = wip[i];
    const float bh = bhh[s * GG + g];
    const float bi = bih[s * GG + g];

    for (int i = g; i < STEPS * IN; i += 192) xs[i] = xb[i];
    {
        const float4* src = (const float4*)(Wa + (size_t)s * HH * HH);
        for (int i = g; i < (HH * HH) / 4; i += 192) ((float4*)wa_s)[i] = src[i];
    }
    if (g < HH) hs[g] = 0.f;
    __syncthreads();

    // precompute all input projections (independent of recurrence)
    for (int t = 0; t < STEPS; t++) {
        float gi = bi;
#pragma unroll
        for (int i = 0; i < IN; i++) gi = fmaf(wi[i], xs[t * IN + i], gi);
        gis[t * GG + g] = gi;
    }
    __syncthreads();

    for (int t = 0; t < STEPS; t++) {
        float a0 = 0.f, a1 = 0.f, a2 = 0.f, a3 = 0.f;
#pragma unroll
        for (int i = 0; i < HH; i += 4) {
            a0 = fmaf(wh[i + 0], hs[i + 0], a0);
            a1 = fmaf(wh[i + 1], hs[i + 1], a1);
            a2 = fmaf(wh[i + 2], hs[i + 2], a2);
            a3 = fmaf(wh[i + 3], hs[i + 3], a3);
        }
        ghs[g] = bh + ((a0 + a1) + (a2 + a3));
        __syncthreads();
        if (g < HH) {
            const float* git = gis + t * GG;
            const float r  = fsig(git[g] + ghs[g]);
            const float z  = fsig(git[HH + g] + ghs[HH + g]);
            const float n  = ftanh(git[2 * HH + g] + r * ghs[2 * HH + g]);
            const float hn = (1.f - z) * n + z * hs[g];
            hs[g] = hn;
            outs[t][g] = hn;
        }
        __syncthreads();
    }
    float* dst = (SRC == 1 ? g_tvec : g_pvec) + s * HH;
    pool_store<STEPS>(outs, hs, wa_s, sc, dst);
}

// ============================================================================
// Kernel 4: bilinear fusion (float4, smem-staged vectors)
// ============================================================================
__global__ __launch_bounds__(128) void k_bilinear(
    const float* __restrict__ B, const float* __restrict__ bb)
{
    const int o = blockIdx.x, s = blockIdx.y;
    const int tid = threadIdx.x;
    __shared__ float tv_s[HH], pv_s[HH];
    if (tid < HH) { tv_s[tid] = g_tvec[s * HH + tid]; pv_s[tid] = g_pvec[s * HH + tid]; }
    __syncthreads();

    const float* Bp = B + ((size_t)s * HH + o) * HH * HH;
    float acc = 0.f;
#pragma unroll
    for (int it = 0; it < 8; it++) {
        const int k4 = (it * 128 + tid) * 4;
        const float4 v = *(const float4*)(Bp + k4);
        const int i = k4 >> 6, j = k4 & 63;
        float p = pv_s[j] * v.x;
        p = fmaf(pv_s[j + 1], v.y, p);
        p = fmaf(pv_s[j + 2], v.z, p);
        p = fmaf(pv_s[j + 3], v.w, p);
        acc = fmaf(tv_s[i], p, acc);
    }
    __shared__ float red[128];
    red[tid] = acc;
    __syncthreads();
    for (int st2 = 64; st2; st2 >>= 1) {
        if (tid < st2) red[tid] += red[tid + st2];
        __syncthreads();
    }
    if (tid == 0) g_feat[s * HH + o] = ftanh(red[0] + bb[s * HH + o]);
}

// ============================================================================
// Kernel 5: GAT head projection
// ============================================================================
__global__ __launch_bounds__(64) void k_gat_proj(
    const float* __restrict__ gatW, const float* __restrict__ gatA)
{
    const int s = blockIdx.x, nh = blockIdx.y;
    const int j = threadIdx.x;
    const float* Wp = gatW + (size_t)nh * HH * HH;
    const float* x  = g_feat + s * HH;
    float acc = 0.f;
#pragma unroll 8
    for (int i = 0; i < HH; i++) acc = fmaf(x[i], Wp[i * HH + j], acc);
    g_hgat[((size_t)nh * NS + s) * HH + j] = acc;

    __shared__ float r1[64], r2[64];
    r1[j] = acc * gatA[nh * 2 * HH + j];
    r2[j] = acc * gatA[nh * 2 * HH + HH + j];
    __syncthreads();
    if (j < 32) {
        float v1 = r1[j] + r1[j + 32];
        float v2 = r2[j] + r2[j + 32];
#pragma unroll
        for (int o = 16; o; o >>= 1) {
            v1 += __shfl_xor_sync(0xffffffffu, v1, o);
            v2 += __shfl_xor_sync(0xffffffffu, v2, o);
        }
        if (j == 0) { g_f1[nh * NS + s] = v1; g_f2[nh * NS + s] = v2; }
    }
}

// ============================================================================
// Kernel 6: GAT masked attention + elu (warp-parallel softmax)
// ============================================================================
__global__ __launch_bounds__(128) void k_gat_attn(const float* __restrict__ adj)
{
    const int s = blockIdx.x, nh = blockIdx.y;
    const int tid = threadIdx.x;
    __shared__ float att[NS];
    __shared__ float sinv;
    const float f1v = g_f1[nh * NS + s];
    if (tid < NS) {
        float v = f1v + g_f2[nh * NS + tid];
        v = (v >= 0.f) ? v : 0.2f * v;
        att[tid] = (adj[s * NS + tid] > 0.f) ? v : -9e15f;
    }
    __syncthreads();
    if (tid < 32) {
        float m = -3.4e38f;
        for (int t = tid; t < NS; t += 32) m = fmaxf(m, att[t]);
#pragma unroll
        for (int o = 16; o; o >>= 1) m = fmaxf(m, __shfl_xor_sync(0xffffffffu, m, o));
        float su = 0.f;
        for (int t = tid; t < NS; t += 32) {
            const float e = fexp(att[t] - m);
            att[t] = e;
            su += e;
        }
#pragma unroll
        for (int o = 16; o; o >>= 1) su += __shfl_xor_sync(0xffffffffu, su, o);
        if (tid == 0) sinv = 1.f / su;
    }
    __syncthreads();
    if (tid < HH) {
        float acc = 0.f;
        for (int t = 0; t < NS; t++)
            acc = fmaf(att[t], g_hgat[((size_t)nh * NS + t) * HH + tid], acc);
        acc = felu(acc * sinv);
        g_x2[(size_t)s * (NHD * HH) + nh * HH + tid] = acc;
    }
}

// ============================================================================
// Kernel 7: final — out-layer GAT, blend, double softmax, loss. One block.
// ============================================================================
__global__ __launch_bounds__(128) void k_final(
    const float* __restrict__ blW, const float* __restrict__ blb,
    const float* __restrict__ outW, const float* __restrict__ outA,
    const float* __restrict__ adj, const int* __restrict__ label,
    float* __restrict__ out, int out_size)
{
    __shared__ float h2[NS][2];
    __shared__ float f1s[NS], f2s[NS];
    __shared__ float o1[NS][2];
    __shared__ float adj_s[NS * NS];
    __shared__ float red[128];
    const int tid  = threadIdx.x;
    const int warp = tid >> 5;
    const int lane = tid & 31;

    for (int i = tid; i < NS * NS; i += 128) adj_s[i] = adj[i];

    // warp-per-stock GEMVs
    for (int s = warp; s < NS; s += 4) {
        const float* xr = g_x2 + (size_t)s * NHD * HH;
        float a0 = 0.f, a1 = 0.f;
        for (int k = lane; k < NHD * HH; k += 32) {
            const float xv = xr[k];
            a0 = fmaf(xv, outW[2 * k + 0], a0);
            a1 = fmaf(xv, outW[2 * k + 1], a1);
        }
        const float* fr = g_feat + s * HH;
        float b0 = 0.f, b1 = 0.f;
        for (int k = lane; k < HH; k += 32) {
            const float fv = fr[k];
            b0 = fmaf(fv, blW[2 * k + 0], b0);
            b1 = fmaf(fv, blW[2 * k + 1], b1);
        }
#pragma unroll
        for (int o = 16; o; o >>= 1) {
            a0 += __shfl_xor_sync(0xffffffffu, a0, o);
            a1 += __shfl_xor_sync(0xffffffffu, a1, o);
            b0 += __shfl_xor_sync(0xffffffffu, b0, o);
            b1 += __shfl_xor_sync(0xffffffffu, b1, o);
        }
        if (lane == 0) {
            h2[s][0] = a0; h2[s][1] = a1;
            f1s[s] = a0 * outA[0] + a1 * outA[1];
            f2s[s] = a0 * outA[2] + a1 * outA[3];
            o1[s][0] = ftanh(b0 + blb[0]);
            o1[s][1] = ftanh(b1 + blb[1]);
        }
    }
    __syncthreads();

    const int off = (out_size > 200) ? (out_size - 200) : 0;
    float lsum = 0.f;
    for (int s = tid; s < NS; s += 128) {
        float m = -3.4e38f;
        for (int t = 0; t < NS; t++) {
            float v = f1s[s] + f2s[t];
            v = (v >= 0.f) ? v : 0.2f * v;
            v = (adj_s[s * NS + t] > 0.f) ? v : -9e15f;
            m = fmaxf(m, v);
        }
        float su = 0.f, a0 = 0.f, a1 = 0.f;
        for (int t = 0; t < NS; t++) {
            float v = f1s[s] + f2s[t];
            v = (v >= 0.f) ? v : 0.2f * v;
            v = (adj_s[s * NS + t] > 0.f) ? v : -9e15f;
            const float e = fexp(v - m);
            su += e;
            a0 = fmaf(e, h2[t][0], a0);
            a1 = fmaf(e, h2[t][1], a1);
        }
        a0 /= su; a1 /= su;
        a0 = felu(a0);
        a1 = felu(a1);
        const float z0 = a0 + o1[s][0];
        const float z1 = a1 + o1[s][1];
        const float zm = fmaxf(z0, z1);
        const float e0 = fexp(z0 - zm), e1 = fexp(z1 - zm);
        const float p0 = e0 / (e0 + e1), p1 = e1 / (e0 + e1);
        if (out_size >= 200) { out[off + 2 * s] = p0; out[off + 2 * s + 1] = p1; }
        const float pm  = fmaxf(p0, p1);
        const float lse = pm + logf(fexp(p0 - pm) + fexp(p1 - pm));
        const float chosen = (label[s] == 0) ? p0 : p1;
        lsum += (lse - chosen);
    }
    red[tid] = lsum;
    __syncthreads();
    for (int st2 = 64; st2; st2 >>= 1) {
        if (tid < st2) red[tid] += red[tid + st2];
        __syncthreads();
    }
    if (tid == 0 && (out_size == 1 || out_size > 200)) out[0] = red[0] * (1.f / NS);
}

// ============================================================================
extern "C" void kernel_launch(void* const* d_in, const int* in_sizes, int n_in,
                              void* d_out, int out_size)
{
    (void)in_sizes;
    const float* text  = (const float*)d_in[0];
    const float* price = (const float*)d_in[1];
    const int*   label = (const int*)d_in[2];
    const float* adj   = (const float*)d_in[3];
    const int wb = n_in - 23;
    const float* pg_Wih = (const float*)d_in[wb + 0];
    const float* pg_Whh = (const float*)d_in[wb + 1];
    const float* pg_bih = (const float*)d_in[wb + 2];
    const float* pg_bhh = (const float*)d_in[wb + 3];
    const float* pa_W   = (const float*)d_in[wb + 4];
    const float* tg_Wih = (const float*)d_in[wb + 5];
    const float* tg_Whh = (const float*)d_in[wb + 6];
    const float* tg_bih = (const float*)d_in[wb + 7];
    const float* tg_bhh = (const float*)d_in[wb + 8];
    const float* ta_W   = (const float*)d_in[wb + 9];
    const float* sg_Wih = (const float*)d_in[wb + 10];
    const float* sg_Whh = (const float*)d_in[wb + 11];
    const float* sg_bih = (const float*)d_in[wb + 12];
    const float* sg_bhh = (const float*)d_in[wb + 13];
    const float* sa_W   = (const float*)d_in[wb + 14];
    const float* bil_B  = (const float*)d_in[wb + 15];
    const float* bil_b  = (const float*)d_in[wb + 16];
    const float* bl_W   = (const float*)d_in[wb + 17];
    const float* bl_b   = (const float*)d_in[wb + 18];
    const float* gat_W  = (const float*)d_in[wb + 19];
    const float* gat_a  = (const float*)d_in[wb + 20];
    const float* out_W  = (const float*)d_in[wb + 21];
    const float* out_a  = (const float*)d_in[wb + 22];

    // price path first (independent of text path)
    k_gru_pool<FP, ND, 0><<<NS, 192>>>(price, pg_Wih, pg_Whh, pg_bih, pg_bhh, pa_W);
    // 1) tensor-core batched GEMM: text GRU input projections
    k_text_gemm_tc<<<dim3(10, 3, NS), 128>>>(text, tg_Wih, tg_bih);
    // 2) 2000 text GRU recurrences + attention pooling -> g_news
    k_text_rec<<<NS * ND, 192>>>(tg_Whh, tg_bhh, ta_W);
    // 3) day-sequence GRU over g_news + pool -> g_tvec
    k_gru_pool<HH, ND, 1><<<NS, 192>>>(nullptr, sg_Wih, sg_Whh, sg_bih, sg_bhh, sa_W);
    // 4) bilinear fusion -> g_feat
    k_bilinear<<<dim3(HH, NS), 128>>>(bil_B, bil_b);
    // 5) GAT heads
    k_gat_proj<<<dim3(NS, NHD), 64>>>(gat_W, gat_a);
    k_gat_attn<<<dim3(NS, NHD), 128>>>(adj);
    // 6) output GAT layer + blend + softmax + loss
    k_final<<<1, 128>>>(bl_W, bl_b, out_W, out_a, adj, label, (float*)d_out, out_size);
}

// round 4
// speedup vs baseline: 1.8377x; 1.0156x over previous
#include <cuda_runtime.h>
#include <cuda_bf16.h>
#include <math.h>

#define NS 100     // stocks
#define ND 20      // days
#define NT 30      // texts per day
#define HH 64      // hidden
#define GG 192     // 3*H
#define NHD 8      // GAT heads
#define FT 512     // text feature
#define FP 3       // price feature
#define MROWS 600  // ND*NT

// ---------------- scratch (device globals; no runtime allocation) ----------------
__device__ float g_gi[(size_t)NS * MROWS * GG];   // text GRU input projections
__device__ float g_news[NS * ND * HH];
__device__ float g_pvec[NS * HH];
__device__ float g_tvec[NS * HH];
__device__ float g_feat[NS * HH];
__device__ float g_hgat[NHD * NS * HH];
__device__ float g_f1[NHD * NS];
__device__ float g_f2[NHD * NS];
__device__ float g_x2[NS * NHD * HH];

#define LOG2E 1.4426950408889634f

__device__ __forceinline__ float fexp2(float x) { float r; asm("ex2.approx.f32 %0,%1;" : "=f"(r) : "f"(x)); return r; }
__device__ __forceinline__ float frcp(float x)  { float r; asm("rcp.approx.f32 %0,%1;" : "=f"(r) : "f"(x)); return r; }
__device__ __forceinline__ float fsig(float x)  { return frcp(1.f + fexp2(-LOG2E * x)); }
__device__ __forceinline__ float ftanh(float x) { return 1.f - 2.f * frcp(1.f + fexp2(2.f * LOG2E * x)); }
__device__ __forceinline__ float fexp(float x)  { return fexp2(LOG2E * x); }
__device__ __forceinline__ float felu(float x)  { return (x > 0.f) ? x : (fexp(x) - 1.f); }

__device__ __forceinline__ unsigned smem_u32(const void* p) {
    return (unsigned)__cvta_generic_to_shared(p);
}

#define LDSM4(r0, r1, r2, r3, addr) \
    asm volatile("ldmatrix.sync.aligned.m8n8.x4.shared.b16 {%0,%1,%2,%3},[%4];" \
                 : "=r"(r0), "=r"(r1), "=r"(r2), "=r"(r3) : "r"(addr))

#define MMA16816(c, a, b0, b1) \
    asm volatile("mma.sync.aligned.m16n8k16.row.col.f32.bf16.bf16.f32 " \
                 "{%0,%1,%2,%3},{%4,%5,%6,%7},{%8,%9},{%0,%1,%2,%3};" \
                 : "+f"((c)[0]), "+f"((c)[1]), "+f"((c)[2]), "+f"((c)[3]) \
                 : "r"((a)[0]), "r"((a)[1]), "r"((a)[2]), "r"((a)[3]), "r"(b0), "r"(b1))

// ============================================================================
// Kernel 1: bf16 tensor-core batched GEMM with inline fp32->bf16 conversion
//   g_gi[s,m,g] = text[s,m,:512] . tg_Wih[s,g,:512] + tg_bih[s,g]
//   block tile 128(M) x 192(N, full), K-tile 64, double-buffered smem,
//   256 threads = 8 warps (4m x 2n), warp tile 32x96.
// ============================================================================
#define SA_STRIDE 72
#define SA_SIZE (128 * SA_STRIDE)
#define SB_SIZE (192 * SA_STRIDE)
#define STAGE_ELEMS (SA_SIZE + SB_SIZE)
#define GEMM_SMEM_BYTES (STAGE_ELEMS * 2 * 2)

__global__ __launch_bounds__(256) void k_text_gemm_bf16(
    const float* __restrict__ A, const float* __restrict__ W,
    const float* __restrict__ bih)
{
    extern __shared__ __nv_bfloat16 sm[];
    const int s  = blockIdx.y;
    const int m0 = blockIdx.x * 128;

    const float* Ab = A + (size_t)s * MROWS * FT;
    const float* Wb = W + (size_t)s * GG * FT;

    const int tid  = threadIdx.x;
    const int lane = tid & 31;
    const int warp = tid >> 5;
    const int wm   = (warp >> 1) * 32;   // 0,32,64,96
    const int wn   = (warp & 1) * 96;    // 0,96

    const int lrow = tid >> 3;           // 0..31
    const int lk   = (tid & 7) * 8;      // 0..56

    float acc[2][12][4];
#pragma unroll
    for (int i = 0; i < 2; i++)
#pragma unroll
        for (int f = 0; f < 12; f++)
#pragma unroll
            for (int v = 0; v < 4; v++) acc[i][f][v] = 0.f;

    // load one pass (32 rows of A or B) for K-tile k0 into given stage
    auto load_pass = [&](int p, int k0, int stage) {
        const int gk = k0 + lk;
        float4 v0, v1;
        __nv_bfloat16* dst;
        if (p < 4) {                       // A pass
            const int r = lrow + 32 * p;
            const int m = m0 + r;
            if (m < MROWS) {
                v0 = *(const float4*)(Ab + (size_t)m * FT + gk);
                v1 = *(const float4*)(Ab + (size_t)m * FT + gk + 4);
            } else {
                v0 = make_float4(0.f, 0.f, 0.f, 0.f);
                v1 = v0;
            }
            dst = sm + stage * STAGE_ELEMS + r * SA_STRIDE + lk;
        } else {                           // B pass
            const int r = lrow + 32 * (p - 4);
            v0 = *(const float4*)(Wb + (size_t)r * FT + gk);
            v1 = *(const float4*)(Wb + (size_t)r * FT + gk + 4);
            dst = sm + stage * STAGE_ELEMS + SA_SIZE + r * SA_STRIDE + lk;
        }
        __nv_bfloat162 p0 = __float22bfloat162_rn(make_float2(v0.x, v0.y));
        __nv_bfloat162 p1 = __float22bfloat162_rn(make_float2(v0.z, v0.w));
        __nv_bfloat162 p2 = __float22bfloat162_rn(make_float2(v1.x, v1.y));
        __nv_bfloat162 p3 = __float22bfloat162_rn(make_float2(v1.z, v1.w));
        uint4 u;
        u.x = *(unsigned*)&p0; u.y = *(unsigned*)&p1;
        u.z = *(unsigned*)&p2; u.w = *(unsigned*)&p3;
        *(uint4*)dst = u;
    };

    // prologue: full tile 0 into stage 0
#pragma unroll
    for (int p = 0; p < 10; p++) load_pass(p, 0, 0);
    __syncthreads();

    const int NKT = FT / 64;   // 8
    for (int kt = 0; kt < NKT; kt++) {
        const int cur = kt & 1, nxt = cur ^ 1;
        const __nv_bfloat16* As_ = sm + cur * STAGE_ELEMS;
        const __nv_bfloat16* Bs_ = As_ + SA_SIZE;

#pragma unroll
        for (int j16 = 0; j16 < 4; j16++) {
            // software pipeline: load a slice of next tile (groups j16, j16+4, j16+8)
            if (kt + 1 < NKT) {
                const int k0n = (kt + 1) * 64;
                load_pass(j16, k0n, nxt);
                load_pass(j16 + 4, k0n, nxt);
                if (j16 < 2) load_pass(j16 + 8, k0n, nxt);
            }

            const int kc = j16 * 16;
            unsigned a[2][4];
#pragma unroll
            for (int mi = 0; mi < 2; mi++) {
                const int r = wm + mi * 16 + (lane & 15);
                const int c = kc + ((lane >> 4) * 8);
                unsigned addr = smem_u32(As_ + r * SA_STRIDE + c);
                LDSM4(a[mi][0], a[mi][1], a[mi][2], a[mi][3], addr);
            }
            unsigned b[12][2];
#pragma unroll
            for (int nj = 0; nj < 6; nj++) {
                const int r = wn + nj * 16 + (lane & 7) + (((lane >> 4) & 1) << 3);
                const int c = kc + (((lane >> 3) & 1) << 3);
                unsigned addr = smem_u32(Bs_ + r * SA_STRIDE + c);
                unsigned t0, t1, t2, t3;
                LDSM4(t0, t1, t2, t3, addr);
                b[2 * nj][0] = t0; b[2 * nj][1] = t1;
                b[2 * nj + 1][0] = t2; b[2 * nj + 1][1] = t3;
            }
#pragma unroll
            for (int mi = 0; mi < 2; mi++)
#pragma unroll
                for (int f = 0; f < 12; f++)
                    MMA16816(acc[mi][f], a[mi], b[f][0], b[f][1]);
        }
        __syncthreads();
    }

    // epilogue: bias + store fp32
#pragma unroll
    for (int mi = 0; mi < 2; mi++) {
        const int row0 = m0 + wm + mi * 16 + (lane >> 2);
#pragma unroll
        for (int f = 0; f < 12; f++) {
            const int col = wn + f * 8 + (lane & 3) * 2;
            const float b0 = bih[s * GG + col];
            const float b1 = bih[s * GG + col + 1];
            if (row0 < MROWS) {
                float2 v = make_float2(acc[mi][f][0] + b0, acc[mi][f][1] + b1);
                *(float2*)(g_gi + ((size_t)s * MROWS + row0) * GG + col) = v;
            }
            if (row0 + 8 < MROWS) {
                float2 v = make_float2(acc[mi][f][2] + b0, acc[mi][f][3] + b1);
                *(float2*)(g_gi + ((size_t)s * MROWS + row0 + 8) * GG + col) = v;
            }
        }
    }
}

// ============================================================================
// Attention pool: softmax_t( tanh(outs @ Wa) . h_last ) @ outs  (4-acc chains)
// ============================================================================
template <int STEPS>
__device__ __forceinline__ void pool_store(
    float (*outs)[HH], const float* hs, const float* wa_s,
    float* sc, float* __restrict__ dst)
{
    const int tid  = threadIdx.x;
    const int warp = tid >> 5;
    const int lane = tid & 31;
    const int nw   = blockDim.x >> 5;

    for (int t = warp; t < STEPS; t += nw) {
        float part = 0.f;
#pragma unroll
        for (int jj = 0; jj < HH; jj += 32) {
            const int j = jj + lane;
            float a0 = 0.f, a1 = 0.f, a2 = 0.f, a3 = 0.f;
#pragma unroll
            for (int i = 0; i < HH; i += 4) {
                a0 = fmaf(outs[t][i + 0], wa_s[(i + 0) * HH + j], a0);
                a1 = fmaf(outs[t][i + 1], wa_s[(i + 1) * HH + j], a1);
                a2 = fmaf(outs[t][i + 2], wa_s[(i + 2) * HH + j], a2);
                a3 = fmaf(outs[t][i + 3], wa_s[(i + 3) * HH + j], a3);
            }
            part = fmaf(ftanh((a0 + a1) + (a2 + a3)), hs[j], part);
        }
#pragma unroll
        for (int o = 16; o; o >>= 1) part += __shfl_xor_sync(0xffffffffu, part, o);
        if (lane == 0) sc[t] = part;
    }
    __syncthreads();
    if (warp == 0) {
        const float v = (lane < STEPS) ? sc[lane] : -3.4e38f;
        float m = v;
#pragma unroll
        for (int o = 16; o; o >>= 1) m = fmaxf(m, __shfl_xor_sync(0xffffffffu, m, o));
        const float e = (lane < STEPS) ? fexp(v - m) : 0.f;
        float su = e;
#pragma unroll
        for (int o = 16; o; o >>= 1) su += __shfl_xor_sync(0xffffffffu, su, o);
        if (lane < STEPS) sc[lane] = e / su;
    }
    __syncthreads();
    if (tid < HH) {
        float a = 0.f;
#pragma unroll
        for (int t = 0; t < STEPS; t++) a = fmaf(sc[t], outs[t][tid], a);
        dst[tid] = a;
    }
}

// ============================================================================
// Kernel 2: text GRU recurrence + pool. One block per (stock, day). 192 threads.
// ============================================================================
__global__ __launch_bounds__(192, 3) void k_text_rec(
    const float* __restrict__ Whh, const float* __restrict__ bhh,
    const float* __restrict__ Wa)
{
    const int sd = blockIdx.x;
    const int s  = sd / ND;
    const int g  = threadIdx.x;

    __shared__ float buf[NT * GG];       // gi during recurrence; Wa during pool
    __shared__ float outs[NT][HH];
    __shared__ float hs[HH];
    __shared__ float ghs[GG];
    __shared__ float sc[32];

    float wh[HH];
    const float* whp = Whh + ((size_t)s * GG + g) * HH;
#pragma unroll
    for (int i = 0; i < HH; i++) wh[i] = whp[i];
    const float bh = bhh[s * GG + g];

    {
        const float4* src = (const float4*)(g_gi + (size_t)sd * NT * GG);
        float4* dst4 = (float4*)buf;
        for (int i = g; i < (NT * GG) / 4; i += 192) dst4[i] = src[i];
    }
    if (g < HH) hs[g] = 0.f;
    __syncthreads();

    for (int t = 0; t < NT; t++) {
        float a0 = 0.f, a1 = 0.f, a2 = 0.f, a3 = 0.f;
#pragma unroll
        for (int i = 0; i < HH; i += 4) {
            a0 = fmaf(wh[i + 0], hs[i + 0], a0);
            a1 = fmaf(wh[i + 1], hs[i + 1], a1);
            a2 = fmaf(wh[i + 2], hs[i + 2], a2);
            a3 = fmaf(wh[i + 3], hs[i + 3], a3);
        }
        ghs[g] = bh + ((a0 + a1) + (a2 + a3));
        __syncthreads();
        if (g < HH) {
            const float* git = buf + t * GG;
            const float r  = fsig(git[g] + ghs[g]);
            const float z  = fsig(git[HH + g] + ghs[HH + g]);
            const float n  = ftanh(git[2 * HH + g] + r * ghs[2 * HH + g]);
            const float hn = (1.f - z) * n + z * hs[g];
            hs[g] = hn;
            outs[t][g] = hn;
        }
        __syncthreads();
    }

    {
        const float4* src = (const float4*)(Wa + (size_t)s * HH * HH);
        float4* dst4 = (float4*)buf;
        for (int i = g; i < (HH * HH) / 4; i += 192) dst4[i] = src[i];
    }
    __syncthreads();
    pool_store<NT>(outs, hs, buf, sc, g_news + (size_t)sd * HH);
}

// ============================================================================
// Kernel 3: generic per-stock GRU + pool (no register-array spills)
//   SRC==0 -> input xin, dst g_pvec;  SRC==1 -> input g_news, dst g_tvec
// ============================================================================
template <int IN, int STEPS, int SRC>
__global__ __launch_bounds__(192) void k_gru_pool(
    const float* __restrict__ xin,
    const float* __restrict__ Wih, const float* __restrict__ Whh,
    const float* __restrict__ bih, const float* __restrict__ bhh,
    const float* __restrict__ Wa)
{
    const int s = blockIdx.x;
    const int g = threadIdx.x;

    __shared__ float xs[STEPS * IN];
    __shared__ float gis[STEPS * GG];
    __shared__ float outs[STEPS][HH];
    __shared__ float hs[HH];
    __shared__ float ghs[GG];
    __shared__ float sc[32];
    __shared__ float wa_s[HH * HH];

    const float* xb = (SRC == 1) ? (g_news + (size_t)s * ND * HH)
                                 : (xin + (size_t)s * STEPS * IN);
    float wh[HH];
    const float* whp = Whh + ((size_t)s * GG + g) * HH;
#pragma unroll
    for (int i = 0; i < HH; i++) wh[i] = whp[i];
    const float bh = bhh[s * GG + g];
    const float bi = bih[s * GG + g];

    for (int i = g; i < STEPS * IN; i += 192) xs[i] = xb[i];
    {
        const float4* src = (const float4*)(Wa + (size_t)s * HH * HH);
        for (int i = g; i < (HH * HH) / 4; i += 192) ((float4*)wa_s)[i] = src[i];
    }
    if (g < HH) hs[g] = 0.f;
    __syncthreads();

    // input projections: STEPS independent accumulator chains, W streamed
    if (SRC == 1) {
        float acct[STEPS];
#pragma unroll
        for (int t = 0; t < STEPS; t++) acct[t] = bi;
        const float* wip = Wih + ((size_t)s * GG + g) * IN;
#pragma unroll 4
        for (int i = 0; i < IN; i++) {
            const float w = wip[i];
#pragma unroll
            for (int t = 0; t < STEPS; t++) acct[t] = fmaf(w, xs[t * IN + i], acct[t]);
        }
#pragma unroll
        for (int t = 0; t < STEPS; t++) gis[t * GG + g] = acct[t];
    } else {
        float wi[IN];
        const float* wip = Wih + ((size_t)s * GG + g) * IN;
#pragma unroll
        for (int i = 0; i < IN; i++) wi[i] = wip[i];
#pragma unroll
        for (int t = 0; t < STEPS; t++) {
            float gi = bi;
#pragma unroll
            for (int i = 0; i < IN; i++) gi = fmaf(wi[i], xs[t * IN + i], gi);
            gis[t * GG + g] = gi;
        }
    }
    __syncthreads();

    for (int t = 0; t < STEPS; t++) {
        float a0 = 0.f, a1 = 0.f, a2 = 0.f, a3 = 0.f;
#pragma unroll
        for (int i = 0; i < HH; i += 4) {
            a0 = fmaf(wh[i + 0], hs[i + 0], a0);
            a1 = fmaf(wh[i + 1], hs[i + 1], a1);
            a2 = fmaf(wh[i + 2], hs[i + 2], a2);
            a3 = fmaf(wh[i + 3], hs[i + 3], a3);
        }
        ghs[g] = bh + ((a0 + a1) + (a2 + a3));
        __syncthreads();
        if (g < HH) {
            const float* git = gis + t * GG;
            const float r  = fsig(git[g] + ghs[g]);
            const float z  = fsig(git[HH + g] + ghs[HH + g]);
            const float n  = ftanh(git[2 * HH + g] + r * ghs[2 * HH + g]);
            const float hn = (1.f - z) * n + z * hs[g];
            hs[g] = hn;
            outs[t][g] = hn;
        }
        __syncthreads();
    }
    float* dst = (SRC == 1 ? g_tvec : g_pvec) + s * HH;
    pool_store<STEPS>(outs, hs, wa_s, sc, dst);
}

// ============================================================================
// Kernel 4: bilinear fusion (float4, smem-staged vectors)
// ============================================================================
__global__ __launch_bounds__(128) void k_bilinear(
    const float* __restrict__ B, const float* __restrict__ bb)
{
    const int o = blockIdx.x, s = blockIdx.y;
    const int tid = threadIdx.x;
    __shared__ float tv_s[HH], pv_s[HH];
    if (tid < HH) { tv_s[tid] = g_tvec[s * HH + tid]; pv_s[tid] = g_pvec[s * HH + tid]; }
    __syncthreads();

    const float* Bp = B + ((size_t)s * HH + o) * HH * HH;
    float acc = 0.f;
#pragma unroll
    for (int it = 0; it < 8; it++) {
        const int k4 = (it * 128 + tid) * 4;
        const float4 v = *(const float4*)(Bp + k4);
        const int i = k4 >> 6, j = k4 & 63;
        float p = pv_s[j] * v.x;
        p = fmaf(pv_s[j + 1], v.y, p);
        p = fmaf(pv_s[j + 2], v.z, p);
        p = fmaf(pv_s[j + 3], v.w, p);
        acc = fmaf(tv_s[i], p, acc);
    }
    __shared__ float red[128];
    red[tid] = acc;
    __syncthreads();
    for (int st2 = 64; st2; st2 >>= 1) {
        if (tid < st2) red[tid] += red[tid + st2];
        __syncthreads();
    }
    if (tid == 0) g_feat[s * HH + o] = ftanh(red[0] + bb[s * HH + o]);
}

// ============================================================================
// Kernel 5: GAT head projection
// ============================================================================
__global__ __launch_bounds__(64) void k_gat_proj(
    const float* __restrict__ gatW, const float* __restrict__ gatA)
{
    const int s = blockIdx.x, nh = blockIdx.y;
    const int j = threadIdx.x;
    const float* Wp = gatW + (size_t)nh * HH * HH;
    const float* x  = g_feat + s * HH;
    float acc = 0.f;
#pragma unroll 8
    for (int i = 0; i < HH; i++) acc = fmaf(x[i], Wp[i * HH + j], acc);
    g_hgat[((size_t)nh * NS + s) * HH + j] = acc;

    __shared__ float r1[64], r2[64];
    r1[j] = acc * gatA[nh * 2 * HH + j];
    r2[j] = acc * gatA[nh * 2 * HH + HH + j];
    __syncthreads();
    if (j < 32) {
        float v1 = r1[j] + r1[j + 32];
        float v2 = r2[j] + r2[j + 32];
#pragma unroll
        for (int o = 16; o; o >>= 1) {
            v1 += __shfl_xor_sync(0xffffffffu, v1, o);
            v2 += __shfl_xor_sync(0xffffffffu, v2, o);
        }
        if (j == 0) { g_f1[nh * NS + s] = v1; g_f2[nh * NS + s] = v2; }
    }
}

// ============================================================================
// Kernel 6: GAT masked attention + elu (warp-parallel softmax)
// ============================================================================
__global__ __launch_bounds__(128) void k_gat_attn(const float* __restrict__ adj)
{
    const int s = blockIdx.x, nh = blockIdx.y;
    const int tid = threadIdx.x;
    __shared__ float att[NS];
    __shared__ float sinv;
    const float f1v = g_f1[nh * NS + s];
    if (tid < NS) {
        float v = f1v + g_f2[nh * NS + tid];
        v = (v >= 0.f) ? v : 0.2f * v;
        att[tid] = (adj[s * NS + tid] > 0.f) ? v : -9e15f;
    }
    __syncthreads();
    if (tid < 32) {
        float m = -3.4e38f;
        for (int t = tid; t < NS; t += 32) m = fmaxf(m, att[t]);
#pragma unroll
        for (int o = 16; o; o >>= 1) m = fmaxf(m, __shfl_xor_sync(0xffffffffu, m, o));
        float su = 0.f;
        for (int t = tid; t < NS; t += 32) {
            const float e = fexp(att[t] - m);
            att[t] = e;
            su += e;
        }
#pragma unroll
        for (int o = 16; o; o >>= 1) su += __shfl_xor_sync(0xffffffffu, su, o);
        if (tid == 0) sinv = 1.f / su;
    }
    __syncthreads();
    if (tid < HH) {
        float acc = 0.f;
        for (int t = 0; t < NS; t++)
            acc = fmaf(att[t], g_hgat[((size_t)nh * NS + t) * HH + tid], acc);
        acc = felu(acc * sinv);
        g_x2[(size_t)s * (NHD * HH) + nh * HH + tid] = acc;
    }
}

// ============================================================================
// Kernel 7: final — out-layer GAT, blend, double softmax, loss. One block.
// ============================================================================
__global__ __launch_bounds__(128) void k_final(
    const float* __restrict__ blW, const float* __restrict__ blb,
    const float* __restrict__ outW, const float* __restrict__ outA,
    const float* __restrict__ adj, const int* __restrict__ label,
    float* __restrict__ out, int out_size)
{
    __shared__ float h2[NS][2];
    __shared__ float f1s[NS], f2s[NS];
    __shared__ float o1[NS][2];
    __shared__ float adj_s[NS * NS];
    __shared__ float red[128];
    const int tid  = threadIdx.x;
    const int warp = tid >> 5;
    const int lane = tid & 31;

    for (int i = tid; i < NS * NS; i += 128) adj_s[i] = adj[i];

    for (int s = warp; s < NS; s += 4) {
        const float* xr = g_x2 + (size_t)s * NHD * HH;
        float a0 = 0.f, a1 = 0.f;
        for (int k = lane; k < NHD * HH; k += 32) {
            const float xv = xr[k];
            a0 = fmaf(xv, outW[2 * k + 0], a0);
            a1 = fmaf(xv, outW[2 * k + 1], a1);
        }
        const float* fr = g_feat + s * HH;
        float b0 = 0.f, b1 = 0.f;
        for (int k = lane; k < HH; k += 32) {
            const float fv = fr[k];
            b0 = fmaf(fv, blW[2 * k + 0], b0);
            b1 = fmaf(fv, blW[2 * k + 1], b1);
        }
#pragma unroll
        for (int o = 16; o; o >>= 1) {
            a0 += __shfl_xor_sync(0xffffffffu, a0, o);
            a1 += __shfl_xor_sync(0xffffffffu, a1, o);
            b0 += __shfl_xor_sync(0xffffffffu, b0, o);
            b1 += __shfl_xor_sync(0xffffffffu, b1, o);
        }
        if (lane == 0) {
            h2[s][0] = a0; h2[s][1] = a1;
            f1s[s] = a0 * outA[0] + a1 * outA[1];
            f2s[s] = a0 * outA[2] + a1 * outA[3];
            o1[s][0] = ftanh(b0 + blb[0]);
            o1[s][1] = ftanh(b1 + blb[1]);
        }
    }
    __syncthreads();

    const int off = (out_size > 200) ? (out_size - 200) : 0;
    float lsum = 0.f;
    for (int s = tid; s < NS; s += 128) {
        float m = -3.4e38f;
        for (int t = 0; t < NS; t++) {
            float v = f1s[s] + f2s[t];
            v = (v >= 0.f) ? v : 0.2f * v;
            v = (adj_s[s * NS + t] > 0.f) ? v : -9e15f;
            m = fmaxf(m, v);
        }
        float su = 0.f, a0 = 0.f, a1 = 0.f;
        for (int t = 0; t < NS; t++) {
            float v = f1s[s] + f2s[t];
            v = (v >= 0.f) ? v : 0.2f * v;
            v = (adj_s[s * NS + t] > 0.f) ? v : -9e15f;
            const float e = fexp(v - m);
            su += e;
            a0 = fmaf(e, h2[t][0], a0);
            a1 = fmaf(e, h2[t][1], a1);
        }
        a0 /= su; a1 /= su;
        a0 = felu(a0);
        a1 = felu(a1);
        const float z0 = a0 + o1[s][0];
        const float z1 = a1 + o1[s][1];
        const float zm = fmaxf(z0, z1);
        const float e0 = fexp(z0 - zm), e1 = fexp(z1 - zm);
        const float p0 = e0 / (e0 + e1), p1 = e1 / (e0 + e1);
        if (out_size >= 200) { out[off + 2 * s] = p0; out[off + 2 * s + 1] = p1; }
        const float pm  = fmaxf(p0, p1);
        const float lse = pm + logf(fexp(p0 - pm) + fexp(p1 - pm));
        const float chosen = (label[s] == 0) ? p0 : p1;
        lsum += (lse - chosen);
    }
    red[tid] = lsum;
    __syncthreads();
    for (int st2 = 64; st2; st2 >>= 1) {
        if (tid < st2) red[tid] += red[tid + st2];
        __syncthreads();
    }
    if (tid == 0 && (out_size == 1 || out_size > 200)) out[0] = red[0] * (1.f / NS);
}

// ============================================================================
extern "C" void kernel_launch(void* const* d_in, const int* in_sizes, int n_in,
                              void* d_out, int out_size)
{
    (void)in_sizes;
    const float* text  = (const float*)d_in[0];
    const float* price = (const float*)d_in[1];
    const int*   label = (const int*)d_in[2];
    const float* adj   = (const float*)d_in[3];
    const int wb = n_in - 23;
    const float* pg_Wih = (const float*)d_in[wb + 0];
    const float* pg_Whh = (const float*)d_in[wb + 1];
    const float* pg_bih = (const float*)d_in[wb + 2];
    const float* pg_bhh = (const float*)d_in[wb + 3];
    const float* pa_W   = (const float*)d_in[wb + 4];
    const float* tg_Wih = (const float*)d_in[wb + 5];
    const float* tg_Whh = (const float*)d_in[wb + 6];
    const float* tg_bih = (const float*)d_in[wb + 7];
    const float* tg_bhh = (const float*)d_in[wb + 8];
    const float* ta_W   = (const float*)d_in[wb + 9];
    const float* sg_Wih = (const float*)d_in[wb + 10];
    const float* sg_Whh = (const float*)d_in[wb + 11];
    const float* sg_bih = (const float*)d_in[wb + 12];
    const float* sg_bhh = (const float*)d_in[wb + 13];
    const float* sa_W   = (const float*)d_in[wb + 14];
    const float* bil_B  = (const float*)d_in[wb + 15];
    const float* bil_b  = (const float*)d_in[wb + 16];
    const float* bl_W   = (const float*)d_in[wb + 17];
    const float* bl_b   = (const float*)d_in[wb + 18];
    const float* gat_W  = (const float*)d_in[wb + 19];
    const float* gat_a  = (const float*)d_in[wb + 20];
    const float* out_W  = (const float*)d_in[wb + 21];
    const float* out_a  = (const float*)d_in[wb + 22];

    static bool smem_set = false;
    if (!smem_set) {
        cudaFuncSetAttribute(k_text_gemm_bf16,
                             cudaFuncAttributeMaxDynamicSharedMemorySize,
                             GEMM_SMEM_BYTES);
        smem_set = true;
    }

    // 1) bf16 tensor-core batched GEMM: text GRU input projections
    k_text_gemm_bf16<<<dim3(5, NS), 256, GEMM_SMEM_BYTES>>>(text, tg_Wih, tg_bih);
    // price path (independent)
    k_gru_pool<FP, ND, 0><<<NS, 192>>>(price, pg_Wih, pg_Whh, pg_bih, pg_bhh, pa_W);
    // 2) 2000 text GRU recurrences + attention pooling -> g_news
    k_text_rec<<<NS * ND, 192>>>(tg_Whh, tg_bhh, ta_W);
    // 3) day-sequence GRU over g_news + pool -> g_tvec
    k_gru_pool<HH, ND, 1><<<NS, 192>>>(nullptr, sg_Wih, sg_Whh, sg_bih, sg_bhh, sa_W);
    // 4) bilinear fusion -> g_feat
    k_bilinear<<<dim3(HH, NS), 128>>>(bil_B, bil_b);
    // 5) GAT heads
    k_gat_proj<<<dim3(NS, NHD), 64>>>(gat_W, gat_a);
    k_gat_attn<<<dim3(NS, NHD), 128>>>(adj);
    // 6) output GAT layer + blend + softmax + loss
    k_final<<<1, 128>>>(bl_W, bl_b, out_W, out_a, adj, label, (float*)d_out, out_size);
}

// round 5
// speedup vs baseline: 1.9592x; 1.0661x over previous
#include <cuda_runtime.h>
#include <cuda_bf16.h>
#include <math.h>

#define NS 100     // stocks
#define ND 20      // days
#define NT 30      // texts per day
#define HH 64      // hidden
#define GG 192     // 3*H
#define NHD 8      // GAT heads
#define FT 512     // text feature
#define FP 3       // price feature
#define MROWS 600  // ND*NT

#define WHS_PAD 65
#define WHS_ELEMS (GG * WHS_PAD)   // 12480 floats

// ---------------- scratch (device globals; no runtime allocation) ----------------
__device__ float g_gi[(size_t)NS * MROWS * GG];   // text GRU input projections
__device__ float g_news[NS * ND * HH];
__device__ float g_pvec[NS * HH];
__device__ float g_tvec[NS * HH];
__device__ float g_feat[NS * HH];
__device__ float g_hgat[NHD * NS * HH];
__device__ float g_f1[NHD * NS];
__device__ float g_f2[NHD * NS];
__device__ float g_x2[NS * NHD * HH];

#define LOG2E 1.4426950408889634f

__device__ __forceinline__ float fexp2(float x) { float r; asm("ex2.approx.f32 %0,%1;" : "=f"(r) : "f"(x)); return r; }
__device__ __forceinline__ float frcp(float x)  { float r; asm("rcp.approx.f32 %0,%1;" : "=f"(r) : "f"(x)); return r; }
__device__ __forceinline__ float fsig(float x)  { return frcp(1.f + fexp2(-LOG2E * x)); }
__device__ __forceinline__ float ftanh(float x) { return 1.f - 2.f * frcp(1.f + fexp2(2.f * LOG2E * x)); }
__device__ __forceinline__ float fexp(float x)  { return fexp2(LOG2E * x); }
__device__ __forceinline__ float felu(float x)  { return (x > 0.f) ? x : (fexp(x) - 1.f); }

__device__ __forceinline__ unsigned smem_u32(const void* p) {
    return (unsigned)__cvta_generic_to_shared(p);
}

// coalesced stage of a [192,64] fp32 matrix into padded smem [192][65]
__device__ __forceinline__ void stage_w(const float* __restrict__ src, float* whs, int tid, int nthr)
{
    const float4* s4 = (const float4*)src;
    for (int idx = tid; idx < (GG * HH) / 4; idx += nthr) {
        const float4 v = s4[idx];
        const int base = idx * 4;
        const int row = base >> 6;
        const int col = base & 63;
        float* d = whs + row * WHS_PAD + col;
        d[0] = v.x; d[1] = v.y; d[2] = v.z; d[3] = v.w;
    }
}

#define LDSM4(r0, r1, r2, r3, addr) \
    asm volatile("ldmatrix.sync.aligned.m8n8.x4.shared.b16 {%0,%1,%2,%3},[%4];" \
                 : "=r"(r0), "=r"(r1), "=r"(r2), "=r"(r3) : "r"(addr))

#define MMA16816(c, a, b0, b1) \
    asm volatile("mma.sync.aligned.m16n8k16.row.col.f32.bf16.bf16.f32 " \
                 "{%0,%1,%2,%3},{%4,%5,%6,%7},{%8,%9},{%0,%1,%2,%3};" \
                 : "+f"((c)[0]), "+f"((c)[1]), "+f"((c)[2]), "+f"((c)[3]) \
                 : "r"((a)[0]), "r"((a)[1]), "r"((a)[2]), "r"((a)[3]), "r"(b0), "r"(b1))

// ============================================================================
// Kernel 1: bf16 tensor-core batched GEMM with inline fp32->bf16 conversion
// ============================================================================
#define SA_STRIDE 72
#define SA_SIZE (128 * SA_STRIDE)
#define SB_SIZE (192 * SA_STRIDE)
#define STAGE_ELEMS (SA_SIZE + SB_SIZE)
#define GEMM_SMEM_BYTES (STAGE_ELEMS * 2 * 2)

__global__ __launch_bounds__(256) void k_text_gemm_bf16(
    const float* __restrict__ A, const float* __restrict__ W,
    const float* __restrict__ bih)
{
    extern __shared__ __nv_bfloat16 sm[];
    const int s  = blockIdx.y;
    const int m0 = blockIdx.x * 128;

    const float* Ab = A + (size_t)s * MROWS * FT;
    const float* Wb = W + (size_t)s * GG * FT;

    const int tid  = threadIdx.x;
    const int lane = tid & 31;
    const int warp = tid >> 5;
    const int wm   = (warp >> 1) * 32;
    const int wn   = (warp & 1) * 96;

    const int lrow = tid >> 3;
    const int lk   = (tid & 7) * 8;

    float acc[2][12][4];
#pragma unroll
    for (int i = 0; i < 2; i++)
#pragma unroll
        for (int f = 0; f < 12; f++)
#pragma unroll
            for (int v = 0; v < 4; v++) acc[i][f][v] = 0.f;

    auto load_pass = [&](int p, int k0, int stage) {
        const int gk = k0 + lk;
        float4 v0, v1;
        __nv_bfloat16* dst;
        if (p < 4) {
            const int r = lrow + 32 * p;
            const int m = m0 + r;
            if (m < MROWS) {
                v0 = *(const float4*)(Ab + (size_t)m * FT + gk);
                v1 = *(const float4*)(Ab + (size_t)m * FT + gk + 4);
            } else {
                v0 = make_float4(0.f, 0.f, 0.f, 0.f);
                v1 = v0;
            }
            dst = sm + stage * STAGE_ELEMS + r * SA_STRIDE + lk;
        } else {
            const int r = lrow + 32 * (p - 4);
            v0 = *(const float4*)(Wb + (size_t)r * FT + gk);
            v1 = *(const float4*)(Wb + (size_t)r * FT + gk + 4);
            dst = sm + stage * STAGE_ELEMS + SA_SIZE + r * SA_STRIDE + lk;
        }
        __nv_bfloat162 p0 = __float22bfloat162_rn(make_float2(v0.x, v0.y));
        __nv_bfloat162 p1 = __float22bfloat162_rn(make_float2(v0.z, v0.w));
        __nv_bfloat162 p2 = __float22bfloat162_rn(make_float2(v1.x, v1.y));
        __nv_bfloat162 p3 = __float22bfloat162_rn(make_float2(v1.z, v1.w));
        uint4 u;
        u.x = *(unsigned*)&p0; u.y = *(unsigned*)&p1;
        u.z = *(unsigned*)&p2; u.w = *(unsigned*)&p3;
        *(uint4*)dst = u;
    };

#pragma unroll
    for (int p = 0; p < 10; p++) load_pass(p, 0, 0);
    __syncthreads();

    const int NKT = FT / 64;
    for (int kt = 0; kt < NKT; kt++) {
        const int cur = kt & 1, nxt = cur ^ 1;
        const __nv_bfloat16* As_ = sm + cur * STAGE_ELEMS;
        const __nv_bfloat16* Bs_ = As_ + SA_SIZE;

#pragma unroll
        for (int j16 = 0; j16 < 4; j16++) {
            if (kt + 1 < NKT) {
                const int k0n = (kt + 1) * 64;
                load_pass(j16, k0n, nxt);
                load_pass(j16 + 4, k0n, nxt);
                if (j16 < 2) load_pass(j16 + 8, k0n, nxt);
            }

            const int kc = j16 * 16;
            unsigned a[2][4];
#pragma unroll
            for (int mi = 0; mi < 2; mi++) {
                const int r = wm + mi * 16 + (lane & 15);
                const int c = kc + ((lane >> 4) * 8);
                unsigned addr = smem_u32(As_ + r * SA_STRIDE + c);
                LDSM4(a[mi][0], a[mi][1], a[mi][2], a[mi][3], addr);
            }
            unsigned b[12][2];
#pragma unroll
            for (int nj = 0; nj < 6; nj++) {
                const int r = wn + nj * 16 + (lane & 7) + (((lane >> 4) & 1) << 3);
                const int c = kc + (((lane >> 3) & 1) << 3);
                unsigned addr = smem_u32(Bs_ + r * SA_STRIDE + c);
                unsigned t0, t1, t2, t3;
                LDSM4(t0, t1, t2, t3, addr);
                b[2 * nj][0] = t0; b[2 * nj][1] = t1;
                b[2 * nj + 1][0] = t2; b[2 * nj + 1][1] = t3;
            }
#pragma unroll
            for (int mi = 0; mi < 2; mi++)
#pragma unroll
                for (int f = 0; f < 12; f++)
                    MMA16816(acc[mi][f], a[mi], b[f][0], b[f][1]);
        }
        __syncthreads();
    }

#pragma unroll
    for (int mi = 0; mi < 2; mi++) {
        const int row0 = m0 + wm + mi * 16 + (lane >> 2);
#pragma unroll
        for (int f = 0; f < 12; f++) {
            const int col = wn + f * 8 + (lane & 3) * 2;
            const float b0 = bih[s * GG + col];
            const float b1 = bih[s * GG + col + 1];
            if (row0 < MROWS) {
                float2 v = make_float2(acc[mi][f][0] + b0, acc[mi][f][1] + b1);
                *(float2*)(g_gi + ((size_t)s * MROWS + row0) * GG + col) = v;
            }
            if (row0 + 8 < MROWS) {
                float2 v = make_float2(acc[mi][f][2] + b0, acc[mi][f][3] + b1);
                *(float2*)(g_gi + ((size_t)s * MROWS + row0 + 8) * GG + col) = v;
            }
        }
    }
}

// ============================================================================
// Attention pool: softmax_t( tanh(outs @ Wa) . h_last ) @ outs
// ============================================================================
template <int STEPS>
__device__ __forceinline__ void pool_store(
    const float* outs, const float* hs, const float* wa_s,
    float* sc, float* __restrict__ dst)
{
    const int tid  = threadIdx.x;
    const int warp = tid >> 5;
    const int lane = tid & 31;
    const int nw   = blockDim.x >> 5;

    for (int t = warp; t < STEPS; t += nw) {
        float part = 0.f;
#pragma unroll
        for (int jj = 0; jj < HH; jj += 32) {
            const int j = jj + lane;
            float a0 = 0.f, a1 = 0.f, a2 = 0.f, a3 = 0.f;
#pragma unroll
            for (int i = 0; i < HH; i += 4) {
                a0 = fmaf(outs[t * HH + i + 0], wa_s[(i + 0) * HH + j], a0);
                a1 = fmaf(outs[t * HH + i + 1], wa_s[(i + 1) * HH + j], a1);
                a2 = fmaf(outs[t * HH + i + 2], wa_s[(i + 2) * HH + j], a2);
                a3 = fmaf(outs[t * HH + i + 3], wa_s[(i + 3) * HH + j], a3);
            }
            part = fmaf(ftanh((a0 + a1) + (a2 + a3)), hs[j], part);
        }
#pragma unroll
        for (int o = 16; o; o >>= 1) part += __shfl_xor_sync(0xffffffffu, part, o);
        if (lane == 0) sc[t] = part;
    }
    __syncthreads();
    if (warp == 0) {
        const float v = (lane < STEPS) ? sc[lane] : -3.4e38f;
        float m = v;
#pragma unroll
        for (int o = 16; o; o >>= 1) m = fmaxf(m, __shfl_xor_sync(0xffffffffu, m, o));
        const float e = (lane < STEPS) ? fexp(v - m) : 0.f;
        float su = e;
#pragma unroll
        for (int o = 16; o; o >>= 1) su += __shfl_xor_sync(0xffffffffu, su, o);
        if (lane < STEPS) sc[lane] = e / su;
    }
    __syncthreads();
    if (tid < HH) {
        float a = 0.f;
#pragma unroll
        for (int t = 0; t < STEPS; t++) a = fmaf(sc[t], outs[t * HH + tid], a);
        dst[tid] = a;
    }
}

// ============================================================================
// Kernel 2: text GRU recurrence + pool. One block per (stock, day).
//   dyn smem: whs[192*65] | buf[NT*GG] (gi; then Wa) | outs | hs | ghs | sc
// ============================================================================
#define TEXT_REC_SMEM ((WHS_ELEMS + NT * GG + NT * HH + HH + GG + 32) * 4)

__global__ __launch_bounds__(192) void k_text_rec(
    const float* __restrict__ Whh, const float* __restrict__ bhh,
    const float* __restrict__ Wa)
{
    extern __shared__ float dyn[];
    float* whs  = dyn;                       // 192*65
    float* buf  = whs + WHS_ELEMS;           // NT*GG
    float* outs = buf + NT * GG;             // NT*HH
    float* hs   = outs + NT * HH;            // 64
    float* ghs  = hs + HH;                   // 192
    float* sc   = ghs + GG;                  // 32

    const int sd = blockIdx.x;
    const int s  = sd / ND;
    const int g  = threadIdx.x;

    const float bh = bhh[s * GG + g];

    stage_w(Whh + (size_t)s * GG * HH, whs, g, 192);
    {
        const float4* src = (const float4*)(g_gi + (size_t)sd * NT * GG);
        float4* dst4 = (float4*)buf;
        for (int i = g; i < (NT * GG) / 4; i += 192) dst4[i] = src[i];
    }
    if (g < HH) hs[g] = 0.f;
    __syncthreads();

    float wh[HH];
#pragma unroll
    for (int i = 0; i < HH; i++) wh[i] = whs[g * WHS_PAD + i];

    for (int t = 0; t < NT; t++) {
        float a0 = 0.f, a1 = 0.f, a2 = 0.f, a3 = 0.f;
#pragma unroll
        for (int i = 0; i < HH; i += 4) {
            a0 = fmaf(wh[i + 0], hs[i + 0], a0);
            a1 = fmaf(wh[i + 1], hs[i + 1], a1);
            a2 = fmaf(wh[i + 2], hs[i + 2], a2);
            a3 = fmaf(wh[i + 3], hs[i + 3], a3);
        }
        ghs[g] = bh + ((a0 + a1) + (a2 + a3));
        __syncthreads();
        if (g < HH) {
            const float* git = buf + t * GG;
            const float r  = fsig(git[g] + ghs[g]);
            const float z  = fsig(git[HH + g] + ghs[HH + g]);
            const float n  = ftanh(git[2 * HH + g] + r * ghs[2 * HH + g]);
            const float hn = (1.f - z) * n + z * hs[g];
            hs[g] = hn;
            outs[t * HH + g] = hn;
        }
        __syncthreads();
    }

    {
        const float4* src = (const float4*)(Wa + (size_t)s * HH * HH);
        float4* dst4 = (float4*)buf;
        for (int i = g; i < (HH * HH) / 4; i += 192) dst4[i] = src[i];
    }
    __syncthreads();
    pool_store<NT>(outs, hs, buf, sc, g_news + (size_t)sd * HH);
}

// ============================================================================
// Kernel 3: generic per-stock GRU + pool, staged weights
//   SRC==0 -> input xin, dst g_pvec;  SRC==1 -> input g_news, dst g_tvec
//   dyn smem: whs | gis[STEPS*GG] | outs[STEPS*HH] | wa[4096] | xs[STEPS*IN] | hs | ghs | sc
// ============================================================================
template <int IN, int STEPS, int SRC>
__global__ __launch_bounds__(192) void k_gru_pool(
    const float* __restrict__ xin,
    const float* __restrict__ Wih, const float* __restrict__ Whh,
    const float* __restrict__ bih, const float* __restrict__ bhh,
    const float* __restrict__ Wa)
{
    extern __shared__ float dyn[];
    float* whs  = dyn;
    float* gis  = whs + WHS_ELEMS;
    float* outs = gis + STEPS * GG;
    float* wa_s = outs + STEPS * HH;
    float* xs   = wa_s + HH * HH;
    float* hs   = xs + STEPS * IN;
    float* ghs  = hs + HH;
    float* sc   = ghs + GG;

    const int s = blockIdx.x;
    const int g = threadIdx.x;

    const float* xb = (SRC == 1) ? (g_news + (size_t)s * ND * HH)
                                 : (xin + (size_t)s * STEPS * IN);
    const float bh = bhh[s * GG + g];
    const float bi = bih[s * GG + g];

    for (int i = g; i < STEPS * IN; i += 192) xs[i] = xb[i];
    {
        const float4* src = (const float4*)(Wa + (size_t)s * HH * HH);
        for (int i = g; i < (HH * HH) / 4; i += 192) ((float4*)wa_s)[i] = src[i];
    }
    if (g < HH) hs[g] = 0.f;

    if (IN == HH) {
        // stage Wih, compute gis from smem, then stage Whh into same buffer
        stage_w(Wih + (size_t)s * GG * IN, whs, g, 192);
        __syncthreads();
        float acct[STEPS];
#pragma unroll
        for (int t = 0; t < STEPS; t++) acct[t] = bi;
#pragma unroll 4
        for (int i = 0; i < IN; i++) {
            const float w = whs[g * WHS_PAD + i];
#pragma unroll
            for (int t = 0; t < STEPS; t++) acct[t] = fmaf(w, xs[t * IN + i], acct[t]);
        }
#pragma unroll
        for (int t = 0; t < STEPS; t++) gis[t * GG + g] = acct[t];
        __syncthreads();
        stage_w(Whh + (size_t)s * GG * HH, whs, g, 192);
        __syncthreads();
    } else {
        // tiny input: direct loads for Wih
        float wi[IN];
        const float* wip = Wih + ((size_t)s * GG + g) * IN;
#pragma unroll
        for (int i = 0; i < IN; i++) wi[i] = wip[i];
        stage_w(Whh + (size_t)s * GG * HH, whs, g, 192);
        __syncthreads();
#pragma unroll
        for (int t = 0; t < STEPS; t++) {
            float gi = bi;
#pragma unroll
            for (int i = 0; i < IN; i++) gi = fmaf(wi[i], xs[t * IN + i], gi);
            gis[t * GG + g] = gi;
        }
        __syncthreads();
    }

    float wh[HH];
#pragma unroll
    for (int i = 0; i < HH; i++) wh[i] = whs[g * WHS_PAD + i];

    for (int t = 0; t < STEPS; t++) {
        float a0 = 0.f, a1 = 0.f, a2 = 0.f, a3 = 0.f;
#pragma unroll
        for (int i = 0; i < HH; i += 4) {
            a0 = fmaf(wh[i + 0], hs[i + 0], a0);
            a1 = fmaf(wh[i + 1], hs[i + 1], a1);
            a2 = fmaf(wh[i + 2], hs[i + 2], a2);
            a3 = fmaf(wh[i + 3], hs[i + 3], a3);
        }
        ghs[g] = bh + ((a0 + a1) + (a2 + a3));
        __syncthreads();
        if (g < HH) {
            const float* git = gis + t * GG;
            const float r  = fsig(git[g] + ghs[g]);
            const float z  = fsig(git[HH + g] + ghs[HH + g]);
            const float n  = ftanh(git[2 * HH + g] + r * ghs[2 * HH + g]);
            const float hn = (1.f - z) * n + z * hs[g];
            hs[g] = hn;
            outs[t * HH + g] = hn;
        }
        __syncthreads();
    }
    float* dst = (SRC == 1 ? g_tvec : g_pvec) + s * HH;
    pool_store<STEPS>(outs, hs, wa_s, sc, dst);
}

// ============================================================================
// Kernel 4: bilinear fusion (float4, smem-staged vectors)
// ============================================================================
__global__ __launch_bounds__(128) void k_bilinear(
    const float* __restrict__ B, const float* __restrict__ bb)
{
    const int o = blockIdx.x, s = blockIdx.y;
    const int tid = threadIdx.x;
    __shared__ float tv_s[HH], pv_s[HH];
    if (tid < HH) { tv_s[tid] = g_tvec[s * HH + tid]; pv_s[tid] = g_pvec[s * HH + tid]; }
    __syncthreads();

    const float* Bp = B + ((size_t)s * HH + o) * HH * HH;
    float acc = 0.f;
#pragma unroll
    for (int it = 0; it < 8; it++) {
        const int k4 = (it * 128 + tid) * 4;
        const float4 v = *(const float4*)(Bp + k4);
        const int i = k4 >> 6, j = k4 & 63;
        float p = pv_s[j] * v.x;
        p = fmaf(pv_s[j + 1], v.y, p);
        p = fmaf(pv_s[j + 2], v.z, p);
        p = fmaf(pv_s[j + 3], v.w, p);
        acc = fmaf(tv_s[i], p, acc);
    }
    __shared__ float red[128];
    red[tid] = acc;
    __syncthreads();
    for (int st2 = 64; st2; st2 >>= 1) {
        if (tid < st2) red[tid] += red[tid + st2];
        __syncthreads();
    }
    if (tid == 0) g_feat[s * HH + o] = ftanh(red[0] + bb[s * HH + o]);
}

// ============================================================================
// Kernel 5: GAT head projection
// ============================================================================
__global__ __launch_bounds__(64) void k_gat_proj(
    const float* __restrict__ gatW, const float* __restrict__ gatA)
{
    const int s = blockIdx.x, nh = blockIdx.y;
    const int j = threadIdx.x;
    const float* Wp = gatW + (size_t)nh * HH * HH;
    const float* x  = g_feat + s * HH;
    float acc = 0.f;
#pragma unroll 8
    for (int i = 0; i < HH; i++) acc = fmaf(x[i], Wp[i * HH + j], acc);
    g_hgat[((size_t)nh * NS + s) * HH + j] = acc;

    __shared__ float r1[64], r2[64];
    r1[j] = acc * gatA[nh * 2 * HH + j];
    r2[j] = acc * gatA[nh * 2 * HH + HH + j];
    __syncthreads();
    if (j < 32) {
        float v1 = r1[j] + r1[j + 32];
        float v2 = r2[j] + r2[j + 32];
#pragma unroll
        for (int o = 16; o; o >>= 1) {
            v1 += __shfl_xor_sync(0xffffffffu, v1, o);
            v2 += __shfl_xor_sync(0xffffffffu, v2, o);
        }
        if (j == 0) { g_f1[nh * NS + s] = v1; g_f2[nh * NS + s] = v2; }
    }
}

// ============================================================================
// Kernel 6: GAT masked attention + elu (warp-parallel softmax)
// ============================================================================
__global__ __launch_bounds__(128) void k_gat_attn(const float* __restrict__ adj)
{
    const int s = blockIdx.x, nh = blockIdx.y;
    const int tid = threadIdx.x;
    __shared__ float att[NS];
    __shared__ float sinv;
    const float f1v = g_f1[nh * NS + s];
    if (tid < NS) {
        float v = f1v + g_f2[nh * NS + tid];
        v = (v >= 0.f) ? v : 0.2f * v;
        att[tid] = (adj[s * NS + tid] > 0.f) ? v : -9e15f;
    }
    __syncthreads();
    if (tid < 32) {
        float m = -3.4e38f;
        for (int t = tid; t < NS; t += 32) m = fmaxf(m, att[t]);
#pragma unroll
        for (int o = 16; o; o >>= 1) m = fmaxf(m, __shfl_xor_sync(0xffffffffu, m, o));
        float su = 0.f;
        for (int t = tid; t < NS; t += 32) {
            const float e = fexp(att[t] - m);
            att[t] = e;
            su += e;
        }
#pragma unroll
        for (int o = 16; o; o >>= 1) su += __shfl_xor_sync(0xffffffffu, su, o);
        if (tid == 0) sinv = 1.f / su;
    }
    __syncthreads();
    if (tid < HH) {
        float acc = 0.f;
        for (int t = 0; t < NS; t++)
            acc = fmaf(att[t], g_hgat[((size_t)nh * NS + t) * HH + tid], acc);
        acc = felu(acc * sinv);
        g_x2[(size_t)s * (NHD * HH) + nh * HH + tid] = acc;
    }
}

// ============================================================================
// Kernel 7: final — out-layer GAT, blend, double softmax, loss. One block.
// ============================================================================
__global__ __launch_bounds__(128) void k_final(
    const float* __restrict__ blW, const float* __restrict__ blb,
    const float* __restrict__ outW, const float* __restrict__ outA,
    const float* __restrict__ adj, const int* __restrict__ label,
    float* __restrict__ out, int out_size)
{
    __shared__ float h2[NS][2];
    __shared__ float f1s[NS], f2s[NS];
    __shared__ float o1[NS][2];
    __shared__ float adj_s[NS * NS];
    __shared__ float red[128];
    const int tid  = threadIdx.x;
    const int warp = tid >> 5;
    const int lane = tid & 31;

    for (int i = tid; i < NS * NS; i += 128) adj_s[i] = adj[i];

    for (int s = warp; s < NS; s += 4) {
        const float* xr = g_x2 + (size_t)s * NHD * HH;
        float a0 = 0.f, a1 = 0.f;
        for (int k = lane; k < NHD * HH; k += 32) {
            const float xv = xr[k];
            a0 = fmaf(xv, outW[2 * k + 0], a0);
            a1 = fmaf(xv, outW[2 * k + 1], a1);
        }
        const float* fr = g_feat + s * HH;
        float b0 = 0.f, b1 = 0.f;
        for (int k = lane; k < HH; k += 32) {
            const float fv = fr[k];
            b0 = fmaf(fv, blW[2 * k + 0], b0);
            b1 = fmaf(fv, blW[2 * k + 1], b1);
        }
#pragma unroll
        for (int o = 16; o; o >>= 1) {
            a0 += __shfl_xor_sync(0xffffffffu, a0, o);
            a1 += __shfl_xor_sync(0xffffffffu, a1, o);
            b0 += __shfl_xor_sync(0xffffffffu, b0, o);
            b1 += __shfl_xor_sync(0xffffffffu, b1, o);
        }
        if (lane == 0) {
            h2[s][0] = a0; h2[s][1] = a1;
            f1s[s] = a0 * outA[0] + a1 * outA[1];
            f2s[s] = a0 * outA[2] + a1 * outA[3];
            o1[s][0] = ftanh(b0 + blb[0]);
            o1[s][1] = ftanh(b1 + blb[1]);
        }
    }
    __syncthreads();

    const int off = (out_size > 200) ? (out_size - 200) : 0;
    float lsum = 0.f;
    for (int s = tid; s < NS; s += 128) {
        float m = -3.4e38f;
        for (int t = 0; t < NS; t++) {
            float v = f1s[s] + f2s[t];
            v = (v >= 0.f) ? v : 0.2f * v;
            v = (adj_s[s * NS + t] > 0.f) ? v : -9e15f;
            m = fmaxf(m, v);
        }
        float su = 0.f, a0 = 0.f, a1 = 0.f;
        for (int t = 0; t < NS; t++) {
            float v = f1s[s] + f2s[t];
            v = (v >= 0.f) ? v : 0.2f * v;
            v = (adj_s[s * NS + t] > 0.f) ? v : -9e15f;
            const float e = fexp(v - m);
            su += e;
            a0 = fmaf(e, h2[t][0], a0);
            a1 = fmaf(e, h2[t][1], a1);
        }
        a0 /= su; a1 /= su;
        a0 = felu(a0);
        a1 = felu(a1);
        const float z0 = a0 + o1[s][0];
        const float z1 = a1 + o1[s][1];
        const float zm = fmaxf(z0, z1);
        const float e0 = fexp(z0 - zm), e1 = fexp(z1 - zm);
        const float p0 = e0 / (e0 + e1), p1 = e1 / (e0 + e1);
        if (out_size >= 200) { out[off + 2 * s] = p0; out[off + 2 * s + 1] = p1; }
        const float pm  = fmaxf(p0, p1);
        const float lse = pm + logf(fexp(p0 - pm) + fexp(p1 - pm));
        const float chosen = (label[s] == 0) ? p0 : p1;
        lsum += (lse - chosen);
    }
    red[tid] = lsum;
    __syncthreads();
    for (int st2 = 64; st2; st2 >>= 1) {
        if (tid < st2) red[tid] += red[tid + st2];
        __syncthreads();
    }
    if (tid == 0 && (out_size == 1 || out_size > 200)) out[0] = red[0] * (1.f / NS);
}

// ============================================================================
extern "C" void kernel_launch(void* const* d_in, const int* in_sizes, int n_in,
                              void* d_out, int out_size)
{
    (void)in_sizes;
    const float* text  = (const float*)d_in[0];
    const float* price = (const float*)d_in[1];
    const int*   label = (const int*)d_in[2];
    const float* adj   = (const float*)d_in[3];
    const int wb = n_in - 23;
    const float* pg_Wih = (const float*)d_in[wb + 0];
    const float* pg_Whh = (const float*)d_in[wb + 1];
    const float* pg_bih = (const float*)d_in[wb + 2];
    const float* pg_bhh = (const float*)d_in[wb + 3];
    const float* pa_W   = (const float*)d_in[wb + 4];
    const float* tg_Wih = (const float*)d_in[wb + 5];
    const float* tg_Whh = (const float*)d_in[wb + 6];
    const float* tg_bih = (const float*)d_in[wb + 7];
    const float* tg_bhh = (const float*)d_in[wb + 8];
    const float* ta_W   = (const float*)d_in[wb + 9];
    const float* sg_Wih = (const float*)d_in[wb + 10];
    const float* sg_Whh = (const float*)d_in[wb + 11];
    const float* sg_bih = (const float*)d_in[wb + 12];
    const float* sg_bhh = (const float*)d_in[wb + 13];
    const float* sa_W   = (const float*)d_in[wb + 14];
    const float* bil_B  = (const float*)d_in[wb + 15];
    const float* bil_b  = (const float*)d_in[wb + 16];
    const float* bl_W   = (const float*)d_in[wb + 17];
    const float* bl_b   = (const float*)d_in[wb + 18];
    const float* gat_W  = (const float*)d_in[wb + 19];
    const float* gat_a  = (const float*)d_in[wb + 20];
    const float* out_W  = (const float*)d_in[wb + 21];
    const float* out_a  = (const float*)d_in[wb + 22];

    const int smem_gru64 = (WHS_ELEMS + ND * GG + ND * HH + HH * HH + ND * HH + HH + GG + 32) * 4;
    const int smem_gru3  = (WHS_ELEMS + ND * GG + ND * HH + HH * HH + ND * FP + HH + GG + 32) * 4;

    static bool smem_set = false;
    if (!smem_set) {
        cudaFuncSetAttribute(k_text_gemm_bf16,
                             cudaFuncAttributeMaxDynamicSharedMemorySize, GEMM_SMEM_BYTES);
        cudaFuncSetAttribute(k_text_rec,
                             cudaFuncAttributeMaxDynamicSharedMemorySize, TEXT_REC_SMEM);
        cudaFuncSetAttribute((const void*)k_gru_pool<HH, ND, 1>,
                             cudaFuncAttributeMaxDynamicSharedMemorySize, smem_gru64);
        cudaFuncSetAttribute((const void*)k_gru_pool<FP, ND, 0>,
                             cudaFuncAttributeMaxDynamicSharedMemorySize, smem_gru3);
        smem_set = true;
    }

    // 1) bf16 tensor-core batched GEMM: text GRU input projections
    k_text_gemm_bf16<<<dim3(5, NS), 256, GEMM_SMEM_BYTES>>>(text, tg_Wih, tg_bih);
    // price path (independent)
    k_gru_pool<FP, ND, 0><<<NS, 192, smem_gru3>>>(price, pg_Wih, pg_Whh, pg_bih, pg_bhh, pa_W);
    // 2) 2000 text GRU recurrences + attention pooling -> g_news
    k_text_rec<<<NS * ND, 192, TEXT_REC_SMEM>>>(tg_Whh, tg_bhh, ta_W);
    // 3) day-sequence GRU over g_news + pool -> g_tvec
    k_gru_pool<HH, ND, 1><<<NS, 192, smem_gru64>>>(nullptr, sg_Wih, sg_Whh, sg_bih, sg_bhh, sa_W);
    // 4) bilinear fusion -> g_feat
    k_bilinear<<<dim3(HH, NS), 128>>>(bil_B, bil_b);
    // 5) GAT heads
    k_gat_proj<<<dim3(NS, NHD), 64>>>(gat_W, gat_a);
    k_gat_attn<<<dim3(NS, NHD), 128>>>(adj);
    // 6) output GAT layer + blend + softmax + loss
    k_final<<<1, 128>>>(bl_W, bl_b, out_W, out_a, adj, label, (float*)d_out, out_size);
}

// round 6
// speedup vs baseline: 2.0109x; 1.0264x over previous
#include <cuda_runtime.h>
#include <cuda_bf16.h>
#include <math.h>

#define NS 100     // stocks
#define ND 20      // days
#define NT 30      // texts per day
#define HH 64      // hidden
#define GG 192     // 3*H
#define NHD 8      // GAT heads
#define FT 512     // text feature
#define FP 3       // price feature
#define MROWS 600  // ND*NT

#define WHS_PAD 65
#define WHS_ELEMS (GG * WHS_PAD)   // 12480 floats

// ---------------- scratch (device globals; no runtime allocation) ----------------
__device__ float g_gi[(size_t)NS * MROWS * GG];   // text GRU input projections
__device__ float g_outs[(size_t)NS * ND * NT * HH]; // text GRU hidden states (all steps)
__device__ float g_news[NS * ND * HH];
__device__ float g_pvec[NS * HH];
__device__ float g_tvec[NS * HH];
__device__ float g_feat[NS * HH];
__device__ float g_hgat[NHD * NS * HH];
__device__ float g_f1[NHD * NS];
__device__ float g_f2[NHD * NS];
__device__ float g_x2[NS * NHD * HH];

#define LOG2E 1.4426950408889634f

__device__ __forceinline__ float fexp2(float x) { float r; asm("ex2.approx.f32 %0,%1;" : "=f"(r) : "f"(x)); return r; }
__device__ __forceinline__ float frcp(float x)  { float r; asm("rcp.approx.f32 %0,%1;" : "=f"(r) : "f"(x)); return r; }
__device__ __forceinline__ float fsig(float x)  { return frcp(1.f + fexp2(-LOG2E * x)); }
__device__ __forceinline__ float ftanh(float x) { return 1.f - 2.f * frcp(1.f + fexp2(2.f * LOG2E * x)); }
__device__ __forceinline__ float fexp(float x)  { return fexp2(LOG2E * x); }
__device__ __forceinline__ float felu(float x)  { return (x > 0.f) ? x : (fexp(x) - 1.f); }

// packed fp32x2 FMA (FFMA2) — 2x fp32 FMA throughput, PTX-only
#define FMA2(c, a, b) asm("fma.rn.f32x2 %0, %1, %2, %0;" : "+l"(c) : "l"(a), "l"(b))
#define PACK2(d, x)   asm("mov.b64 %0, {%1, %1};" : "=l"(d) : "f"(x))
#define UNPACK2(lo, hi, v) asm("mov.b64 {%0, %1}, %2;" : "=f"(lo), "=f"(hi) : "l"(v))

__device__ __forceinline__ unsigned smem_u32(const void* p) {
    return (unsigned)__cvta_generic_to_shared(p);
}

// coalesced stage of a [192,64] fp32 matrix into padded smem [192][65]
__device__ __forceinline__ void stage_w(const float* __restrict__ src, float* whs, int tid, int nthr)
{
    const float4* s4 = (const float4*)src;
    for (int idx = tid; idx < (GG * HH) / 4; idx += nthr) {
        const float4 v = s4[idx];
        const int base = idx * 4;
        const int row = base >> 6;
        const int col = base & 63;
        float* d = whs + row * WHS_PAD + col;
        d[0] = v.x; d[1] = v.y; d[2] = v.z; d[3] = v.w;
    }
}

#define LDSM4(r0, r1, r2, r3, addr) \
    asm volatile("ldmatrix.sync.aligned.m8n8.x4.shared.b16 {%0,%1,%2,%3},[%4];" \
                 : "=r"(r0), "=r"(r1), "=r"(r2), "=r"(r3) : "r"(addr))

#define MMA16816(c, a, b0, b1) \
    asm volatile("mma.sync.aligned.m16n8k16.row.col.f32.bf16.bf16.f32 " \
                 "{%0,%1,%2,%3},{%4,%5,%6,%7},{%8,%9},{%0,%1,%2,%3};" \
                 : "+f"((c)[0]), "+f"((c)[1]), "+f"((c)[2]), "+f"((c)[3]) \
                 : "r"((a)[0]), "r"((a)[1]), "r"((a)[2]), "r"((a)[3]), "r"(b0), "r"(b1))

// ============================================================================
// Kernel 1: bf16 tensor-core batched GEMM with inline fp32->bf16 conversion
// ============================================================================
#define SA_STRIDE 72
#define SA_SIZE (128 * SA_STRIDE)
#define SB_SIZE (192 * SA_STRIDE)
#define STAGE_ELEMS (SA_SIZE + SB_SIZE)
#define GEMM_SMEM_BYTES (STAGE_ELEMS * 2 * 2)

__global__ __launch_bounds__(256) void k_text_gemm_bf16(
    const float* __restrict__ A, const float* __restrict__ W,
    const float* __restrict__ bih)
{
    extern __shared__ __nv_bfloat16 sm[];
    const int s  = blockIdx.y;
    const int m0 = blockIdx.x * 128;

    const float* Ab = A + (size_t)s * MROWS * FT;
    const float* Wb = W + (size_t)s * GG * FT;

    const int tid  = threadIdx.x;
    const int lane = tid & 31;
    const int warp = tid >> 5;
    const int wm   = (warp >> 1) * 32;
    const int wn   = (warp & 1) * 96;

    const int lrow = tid >> 3;
    const int lk   = (tid & 7) * 8;

    float acc[2][12][4];
#pragma unroll
    for (int i = 0; i < 2; i++)
#pragma unroll
        for (int f = 0; f < 12; f++)
#pragma unroll
            for (int v = 0; v < 4; v++) acc[i][f][v] = 0.f;

    auto load_pass = [&](int p, int k0, int stage) {
        const int gk = k0 + lk;
        float4 v0, v1;
        __nv_bfloat16* dst;
        if (p < 4) {
            const int r = lrow + 32 * p;
            const int m = m0 + r;
            if (m < MROWS) {
                v0 = *(const float4*)(Ab + (size_t)m * FT + gk);
                v1 = *(const float4*)(Ab + (size_t)m * FT + gk + 4);
            } else {
                v0 = make_float4(0.f, 0.f, 0.f, 0.f);
                v1 = v0;
            }
            dst = sm + stage * STAGE_ELEMS + r * SA_STRIDE + lk;
        } else {
            const int r = lrow + 32 * (p - 4);
            v0 = *(const float4*)(Wb + (size_t)r * FT + gk);
            v1 = *(const float4*)(Wb + (size_t)r * FT + gk + 4);
            dst = sm + stage * STAGE_ELEMS + SA_SIZE + r * SA_STRIDE + lk;
        }
        __nv_bfloat162 p0 = __float22bfloat162_rn(make_float2(v0.x, v0.y));
        __nv_bfloat162 p1 = __float22bfloat162_rn(make_float2(v0.z, v0.w));
        __nv_bfloat162 p2 = __float22bfloat162_rn(make_float2(v1.x, v1.y));
        __nv_bfloat162 p3 = __float22bfloat162_rn(make_float2(v1.z, v1.w));
        uint4 u;
        u.x = *(unsigned*)&p0; u.y = *(unsigned*)&p1;
        u.z = *(unsigned*)&p2; u.w = *(unsigned*)&p3;
        *(uint4*)dst = u;
    };

#pragma unroll
    for (int p = 0; p < 10; p++) load_pass(p, 0, 0);
    __syncthreads();

    const int NKT = FT / 64;
    for (int kt = 0; kt < NKT; kt++) {
        const int cur = kt & 1, nxt = cur ^ 1;
        const __nv_bfloat16* As_ = sm + cur * STAGE_ELEMS;
        const __nv_bfloat16* Bs_ = As_ + SA_SIZE;

#pragma unroll
        for (int j16 = 0; j16 < 4; j16++) {
            if (kt + 1 < NKT) {
                const int k0n = (kt + 1) * 64;
                load_pass(j16, k0n, nxt);
                load_pass(j16 + 4, k0n, nxt);
                if (j16 < 2) load_pass(j16 + 8, k0n, nxt);
            }

            const int kc = j16 * 16;
            unsigned a[2][4];
#pragma unroll
            for (int mi = 0; mi < 2; mi++) {
                const int r = wm + mi * 16 + (lane & 15);
                const int c = kc + ((lane >> 4) * 8);
                unsigned addr = smem_u32(As_ + r * SA_STRIDE + c);
                LDSM4(a[mi][0], a[mi][1], a[mi][2], a[mi][3], addr);
            }
            unsigned b[12][2];
#pragma unroll
            for (int nj = 0; nj < 6; nj++) {
                const int r = wn + nj * 16 + (lane & 7) + (((lane >> 4) & 1) << 3);
                const int c = kc + (((lane >> 3) & 1) << 3);
                unsigned addr = smem_u32(Bs_ + r * SA_STRIDE + c);
                unsigned t0, t1, t2, t3;
                LDSM4(t0, t1, t2, t3, addr);
                b[2 * nj][0] = t0; b[2 * nj][1] = t1;
                b[2 * nj + 1][0] = t2; b[2 * nj + 1][1] = t3;
            }
#pragma unroll
            for (int mi = 0; mi < 2; mi++)
#pragma unroll
                for (int f = 0; f < 12; f++)
                    MMA16816(acc[mi][f], a[mi], b[f][0], b[f][1]);
        }
        __syncthreads();
    }

#pragma unroll
    for (int mi = 0; mi < 2; mi++) {
        const int row0 = m0 + wm + mi * 16 + (lane >> 2);
#pragma unroll
        for (int f = 0; f < 12; f++) {
            const int col = wn + f * 8 + (lane & 3) * 2;
            const float b0 = bih[s * GG + col];
            const float b1 = bih[s * GG + col + 1];
            if (row0 < MROWS) {
                float2 v = make_float2(acc[mi][f][0] + b0, acc[mi][f][1] + b1);
                *(float2*)(g_gi + ((size_t)s * MROWS + row0) * GG + col) = v;
            }
            if (row0 + 8 < MROWS) {
                float2 v = make_float2(acc[mi][f][2] + b0, acc[mi][f][3] + b1);
                *(float2*)(g_gi + ((size_t)s * MROWS + row0 + 8) * GG + col) = v;
            }
        }
    }
}

// ============================================================================
// Attention pool: softmax_t( tanh(outs @ Wa) . h_last ) @ outs
// ============================================================================
template <int STEPS>
__device__ __forceinline__ void pool_store(
    const float* outs, const float* hs, const float* wa_s,
    float* sc, float* __restrict__ dst)
{
    const int tid  = threadIdx.x;
    const int warp = tid >> 5;
    const int lane = tid & 31;
    const int nw   = blockDim.x >> 5;

    for (int t = warp; t < STEPS; t += nw) {
        float part = 0.f;
#pragma unroll
        for (int jj = 0; jj < HH; jj += 32) {
            const int j = jj + lane;
            float a0 = 0.f, a1 = 0.f, a2 = 0.f, a3 = 0.f;
#pragma unroll
            for (int i = 0; i < HH; i += 4) {
                a0 = fmaf(outs[t * HH + i + 0], wa_s[(i + 0) * HH + j], a0);
                a1 = fmaf(outs[t * HH + i + 1], wa_s[(i + 1) * HH + j], a1);
                a2 = fmaf(outs[t * HH + i + 2], wa_s[(i + 2) * HH + j], a2);
                a3 = fmaf(outs[t * HH + i + 3], wa_s[(i + 3) * HH + j], a3);
            }
            part = fmaf(ftanh((a0 + a1) + (a2 + a3)), hs[j], part);
        }
#pragma unroll
        for (int o = 16; o; o >>= 1) part += __shfl_xor_sync(0xffffffffu, part, o);
        if (lane == 0) sc[t] = part;
    }
    __syncthreads();
    if (warp == 0) {
        const float v = (lane < STEPS) ? sc[lane] : -3.4e38f;
        float m = v;
#pragma unroll
        for (int o = 16; o; o >>= 1) m = fmaxf(m, __shfl_xor_sync(0xffffffffu, m, o));
        const float e = (lane < STEPS) ? fexp(v - m) : 0.f;
        float su = e;
#pragma unroll
        for (int o = 16; o; o >>= 1) su += __shfl_xor_sync(0xffffffffu, su, o);
        if (lane < STEPS) sc[lane] = e / su;
    }
    __syncthreads();
    if (tid < HH) {
        float a = 0.f;
#pragma unroll
        for (int t = 0; t < STEPS; t++) a = fmaf(sc[t], outs[t * HH + tid], a);
        dst[tid] = a;
    }
}

// ============================================================================
// Kernel 2a: BATCHED text GRU recurrence — one block per STOCK, 20 days in
// parallel. 192 threads (one per gate row). f32x2 packed FMA over day pairs.
//   dyn smem: whs[192*65] | hs[64][20] | ghs[20][192]
// ============================================================================
#define TRB_SMEM ((WHS_ELEMS + HH * ND + ND * GG) * 4)

__global__ __launch_bounds__(192) void k_text_rec_b(
    const float* __restrict__ Whh, const float* __restrict__ bhh)
{
    extern __shared__ float dyn[];
    float* whs = dyn;                  // [192][65]
    float* hs  = whs + WHS_ELEMS;      // [64][20]  (i-major, day contiguous)
    float* ghs = hs + HH * ND;         // [20][192]

    const int s = blockIdx.x;
    const int g = threadIdx.x;
    const float bh = bhh[s * GG + g];

    stage_w(Whh + (size_t)s * GG * HH, whs, g, 192);
    for (int i = g; i < HH * ND; i += 192) hs[i] = 0.f;
    __syncthreads();

    const float* gib = g_gi + (size_t)s * ND * NT * GG;

    // register prefetch of gi (gate inputs) for the current step
    float cur0[7], cur1[7], cur2[7];
    float pre0[7], pre1[7], pre2[7];
#pragma unroll
    for (int k = 0; k < 7; k++) {
        const int p = g + 192 * k;
        if (p < ND * HH) {
            const int d = p >> 6, j = p & 63;
            const float* gp = gib + ((size_t)d * NT) * GG + j;
            pre0[k] = gp[0]; pre1[k] = gp[64]; pre2[k] = gp[128];
        }
    }

    const float* wrow = whs + g * WHS_PAD;
    unsigned long long bh2;
    PACK2(bh2, bh);

    for (int t = 0; t < NT; t++) {
        // --- gh[g][d] = bh + sum_i Whh[g][i] * h[d][i], all 20 days, packed f32x2
        unsigned long long acc[10];
#pragma unroll
        for (int dd = 0; dd < 10; dd++) acc[dd] = bh2;
#pragma unroll 8
        for (int i = 0; i < HH; i++) {
            const float w = wrow[i];
            unsigned long long w2;
            PACK2(w2, w);
            const ulonglong2* hp = (const ulonglong2*)(hs + i * ND);
            const ulonglong2 h0 = hp[0], h1 = hp[1], h2 = hp[2], h3 = hp[3], h4 = hp[4];
            FMA2(acc[0], w2, h0.x); FMA2(acc[1], w2, h0.y);
            FMA2(acc[2], w2, h1.x); FMA2(acc[3], w2, h1.y);
            FMA2(acc[4], w2, h2.x); FMA2(acc[5], w2, h2.y);
            FMA2(acc[6], w2, h3.x); FMA2(acc[7], w2, h3.y);
            FMA2(acc[8], w2, h4.x); FMA2(acc[9], w2, h4.y);
        }
#pragma unroll
        for (int dd = 0; dd < 10; dd++) {
            float lo, hi;
            UNPACK2(lo, hi, acc[dd]);
            ghs[(2 * dd) * GG + g]     = lo;
            ghs[(2 * dd + 1) * GG + g] = hi;
        }
        __syncthreads();

        // consume current prefetch; kick off next step's gi loads
#pragma unroll
        for (int k = 0; k < 7; k++) { cur0[k] = pre0[k]; cur1[k] = pre1[k]; cur2[k] = pre2[k]; }
        if (t + 1 < NT) {
#pragma unroll
            for (int k = 0; k < 7; k++) {
                const int p = g + 192 * k;
                if (p < ND * HH) {
                    const int d = p >> 6, j = p & 63;
                    const float* gp = gib + ((size_t)d * NT + (t + 1)) * GG + j;
                    pre0[k] = gp[0]; pre1[k] = gp[64]; pre2[k] = gp[128];
                }
            }
        }

        // --- gates: 1280 (d,j) pairs over 192 threads
#pragma unroll
        for (int k = 0; k < 7; k++) {
            const int p = g + 192 * k;
            if (p < ND * HH) {
                const int d = p >> 6, j = p & 63;
                const float r  = fsig(cur0[k] + ghs[d * GG + j]);
                const float z  = fsig(cur1[k] + ghs[d * GG + 64 + j]);
                const float n  = ftanh(cur2[k] + r * ghs[d * GG + 128 + j]);
                const float hp_ = hs[j * ND + d];
                const float hn  = (1.f - z) * n + z * hp_;
                hs[j * ND + d] = hn;
                g_outs[((size_t)(s * ND + d) * NT + t) * HH + j] = hn;
            }
        }
        __syncthreads();
    }
}

// ============================================================================
// Kernel 2b: text attention pooling — one block per (stock, day)
// ============================================================================
__global__ __launch_bounds__(192) void k_text_pool(const float* __restrict__ Wa)
{
    __shared__ float outs_s[NT * HH];
    __shared__ float wa_s[HH * HH];
    __shared__ float sc[32];
    const int sd = blockIdx.x;
    const int s  = sd / ND;
    const int g  = threadIdx.x;

    const float4* src = (const float4*)(g_outs + (size_t)sd * NT * HH);
    for (int i = g; i < (NT * HH) / 4; i += 192) ((float4*)outs_s)[i] = src[i];
    const float4* wsrc = (const float4*)(Wa + (size_t)s * HH * HH);
    for (int i = g; i < (HH * HH) / 4; i += 192) ((float4*)wa_s)[i] = wsrc[i];
    __syncthreads();

    pool_store<NT>(outs_s, outs_s + (NT - 1) * HH, wa_s, sc, g_news + (size_t)sd * HH);
}

// ============================================================================
// Kernel 3: generic per-stock GRU + pool, staged weights
// ============================================================================
template <int IN, int STEPS, int SRC>
__global__ __launch_bounds__(192) void k_gru_pool(
    const float* __restrict__ xin,
    const float* __restrict__ Wih, const float* __restrict__ Whh,
    const float* __restrict__ bih, const float* __restrict__ bhh,
    const float* __restrict__ Wa)
{
    extern __shared__ float dyn[];
    float* whs  = dyn;
    float* gis  = whs + WHS_ELEMS;
    float* outs = gis + STEPS * GG;
    float* wa_s = outs + STEPS * HH;
    float* xs   = wa_s + HH * HH;
    float* hs   = xs + STEPS * IN;
    float* ghs  = hs + HH;
    float* sc   = ghs + GG;

    const int s = blockIdx.x;
    const int g = threadIdx.x;

    const float* xb = (SRC == 1) ? (g_news + (size_t)s * ND * HH)
                                 : (xin + (size_t)s * STEPS * IN);
    const float bh = bhh[s * GG + g];
    const float bi = bih[s * GG + g];

    for (int i = g; i < STEPS * IN; i += 192) xs[i] = xb[i];
    {
        const float4* src = (const float4*)(Wa + (size_t)s * HH * HH);
        for (int i = g; i < (HH * HH) / 4; i += 192) ((float4*)wa_s)[i] = src[i];
    }
    if (g < HH) hs[g] = 0.f;

    if (IN == HH) {
        stage_w(Wih + (size_t)s * GG * IN, whs, g, 192);
        __syncthreads();
        float acct[STEPS];
#pragma unroll
        for (int t = 0; t < STEPS; t++) acct[t] = bi;
#pragma unroll 4
        for (int i = 0; i < IN; i++) {
            const float w = whs[g * WHS_PAD + i];
#pragma unroll
            for (int t = 0; t < STEPS; t++) acct[t] = fmaf(w, xs[t * IN + i], acct[t]);
        }
#pragma unroll
        for (int t = 0; t < STEPS; t++) gis[t * GG + g] = acct[t];
        __syncthreads();
        stage_w(Whh + (size_t)s * GG * HH, whs, g, 192);
        __syncthreads();
    } else {
        float wi[IN];
        const float* wip = Wih + ((size_t)s * GG + g) * IN;
#pragma unroll
        for (int i = 0; i < IN; i++) wi[i] = wip[i];
        stage_w(Whh + (size_t)s * GG * HH, whs, g, 192);
        __syncthreads();
#pragma unroll
        for (int t = 0; t < STEPS; t++) {
            float gi = bi;
#pragma unroll
            for (int i = 0; i < IN; i++) gi = fmaf(wi[i], xs[t * IN + i], gi);
            gis[t * GG + g] = gi;
        }
        __syncthreads();
    }

    float wh[HH];
#pragma unroll
    for (int i = 0; i < HH; i++) wh[i] = whs[g * WHS_PAD + i];

    for (int t = 0; t < STEPS; t++) {
        float a0 = 0.f, a1 = 0.f, a2 = 0.f, a3 = 0.f;
#pragma unroll
        for (int i = 0; i < HH; i += 4) {
            a0 = fmaf(wh[i + 0], hs[i + 0], a0);
            a1 = fmaf(wh[i + 1], hs[i + 1], a1);
            a2 = fmaf(wh[i + 2], hs[i + 2], a2);
            a3 = fmaf(wh[i + 3], hs[i + 3], a3);
        }
        ghs[g] = bh + ((a0 + a1) + (a2 + a3));
        __syncthreads();
        if (g < HH) {
            const float* git = gis + t * GG;
            const float r  = fsig(git[g] + ghs[g]);
            const float z  = fsig(git[HH + g] + ghs[HH + g]);
            const float n  = ftanh(git[2 * HH + g] + r * ghs[2 * HH + g]);
            const float hn = (1.f - z) * n + z * hs[g];
            hs[g] = hn;
            outs[t * HH + g] = hn;
        }
        __syncthreads();
    }
    float* dst = (SRC == 1 ? g_tvec : g_pvec) + s * HH;
    pool_store<STEPS>(outs, hs, wa_s, sc, dst);
}

// ============================================================================
// Kernel 4: bilinear fusion (float4, smem-staged vectors)
// ============================================================================
__global__ __launch_bounds__(128) void k_bilinear(
    const float* __restrict__ B, const float* __restrict__ bb)
{
    const int o = blockIdx.x, s = blockIdx.y;
    const int tid = threadIdx.x;
    __shared__ float tv_s[HH], pv_s[HH];
    if (tid < HH) { tv_s[tid] = g_tvec[s * HH + tid]; pv_s[tid] = g_pvec[s * HH + tid]; }
    __syncthreads();

    const float* Bp = B + ((size_t)s * HH + o) * HH * HH;
    float acc = 0.f;
#pragma unroll
    for (int it = 0; it < 8; it++) {
        const int k4 = (it * 128 + tid) * 4;
        const float4 v = *(const float4*)(Bp + k4);
        const int i = k4 >> 6, j = k4 & 63;
        float p = pv_s[j] * v.x;
        p = fmaf(pv_s[j + 1], v.y, p);
        p = fmaf(pv_s[j + 2], v.z, p);
        p = fmaf(pv_s[j + 3], v.w, p);
        acc = fmaf(tv_s[i], p, acc);
    }
    __shared__ float red[128];
    red[tid] = acc;
    __syncthreads();
    for (int st2 = 64; st2; st2 >>= 1) {
        if (tid < st2) red[tid] += red[tid + st2];
        __syncthreads();
    }
    if (tid == 0) g_feat[s * HH + o] = ftanh(red[0] + bb[s * HH + o]);
}

// ============================================================================
// Kernel 5: GAT head projection
// ============================================================================
__global__ __launch_bounds__(64) void k_gat_proj(
    const float* __restrict__ gatW, const float* __restrict__ gatA)
{
    const int s = blockIdx.x, nh = blockIdx.y;
    const int j = threadIdx.x;
    const float* Wp = gatW + (size_t)nh * HH * HH;
    const float* x  = g_feat + s * HH;
    float acc = 0.f;
#pragma unroll 8
    for (int i = 0; i < HH; i++) acc = fmaf(x[i], Wp[i * HH + j], acc);
    g_hgat[((size_t)nh * NS + s) * HH + j] = acc;

    __shared__ float r1[64], r2[64];
    r1[j] = acc * gatA[nh * 2 * HH + j];
    r2[j] = acc * gatA[nh * 2 * HH + HH + j];
    __syncthreads();
    if (j < 32) {
        float v1 = r1[j] + r1[j + 32];
        float v2 = r2[j] + r2[j + 32];
#pragma unroll
        for (int o = 16; o; o >>= 1) {
            v1 += __shfl_xor_sync(0xffffffffu, v1, o);
            v2 += __shfl_xor_sync(0xffffffffu, v2, o);
        }
        if (j == 0) { g_f1[nh * NS + s] = v1; g_f2[nh * NS + s] = v2; }
    }
}

// ============================================================================
// Kernel 6: GAT masked attention + elu (warp-parallel softmax)
// ============================================================================
__global__ __launch_bounds__(128) void k_gat_attn(const float* __restrict__ adj)
{
    const int s = blockIdx.x, nh = blockIdx.y;
    const int tid = threadIdx.x;
    __shared__ float att[NS];
    __shared__ float sinv;
    const float f1v = g_f1[nh * NS + s];
    if (tid < NS) {
        float v = f1v + g_f2[nh * NS + tid];
        v = (v >= 0.f) ? v : 0.2f * v;
        att[tid] = (adj[s * NS + tid] > 0.f) ? v : -9e15f;
    }
    __syncthreads();
    if (tid < 32) {
        float m = -3.4e38f;
        for (int t = tid; t < NS; t += 32) m = fmaxf(m, att[t]);
#pragma unroll
        for (int o = 16; o; o >>= 1) m = fmaxf(m, __shfl_xor_sync(0xffffffffu, m, o));
        float su = 0.f;
        for (int t = tid; t < NS; t += 32) {
            const float e = fexp(att[t] - m);
            att[t] = e;
            su += e;
        }
#pragma unroll
        for (int o = 16; o; o >>= 1) su += __shfl_xor_sync(0xffffffffu, su, o);
        if (tid == 0) sinv = 1.f / su;
    }
    __syncthreads();
    if (tid < HH) {
        float acc = 0.f;
        for (int t = 0; t < NS; t++)
            acc = fmaf(att[t], g_hgat[((size_t)nh * NS + t) * HH + tid], acc);
        acc = felu(acc * sinv);
        g_x2[(size_t)s * (NHD * HH) + nh * HH + tid] = acc;
    }
}

// ============================================================================
// Kernel 7: final — out-layer GAT, blend, double softmax, loss. One block.
// ============================================================================
__global__ __launch_bounds__(128) void k_final(
    const float* __restrict__ blW, const float* __restrict__ blb,
    const float* __restrict__ outW, const float* __restrict__ outA,
    const float* __restrict__ adj, const int* __restrict__ label,
    float* __restrict__ out, int out_size)
{
    __shared__ float h2[NS][2];
    __shared__ float f1s[NS], f2s[NS];
    __shared__ float o1[NS][2];
    __shared__ float adj_s[NS * NS];
    __shared__ float red[128];
    const int tid  = threadIdx.x;
    const int warp = tid >> 5;
    const int lane = tid & 31;

    for (int i = tid; i < NS * NS; i += 128) adj_s[i] = adj[i];

    for (int s = warp; s < NS; s += 4) {
        const float* xr = g_x2 + (size_t)s * NHD * HH;
        float a0 = 0.f, a1 = 0.f;
        for (int k = lane; k < NHD * HH; k += 32) {
            const float xv = xr[k];
            a0 = fmaf(xv, outW[2 * k + 0], a0);
            a1 = fmaf(xv, outW[2 * k + 1], a1);
        }
        const float* fr = g_feat + s * HH;
        float b0 = 0.f, b1 = 0.f;
        for (int k = lane; k < HH; k += 32) {
            const float fv = fr[k];
            b0 = fmaf(fv, blW[2 * k + 0], b0);
            b1 = fmaf(fv, blW[2 * k + 1], b1);
        }
#pragma unroll
        for (int o = 16; o; o >>= 1) {
            a0 += __shfl_xor_sync(0xffffffffu, a0, o);
            a1 += __shfl_xor_sync(0xffffffffu, a1, o);
            b0 += __shfl_xor_sync(0xffffffffu, b0, o);
            b1 += __shfl_xor_sync(0xffffffffu, b1, o);
        }
        if (lane == 0) {
            h2[s][0] = a0; h2[s][1] = a1;
            f1s[s] = a0 * outA[0] + a1 * outA[1];
            f2s[s] = a0 * outA[2] + a1 * outA[3];
            o1[s][0] = ftanh(b0 + blb[0]);
            o1[s][1] = ftanh(b1 + blb[1]);
        }
    }
    __syncthreads();

    const int off = (out_size > 200) ? (out_size - 200) : 0;
    float lsum = 0.f;
    for (int s = tid; s < NS; s += 128) {
        float m = -3.4e38f;
        for (int t = 0; t < NS; t++) {
            float v = f1s[s] + f2s[t];
            v = (v >= 0.f) ? v : 0.2f * v;
            v = (adj_s[s * NS + t] > 0.f) ? v : -9e15f;
            m = fmaxf(m, v);
        }
        float su = 0.f, a0 = 0.f, a1 = 0.f;
        for (int t = 0; t < NS; t++) {
            float v = f1s[s] + f2s[t];
            v = (v >= 0.f) ? v : 0.2f * v;
            v = (adj_s[s * NS + t] > 0.f) ? v : -9e15f;
            const float e = fexp(v - m);
            su += e;
            a0 = fmaf(e, h2[t][0], a0);
            a1 = fmaf(e, h2[t][1], a1);
        }
        a0 /= su; a1 /= su;
        a0 = felu(a0);
        a1 = felu(a1);
        const float z0 = a0 + o1[s][0];
        const float z1 = a1 + o1[s][1];
        const float zm = fmaxf(z0, z1);
        const float e0 = fexp(z0 - zm), e1 = fexp(z1 - zm);
        const float p0 = e0 / (e0 + e1), p1 = e1 / (e0 + e1);
        if (out_size >= 200) { out[off + 2 * s] = p0; out[off + 2 * s + 1] = p1; }
        const float pm  = fmaxf(p0, p1);
        const float lse = pm + logf(fexp(p0 - pm) + fexp(p1 - pm));
        const float chosen = (label[s] == 0) ? p0 : p1;
        lsum += (lse - chosen);
    }
    red[tid] = lsum;
    __syncthreads();
    for (int st2 = 64; st2; st2 >>= 1) {
        if (tid < st2) red[tid] += red[tid + st2];
        __syncthreads();
    }
    if (tid == 0 && (out_size == 1 || out_size > 200)) out[0] = red[0] * (1.f / NS);
}

// ============================================================================
extern "C" void kernel_launch(void* const* d_in, const int* in_sizes, int n_in,
                              void* d_out, int out_size)
{
    (void)in_sizes;
    const float* text  = (const float*)d_in[0];
    const float* price = (const float*)d_in[1];
    const int*   label = (const int*)d_in[2];
    const float* adj   = (const float*)d_in[3];
    const int wb = n_in - 23;
    const float* pg_Wih = (const float*)d_in[wb + 0];
    const float* pg_Whh = (const float*)d_in[wb + 1];
    const float* pg_bih = (const float*)d_in[wb + 2];
    const float* pg_bhh = (const float*)d_in[wb + 3];
    const float* pa_W   = (const float*)d_in[wb + 4];
    const float* tg_Wih = (const float*)d_in[wb + 5];
    const float* tg_Whh = (const float*)d_in[wb + 6];
    const float* tg_bih = (const float*)d_in[wb + 7];
    const float* tg_bhh = (const float*)d_in[wb + 8];
    const float* ta_W   = (const float*)d_in[wb + 9];
    const float* sg_Wih = (const float*)d_in[wb + 10];
    const float* sg_Whh = (const float*)d_in[wb + 11];
    const float* sg_bih = (const float*)d_in[wb + 12];
    const float* sg_bhh = (const float*)d_in[wb + 13];
    const float* sa_W   = (const float*)d_in[wb + 14];
    const float* bil_B  = (const float*)d_in[wb + 15];
    const float* bil_b  = (const float*)d_in[wb + 16];
    const float* bl_W   = (const float*)d_in[wb + 17];
    const float* bl_b   = (const float*)d_in[wb + 18];
    const float* gat_W  = (const float*)d_in[wb + 19];
    const float* gat_a  = (const float*)d_in[wb + 20];
    const float* out_W  = (const float*)d_in[wb + 21];
    const float* out_a  = (const float*)d_in[wb + 22];

    const int smem_gru64 = (WHS_ELEMS + ND * GG + ND * HH + HH * HH + ND * HH + HH + GG + 32) * 4;
    const int smem_gru3  = (WHS_ELEMS + ND * GG + ND * HH + HH * HH + ND * FP + HH + GG + 32) * 4;

    static bool smem_set = false;
    if (!smem_set) {
        cudaFuncSetAttribute(k_text_gemm_bf16,
                             cudaFuncAttributeMaxDynamicSharedMemorySize, GEMM_SMEM_BYTES);
        cudaFuncSetAttribute(k_text_rec_b,
                             cudaFuncAttributeMaxDynamicSharedMemorySize, TRB_SMEM);
        cudaFuncSetAttribute((const void*)k_gru_pool<HH, ND, 1>,
                             cudaFuncAttributeMaxDynamicSharedMemorySize, smem_gru64);
        cudaFuncSetAttribute((const void*)k_gru_pool<FP, ND, 0>,
                             cudaFuncAttributeMaxDynamicSharedMemorySize, smem_gru3);
        smem_set = true;
    }

    // 1) bf16 tensor-core batched GEMM: text GRU input projections
    k_text_gemm_bf16<<<dim3(5, NS), 256, GEMM_SMEM_BYTES>>>(text, tg_Wih, tg_bih);
    // price path (independent)
    k_gru_pool<FP, ND, 0><<<NS, 192, smem_gru3>>>(price, pg_Wih, pg_Whh, pg_bih, pg_bhh, pa_W);
    // 2a) batched text GRU recurrences (20 days/block) -> g_outs
    k_text_rec_b<<<NS, 192, TRB_SMEM>>>(tg_Whh, tg_bhh);
    // 2b) text attention pooling -> g_news
    k_text_pool<<<NS * ND, 192>>>(ta_W);
    // 3) day-sequence GRU over g_news + pool -> g_tvec
    k_gru_pool<HH, ND, 1><<<NS, 192, smem_gru64>>>(nullptr, sg_Wih, sg_Whh, sg_bih, sg_bhh, sa_W);
    // 4) bilinear fusion -> g_feat
    k_bilinear<<<dim3(HH, NS), 128>>>(bil_B, bil_b);
    // 5) GAT heads
    k_gat_proj<<<dim3(NS, NHD), 64>>>(gat_W, gat_a);
    k_gat_attn<<<dim3(NS, NHD), 128>>>(adj);
    // 6) output GAT layer + blend + softmax + loss
    k_final<<<1, 128>>>(bl_W, bl_b, out_W, out_a, adj, label, (float*)d_out, out_size);
}

// round 7
// speedup vs baseline: 2.0656x; 1.0272x over previous
#include <cuda_runtime.h>
#include <cuda_bf16.h>
#include <math.h>

#define NS 100     // stocks
#define ND 20      // days
#define NT 30      // texts per day
#define HH 64      // hidden
#define GG 192     // 3*H
#define NHD 8      // GAT heads
#define FT 512     // text feature
#define FP 3       // price feature
#define MROWS 600  // ND*NT

#define WHS_PAD 65
#define WHS_ELEMS (GG * WHS_PAD)   // 12480 floats

// ---------------- scratch (device globals; no runtime allocation) ----------------
__device__ __nv_bfloat16 g_gi_bf[(size_t)NS * MROWS * GG];  // text GRU input projections (bf16)
__device__ float g_outs[(size_t)NS * ND * NT * HH];         // text GRU hidden states
__device__ float g_news[NS * ND * HH];
__device__ float g_pvec[NS * HH];
__device__ float g_tvec[NS * HH];
__device__ float g_feat[NS * HH];
__device__ float g_hgat[NHD * NS * HH];
__device__ float g_f1[NHD * NS];
__device__ float g_f2[NHD * NS];
__device__ float g_x2[NS * NHD * HH];

#define LOG2E 1.4426950408889634f

__device__ __forceinline__ float fexp2(float x) { float r; asm("ex2.approx.f32 %0,%1;" : "=f"(r) : "f"(x)); return r; }
__device__ __forceinline__ float frcp(float x)  { float r; asm("rcp.approx.f32 %0,%1;" : "=f"(r) : "f"(x)); return r; }
__device__ __forceinline__ float fsig(float x)  { return frcp(1.f + fexp2(-LOG2E * x)); }
__device__ __forceinline__ float ftanh(float x) { return 1.f - 2.f * frcp(1.f + fexp2(2.f * LOG2E * x)); }
__device__ __forceinline__ float fexp(float x)  { return fexp2(LOG2E * x); }
__device__ __forceinline__ float felu(float x)  { return (x > 0.f) ? x : (fexp(x) - 1.f); }

// packed fp32x2 FMA (FFMA2) — 2x fp32 FMA throughput, PTX-only
#define FMA2(c, a, b) asm("fma.rn.f32x2 %0, %1, %2, %0;" : "+l"(c) : "l"(a), "l"(b))
#define PACK2(d, x)   asm("mov.b64 %0, {%1, %1};" : "=l"(d) : "f"(x))
#define UNPACK2(lo, hi, v) asm("mov.b64 {%0, %1}, %2;" : "=f"(lo), "=f"(hi) : "l"(v))

__device__ __forceinline__ unsigned smem_u32(const void* p) {
    return (unsigned)__cvta_generic_to_shared(p);
}

// coalesced stage of a [192,64] fp32 matrix into padded smem [192][65]
__device__ __forceinline__ void stage_w(const float* __restrict__ src, float* whs, int tid, int nthr)
{
    const float4* s4 = (const float4*)src;
    for (int idx = tid; idx < (GG * HH) / 4; idx += nthr) {
        const float4 v = s4[idx];
        const int base = idx * 4;
        const int row = base >> 6;
        const int col = base & 63;
        float* d = whs + row * WHS_PAD + col;
        d[0] = v.x; d[1] = v.y; d[2] = v.z; d[3] = v.w;
    }
}

#define LDSM4(r0, r1, r2, r3, addr) \
    asm volatile("ldmatrix.sync.aligned.m8n8.x4.shared.b16 {%0,%1,%2,%3},[%4];" \
                 : "=r"(r0), "=r"(r1), "=r"(r2), "=r"(r3) : "r"(addr))

#define MMA16816(c, a, b0, b1) \
    asm volatile("mma.sync.aligned.m16n8k16.row.col.f32.bf16.bf16.f32 " \
                 "{%0,%1,%2,%3},{%4,%5,%6,%7},{%8,%9},{%0,%1,%2,%3};" \
                 : "+f"((c)[0]), "+f"((c)[1]), "+f"((c)[2]), "+f"((c)[3]) \
                 : "r"((a)[0]), "r"((a)[1]), "r"((a)[2]), "r"((a)[3]), "r"(b0), "r"(b1))

// ============================================================================
// Kernel 1: bf16 tensor-core batched GEMM; writes g_gi in bf16
// ============================================================================
#define SA_STRIDE 72
#define SA_SIZE (128 * SA_STRIDE)
#define SB_SIZE (192 * SA_STRIDE)
#define STAGE_ELEMS (SA_SIZE + SB_SIZE)
#define GEMM_SMEM_BYTES (STAGE_ELEMS * 2 * 2)

__global__ __launch_bounds__(256) void k_text_gemm_bf16(
    const float* __restrict__ A, const float* __restrict__ W,
    const float* __restrict__ bih)
{
    extern __shared__ __nv_bfloat16 sm[];
    const int s  = blockIdx.y;
    const int m0 = blockIdx.x * 128;

    const float* Ab = A + (size_t)s * MROWS * FT;
    const float* Wb = W + (size_t)s * GG * FT;

    const int tid  = threadIdx.x;
    const int lane = tid & 31;
    const int warp = tid >> 5;
    const int wm   = (warp >> 1) * 32;
    const int wn   = (warp & 1) * 96;

    const int lrow = tid >> 3;
    const int lk   = (tid & 7) * 8;

    float acc[2][12][4];
#pragma unroll
    for (int i = 0; i < 2; i++)
#pragma unroll
        for (int f = 0; f < 12; f++)
#pragma unroll
            for (int v = 0; v < 4; v++) acc[i][f][v] = 0.f;

    auto load_pass = [&](int p, int k0, int stage) {
        const int gk = k0 + lk;
        float4 v0, v1;
        __nv_bfloat16* dst;
        if (p < 4) {
            const int r = lrow + 32 * p;
            const int m = m0 + r;
            if (m < MROWS) {
                v0 = *(const float4*)(Ab + (size_t)m * FT + gk);
                v1 = *(const float4*)(Ab + (size_t)m * FT + gk + 4);
            } else {
                v0 = make_float4(0.f, 0.f, 0.f, 0.f);
                v1 = v0;
            }
            dst = sm + stage * STAGE_ELEMS + r * SA_STRIDE + lk;
        } else {
            const int r = lrow + 32 * (p - 4);
            v0 = *(const float4*)(Wb + (size_t)r * FT + gk);
            v1 = *(const float4*)(Wb + (size_t)r * FT + gk + 4);
            dst = sm + stage * STAGE_ELEMS + SA_SIZE + r * SA_STRIDE + lk;
        }
        __nv_bfloat162 p0 = __float22bfloat162_rn(make_float2(v0.x, v0.y));
        __nv_bfloat162 p1 = __float22bfloat162_rn(make_float2(v0.z, v0.w));
        __nv_bfloat162 p2 = __float22bfloat162_rn(make_float2(v1.x, v1.y));
        __nv_bfloat162 p3 = __float22bfloat162_rn(make_float2(v1.z, v1.w));
        uint4 u;
        u.x = *(unsigned*)&p0; u.y = *(unsigned*)&p1;
        u.z = *(unsigned*)&p2; u.w = *(unsigned*)&p3;
        *(uint4*)dst = u;
    };

#pragma unroll
    for (int p = 0; p < 10; p++) load_pass(p, 0, 0);
    __syncthreads();

    const int NKT = FT / 64;
    for (int kt = 0; kt < NKT; kt++) {
        const int cur = kt & 1, nxt = cur ^ 1;
        const __nv_bfloat16* As_ = sm + cur * STAGE_ELEMS;
        const __nv_bfloat16* Bs_ = As_ + SA_SIZE;

#pragma unroll
        for (int j16 = 0; j16 < 4; j16++) {
            if (kt + 1 < NKT) {
                const int k0n = (kt + 1) * 64;
                load_pass(j16, k0n, nxt);
                load_pass(j16 + 4, k0n, nxt);
                if (j16 < 2) load_pass(j16 + 8, k0n, nxt);
            }

            const int kc = j16 * 16;
            unsigned a[2][4];
#pragma unroll
            for (int mi = 0; mi < 2; mi++) {
                const int r = wm + mi * 16 + (lane & 15);
                const int c = kc + ((lane >> 4) * 8);
                unsigned addr = smem_u32(As_ + r * SA_STRIDE + c);
                LDSM4(a[mi][0], a[mi][1], a[mi][2], a[mi][3], addr);
            }
            unsigned b[12][2];
#pragma unroll
            for (int nj = 0; nj < 6; nj++) {
                const int r = wn + nj * 16 + (lane & 7) + (((lane >> 4) & 1) << 3);
                const int c = kc + (((lane >> 3) & 1) << 3);
                unsigned addr = smem_u32(Bs_ + r * SA_STRIDE + c);
                unsigned t0, t1, t2, t3;
                LDSM4(t0, t1, t2, t3, addr);
                b[2 * nj][0] = t0; b[2 * nj][1] = t1;
                b[2 * nj + 1][0] = t2; b[2 * nj + 1][1] = t3;
            }
#pragma unroll
            for (int mi = 0; mi < 2; mi++)
#pragma unroll
                for (int f = 0; f < 12; f++)
                    MMA16816(acc[mi][f], a[mi], b[f][0], b[f][1]);
        }
        __syncthreads();
    }

    // epilogue: bias + bf16 store
#pragma unroll
    for (int mi = 0; mi < 2; mi++) {
        const int row0 = m0 + wm + mi * 16 + (lane >> 2);
#pragma unroll
        for (int f = 0; f < 12; f++) {
            const int col = wn + f * 8 + (lane & 3) * 2;
            const float b0 = bih[s * GG + col];
            const float b1 = bih[s * GG + col + 1];
            if (row0 < MROWS) {
                __nv_bfloat162 v = __float22bfloat162_rn(
                    make_float2(acc[mi][f][0] + b0, acc[mi][f][1] + b1));
                *(__nv_bfloat162*)(g_gi_bf + ((size_t)s * MROWS + row0) * GG + col) = v;
            }
            if (row0 + 8 < MROWS) {
                __nv_bfloat162 v = __float22bfloat162_rn(
                    make_float2(acc[mi][f][2] + b0, acc[mi][f][3] + b1));
                *(__nv_bfloat162*)(g_gi_bf + ((size_t)s * MROWS + row0 + 8) * GG + col) = v;
            }
        }
    }
}

// ============================================================================
// Attention pool: softmax_t( tanh(outs @ Wa) . h_last ) @ outs
//   Wa-register-reuse version: each warp keeps acc[t][2] in registers and
//   reads each Wa element ONCE (reused across its ~STEPS/6 steps).
//   Requires blockDim == 192 (6 warps).
// ============================================================================
template <int STEPS>
__device__ __forceinline__ void pool_store(
    const float* outs, const float* hs, const float* wa_s,
    float* sc, float* __restrict__ dst)
{
    const int tid  = threadIdx.x;
    const int warp = tid >> 5;
    const int lane = tid & 31;
    constexpr int TL = (STEPS + 5) / 6;

    float acc[TL][2];
#pragma unroll
    for (int tl = 0; tl < TL; tl++) { acc[tl][0] = 0.f; acc[tl][1] = 0.f; }

#pragma unroll 8
    for (int i = 0; i < HH; i++) {
        const float w0 = wa_s[i * HH + lane];
        const float w1 = wa_s[i * HH + 32 + lane];
#pragma unroll
        for (int tl = 0; tl < TL; tl++) {
            const int t = warp + 6 * tl;
            if (t < STEPS) {
                const float o = outs[t * HH + i];
                acc[tl][0] = fmaf(o, w0, acc[tl][0]);
                acc[tl][1] = fmaf(o, w1, acc[tl][1]);
            }
        }
    }
#pragma unroll
    for (int tl = 0; tl < TL; tl++) {
        const int t = warp + 6 * tl;
        if (t < STEPS) {
            float p = fmaf(ftanh(acc[tl][0]), hs[lane],
                           ftanh(acc[tl][1]) * hs[lane + 32]);
#pragma unroll
            for (int o = 16; o; o >>= 1) p += __shfl_xor_sync(0xffffffffu, p, o);
            if (lane == 0) sc[t] = p;
        }
    }
    __syncthreads();
    if (warp == 0) {
        const float v = (lane < STEPS) ? sc[lane] : -3.4e38f;
        float m = v;
#pragma unroll
        for (int o = 16; o; o >>= 1) m = fmaxf(m, __shfl_xor_sync(0xffffffffu, m, o));
        const float e = (lane < STEPS) ? fexp(v - m) : 0.f;
        float su = e;
#pragma unroll
        for (int o = 16; o; o >>= 1) su += __shfl_xor_sync(0xffffffffu, su, o);
        if (lane < STEPS) sc[lane] = e / su;
    }
    __syncthreads();
    if (tid < HH) {
        float a = 0.f;
#pragma unroll
        for (int t = 0; t < STEPS; t++) a = fmaf(sc[t], outs[t * HH + tid], a);
        dst[tid] = a;
    }
}

// ============================================================================
// Kernel 2a: BATCHED text GRU recurrence — one block per STOCK, 20 days.
// ============================================================================
#define TRB_SMEM ((WHS_ELEMS + HH * ND + ND * GG) * 4)

__global__ __launch_bounds__(192) void k_text_rec_b(
    const float* __restrict__ Whh, const float* __restrict__ bhh)
{
    extern __shared__ float dyn[];
    float* whs = dyn;                  // [192][65]
    float* hs  = whs + WHS_ELEMS;      // [64][20]
    float* ghs = hs + HH * ND;         // [20][192]

    const int s = blockIdx.x;
    const int g = threadIdx.x;
    const float bh = bhh[s * GG + g];

    stage_w(Whh + (size_t)s * GG * HH, whs, g, 192);
    for (int i = g; i < HH * ND; i += 192) hs[i] = 0.f;
    __syncthreads();

    const __nv_bfloat16* gib = g_gi_bf + (size_t)s * ND * NT * GG;

    float cur0[7], cur1[7], cur2[7];
    float pre0[7], pre1[7], pre2[7];
#pragma unroll
    for (int k = 0; k < 7; k++) {
        const int p = g + 192 * k;
        if (p < ND * HH) {
            const int d = p >> 6, j = p & 63;
            const __nv_bfloat16* gp = gib + ((size_t)d * NT) * GG + j;
            pre0[k] = __bfloat162float(gp[0]);
            pre1[k] = __bfloat162float(gp[64]);
            pre2[k] = __bfloat162float(gp[128]);
        }
    }

    const float* wrow = whs + g * WHS_PAD;
    unsigned long long bh2;
    PACK2(bh2, bh);

    for (int t = 0; t < NT; t++) {
        unsigned long long acc[10];
#pragma unroll
        for (int dd = 0; dd < 10; dd++) acc[dd] = bh2;
#pragma unroll 8
        for (int i = 0; i < HH; i++) {
            const float w = wrow[i];
            unsigned long long w2;
            PACK2(w2, w);
            const ulonglong2* hp = (const ulonglong2*)(hs + i * ND);
            const ulonglong2 h0 = hp[0], h1 = hp[1], h2 = hp[2], h3 = hp[3], h4 = hp[4];
            FMA2(acc[0], w2, h0.x); FMA2(acc[1], w2, h0.y);
            FMA2(acc[2], w2, h1.x); FMA2(acc[3], w2, h1.y);
            FMA2(acc[4], w2, h2.x); FMA2(acc[5], w2, h2.y);
            FMA2(acc[6], w2, h3.x); FMA2(acc[7], w2, h3.y);
            FMA2(acc[8], w2, h4.x); FMA2(acc[9], w2, h4.y);
        }
#pragma unroll
        for (int dd = 0; dd < 10; dd++) {
            float lo, hi;
            UNPACK2(lo, hi, acc[dd]);
            ghs[(2 * dd) * GG + g]     = lo;
            ghs[(2 * dd + 1) * GG + g] = hi;
        }
        __syncthreads();

#pragma unroll
        for (int k = 0; k < 7; k++) { cur0[k] = pre0[k]; cur1[k] = pre1[k]; cur2[k] = pre2[k]; }
        if (t + 1 < NT) {
#pragma unroll
            for (int k = 0; k < 7; k++) {
                const int p = g + 192 * k;
                if (p < ND * HH) {
                    const int d = p >> 6, j = p & 63;
                    const __nv_bfloat16* gp = gib + ((size_t)d * NT + (t + 1)) * GG + j;
                    pre0[k] = __bfloat162float(gp[0]);
                    pre1[k] = __bfloat162float(gp[64]);
                    pre2[k] = __bfloat162float(gp[128]);
                }
            }
        }

#pragma unroll
        for (int k = 0; k < 7; k++) {
            const int p = g + 192 * k;
            if (p < ND * HH) {
                const int d = p >> 6, j = p & 63;
                const float r  = fsig(cur0[k] + ghs[d * GG + j]);
                const float z  = fsig(cur1[k] + ghs[d * GG + 64 + j]);
                const float n  = ftanh(cur2[k] + r * ghs[d * GG + 128 + j]);
                const float hp_ = hs[j * ND + d];
                const float hn  = (1.f - z) * n + z * hp_;
                hs[j * ND + d] = hn;
                g_outs[((size_t)(s * ND + d) * NT + t) * HH + j] = hn;
            }
        }
        __syncthreads();
    }
}

// ============================================================================
// Kernel 2b: text attention pooling — one block per (stock, day)
// ============================================================================
__global__ __launch_bounds__(192) void k_text_pool(const float* __restrict__ Wa)
{
    __shared__ float outs_s[NT * HH];
    __shared__ float wa_s[HH * HH];
    __shared__ float sc[32];
    const int sd = blockIdx.x;
    const int s  = sd / ND;
    const int g  = threadIdx.x;

    const float4* src = (const float4*)(g_outs + (size_t)sd * NT * HH);
    for (int i = g; i < (NT * HH) / 4; i += 192) ((float4*)outs_s)[i] = src[i];
    const float4* wsrc = (const float4*)(Wa + (size_t)s * HH * HH);
    for (int i = g; i < (HH * HH) / 4; i += 192) ((float4*)wa_s)[i] = wsrc[i];
    __syncthreads();

    pool_store<NT>(outs_s, outs_s + (NT - 1) * HH, wa_s, sc, g_news + (size_t)sd * HH);
}

// ============================================================================
// Kernel 3: generic per-stock GRU + pool; single staging phase
// ============================================================================
template <int IN, int STEPS, int SRC>
__global__ __launch_bounds__(192) void k_gru_pool(
    const float* __restrict__ xin,
    const float* __restrict__ Wih, const float* __restrict__ Whh,
    const float* __restrict__ bih, const float* __restrict__ bhh,
    const float* __restrict__ Wa)
{
    extern __shared__ float dyn[];
    float* whh_s = dyn;                                     // WHS_ELEMS
    float* wih_s = whh_s + WHS_ELEMS;                       // WHS_ELEMS if IN==HH else 0
    float* gis   = wih_s + (IN == HH ? WHS_ELEMS : 0);      // STEPS*GG
    float* outs  = gis + STEPS * GG;                        // STEPS*HH
    float* wa_s  = outs + STEPS * HH;                       // HH*HH
    float* xs    = wa_s + HH * HH;                          // STEPS*IN
    float* hs    = xs + STEPS * IN;                         // HH
    float* ghs   = hs + HH;                                 // GG
    float* sc    = ghs + GG;                                // 32

    const int s = blockIdx.x;
    const int g = threadIdx.x;

    const float* xb = (SRC == 1) ? (g_news + (size_t)s * ND * HH)
                                 : (xin + (size_t)s * STEPS * IN);
    const float bh = bhh[s * GG + g];
    const float bi = bih[s * GG + g];

    // ---- single staging phase ----
    for (int i = g; i < STEPS * IN; i += 192) xs[i] = xb[i];
    {
        const float4* src = (const float4*)(Wa + (size_t)s * HH * HH);
        for (int i = g; i < (HH * HH) / 4; i += 192) ((float4*)wa_s)[i] = src[i];
    }
    stage_w(Whh + (size_t)s * GG * HH, whh_s, g, 192);
    if (IN == HH) stage_w(Wih + (size_t)s * GG * IN, wih_s, g, 192);
    float wi[IN <= 4 ? IN : 1];
    if (IN != HH) {
        const float* wip = Wih + ((size_t)s * GG + g) * IN;
#pragma unroll
        for (int i = 0; i < IN; i++) wi[i] = wip[i];
    }
    if (g < HH) hs[g] = 0.f;
    __syncthreads();

    // ---- input projections ----
    if (IN == HH) {
        float acct[STEPS];
#pragma unroll
        for (int t = 0; t < STEPS; t++) acct[t] = bi;
#pragma unroll 4
        for (int i = 0; i < IN; i++) {
            const float w = wih_s[g * WHS_PAD + i];
#pragma unroll
            for (int t = 0; t < STEPS; t++) acct[t] = fmaf(w, xs[t * IN + i], acct[t]);
        }
#pragma unroll
        for (int t = 0; t < STEPS; t++) gis[t * GG + g] = acct[t];
    } else {
#pragma unroll
        for (int t = 0; t < STEPS; t++) {
            float gi = bi;
#pragma unroll
            for (int i = 0; i < IN; i++) gi = fmaf(wi[i], xs[t * IN + i], gi);
            gis[t * GG + g] = gi;
        }
    }
    __syncthreads();

    float wh[HH];
#pragma unroll
    for (int i = 0; i < HH; i++) wh[i] = whh_s[g * WHS_PAD + i];

    for (int t = 0; t < STEPS; t++) {
        float a0 = 0.f, a1 = 0.f, a2 = 0.f, a3 = 0.f;
#pragma unroll
        for (int i = 0; i < HH; i += 4) {
            a0 = fmaf(wh[i + 0], hs[i + 0], a0);
            a1 = fmaf(wh[i + 1], hs[i + 1], a1);
            a2 = fmaf(wh[i + 2], hs[i + 2], a2);
            a3 = fmaf(wh[i + 3], hs[i + 3], a3);
        }
        ghs[g] = bh + ((a0 + a1) + (a2 + a3));
        __syncthreads();
        if (g < HH) {
            const float* git = gis + t * GG;
            const float r  = fsig(git[g] + ghs[g]);
            const float z  = fsig(git[HH + g] + ghs[HH + g]);
            const float n  = ftanh(git[2 * HH + g] + r * ghs[2 * HH + g]);
            const float hn = (1.f - z) * n + z * hs[g];
            hs[g] = hn;
            outs[t * HH + g] = hn;
        }
        __syncthreads();
    }
    float* dst = (SRC == 1 ? g_tvec : g_pvec) + s * HH;
    pool_store<STEPS>(outs, hs, wa_s, sc, dst);
}

// ============================================================================
// Kernel 4: bilinear fusion (float4, smem-staged vectors)
// ============================================================================
__global__ __launch_bounds__(128) void k_bilinear(
    const float* __restrict__ B, const float* __restrict__ bb)
{
    const int o = blockIdx.x, s = blockIdx.y;
    const int tid = threadIdx.x;
    __shared__ float tv_s[HH], pv_s[HH];
    if (tid < HH) { tv_s[tid] = g_tvec[s * HH + tid]; pv_s[tid] = g_pvec[s * HH + tid]; }
    __syncthreads();

    const float* Bp = B + ((size_t)s * HH + o) * HH * HH;
    float acc = 0.f;
#pragma unroll
    for (int it = 0; it < 8; it++) {
        const int k4 = (it * 128 + tid) * 4;
        const float4 v = *(const float4*)(Bp + k4);
        const int i = k4 >> 6, j = k4 & 63;
        float p = pv_s[j] * v.x;
        p = fmaf(pv_s[j + 1], v.y, p);
        p = fmaf(pv_s[j + 2], v.z, p);
        p = fmaf(pv_s[j + 3], v.w, p);
        acc = fmaf(tv_s[i], p, acc);
    }
    __shared__ float red[128];
    red[tid] = acc;
    __syncthreads();
    for (int st2 = 64; st2; st2 >>= 1) {
        if (tid < st2) red[tid] += red[tid + st2];
        __syncthreads();
    }
    if (tid == 0) g_feat[s * HH + o] = ftanh(red[0] + bb[s * HH + o]);
}

// ============================================================================
// Kernel 5: GAT head projection
// ============================================================================
__global__ __launch_bounds__(64) void k_gat_proj(
    const float* __restrict__ gatW, const float* __restrict__ gatA)
{
    const int s = blockIdx.x, nh = blockIdx.y;
    const int j = threadIdx.x;
    const float* Wp = gatW + (size_t)nh * HH * HH;
    const float* x  = g_feat + s * HH;
    float acc = 0.f;
#pragma unroll 8
    for (int i = 0; i < HH; i++) acc = fmaf(x[i], Wp[i * HH + j], acc);
    g_hgat[((size_t)nh * NS + s) * HH + j] = acc;

    __shared__ float r1[64], r2[64];
    r1[j] = acc * gatA[nh * 2 * HH + j];
    r2[j] = acc * gatA[nh * 2 * HH + HH + j];
    __syncthreads();
    if (j < 32) {
        float v1 = r1[j] + r1[j + 32];
        float v2 = r2[j] + r2[j + 32];
#pragma unroll
        for (int o = 16; o; o >>= 1) {
            v1 += __shfl_xor_sync(0xffffffffu, v1, o);
            v2 += __shfl_xor_sync(0xffffffffu, v2, o);
        }
        if (j == 0) { g_f1[nh * NS + s] = v1; g_f2[nh * NS + s] = v2; }
    }
}

// ============================================================================
// Kernel 6: GAT masked attention + elu (warp-parallel softmax)
// ============================================================================
__global__ __launch_bounds__(128) void k_gat_attn(const float* __restrict__ adj)
{
    const int s = blockIdx.x, nh = blockIdx.y;
    const int tid = threadIdx.x;
    __shared__ float att[NS];
    __shared__ float sinv;
    const float f1v = g_f1[nh * NS + s];
    if (tid < NS) {
        float v = f1v + g_f2[nh * NS + tid];
        v = (v >= 0.f) ? v : 0.2f * v;
        att[tid] = (adj[s * NS + tid] > 0.f) ? v : -9e15f;
    }
    __syncthreads();
    if (tid < 32) {
        float m = -3.4e38f;
        for (int t = tid; t < NS; t += 32) m = fmaxf(m, att[t]);
#pragma unroll
        for (int o = 16; o; o >>= 1) m = fmaxf(m, __shfl_xor_sync(0xffffffffu, m, o));
        float su = 0.f;
        for (int t = tid; t < NS; t += 32) {
            const float e = fexp(att[t] - m);
            att[t] = e;
            su += e;
        }
#pragma unroll
        for (int o = 16; o; o >>= 1) su += __shfl_xor_sync(0xffffffffu, su, o);
        if (tid == 0) sinv = 1.f / su;
    }
    __syncthreads();
    if (tid < HH) {
        float acc = 0.f;
        for (int t = 0; t < NS; t++)
            acc = fmaf(att[t], g_hgat[((size_t)nh * NS + t) * HH + tid], acc);
        acc = felu(acc * sinv);
        g_x2[(size_t)s * (NHD * HH) + nh * HH + tid] = acc;
    }
}

// ============================================================================
// Kernel 7: final — out-layer GAT, blend, double softmax, loss. One block.
// ============================================================================
__global__ __launch_bounds__(128) void k_final(
    const float* __restrict__ blW, const float* __restrict__ blb,
    const float* __restrict__ outW, const float* __restrict__ outA,
    const float* __restrict__ adj, const int* __restrict__ label,
    float* __restrict__ out, int out_size)
{
    __shared__ float h2[NS][2];
    __shared__ float f1s[NS], f2s[NS];
    __shared__ float o1[NS][2];
    __shared__ float adj_s[NS * NS];
    __shared__ float red[128];
    const int tid  = threadIdx.x;
    const int warp = tid >> 5;
    const int lane = tid & 31;

    for (int i = tid; i < NS * NS; i += 128) adj_s[i] = adj[i];

    for (int s = warp; s < NS; s += 4) {
        const float* xr = g_x2 + (size_t)s * NHD * HH;
        float a0 = 0.f, a1 = 0.f;
        for (int k = lane; k < NHD * HH; k += 32) {
            const float xv = xr[k];
            a0 = fmaf(xv, outW[2 * k + 0], a0);
            a1 = fmaf(xv, outW[2 * k + 1], a1);
        }
        const float* fr = g_feat + s * HH;
        float b0 = 0.f, b1 = 0.f;
        for (int k = lane; k < HH; k += 32) {
            const float fv = fr[k];
            b0 = fmaf(fv, blW[2 * k + 0], b0);
            b1 = fmaf(fv, blW[2 * k + 1], b1);
        }
#pragma unroll
        for (int o = 16; o; o >>= 1) {
            a0 += __shfl_xor_sync(0xffffffffu, a0, o);
            a1 += __shfl_xor_sync(0xffffffffu, a1, o);
            b0 += __shfl_xor_sync(0xffffffffu, b0, o);
            b1 += __shfl_xor_sync(0xffffffffu, b1, o);
        }
        if (lane == 0) {
            h2[s][0] = a0; h2[s][1] = a1;
            f1s[s] = a0 * outA[0] + a1 * outA[1];
            f2s[s] = a0 * outA[2] + a1 * outA[3];
            o1[s][0] = ftanh(b0 + blb[0]);
            o1[s][1] = ftanh(b1 + blb[1]);
        }
    }
    __syncthreads();

    const int off = (out_size > 200) ? (out_size - 200) : 0;
    float lsum = 0.f;
    for (int s = tid; s < NS; s += 128) {
        float m = -3.4e38f;
        for (int t = 0; t < NS; t++) {
            float v = f1s[s] + f2s[t];
            v = (v >= 0.f) ? v : 0.2f * v;
            v = (adj_s[s * NS + t] > 0.f) ? v : -9e15f;
            m = fmaxf(m, v);
        }
        float su = 0.f, a0 = 0.f, a1 = 0.f;
        for (int t = 0; t < NS; t++) {
            float v = f1s[s] + f2s[t];
            v = (v >= 0.f) ? v : 0.2f * v;
            v = (adj_s[s * NS + t] > 0.f) ? v : -9e15f;
            const float e = fexp(v - m);
            su += e;
            a0 = fmaf(e, h2[t][0], a0);
            a1 = fmaf(e, h2[t][1], a1);
        }
        a0 /= su; a1 /= su;
        a0 = felu(a0);
        a1 = felu(a1);
        const float z0 = a0 + o1[s][0];
        const float z1 = a1 + o1[s][1];
        const float zm = fmaxf(z0, z1);
        const float e0 = fexp(z0 - zm), e1 = fexp(z1 - zm);
        const float p0 = e0 / (e0 + e1), p1 = e1 / (e0 + e1);
        if (out_size >= 200) { out[off + 2 * s] = p0; out[off + 2 * s + 1] = p1; }
        const float pm  = fmaxf(p0, p1);
        const float lse = pm + logf(fexp(p0 - pm) + fexp(p1 - pm));
        const float chosen = (label[s] == 0) ? p0 : p1;
        lsum += (lse - chosen);
    }
    red[tid] = lsum;
    __syncthreads();
    for (int st2 = 64; st2; st2 >>= 1) {
        if (tid < st2) red[tid] += red[tid + st2];
        __syncthreads();
    }
    if (tid == 0 && (out_size == 1 || out_size > 200)) out[0] = red[0] * (1.f / NS);
}

// ============================================================================
extern "C" void kernel_launch(void* const* d_in, const int* in_sizes, int n_in,
                              void* d_out, int out_size)
{
    (void)in_sizes;
    const float* text  = (const float*)d_in[0];
    const float* price = (const float*)d_in[1];
    const int*   label = (const int*)d_in[2];
    const float* adj   = (const float*)d_in[3];
    const int wb = n_in - 23;
    const float* pg_Wih = (const float*)d_in[wb + 0];
    const float* pg_Whh = (const float*)d_in[wb + 1];
    const float* pg_bih = (const float*)d_in[wb + 2];
    const float* pg_bhh = (const float*)d_in[wb + 3];
    const float* pa_W   = (const float*)d_in[wb + 4];
    const float* tg_Wih = (const float*)d_in[wb + 5];
    const float* tg_Whh = (const float*)d_in[wb + 6];
    const float* tg_bih = (const float*)d_in[wb + 7];
    const float* tg_bhh = (const float*)d_in[wb + 8];
    const float* ta_W   = (const float*)d_in[wb + 9];
    const float* sg_Wih = (const float*)d_in[wb + 10];
    const float* sg_Whh = (const float*)d_in[wb + 11];
    const float* sg_bih = (const float*)d_in[wb + 12];
    const float* sg_bhh = (const float*)d_in[wb + 13];
    const float* sa_W   = (const float*)d_in[wb + 14];
    const float* bil_B  = (const float*)d_in[wb + 15];
    const float* bil_b  = (const float*)d_in[wb + 16];
    const float* bl_W   = (const float*)d_in[wb + 17];
    const float* bl_b   = (const float*)d_in[wb + 18];
    const float* gat_W  = (const float*)d_in[wb + 19];
    const float* gat_a  = (const float*)d_in[wb + 20];
    const float* out_W  = (const float*)d_in[wb + 21];
    const float* out_a  = (const float*)d_in[wb + 22];

    const int smem_gru64 = (2 * WHS_ELEMS + ND * GG + ND * HH + HH * HH + ND * HH + HH + GG + 32) * 4;
    const int smem_gru3  = (WHS_ELEMS + ND * GG + ND * HH + HH * HH + ND * FP + HH + GG + 32) * 4;

    static bool smem_set = false;
    if (!smem_set) {
        cudaFuncSetAttribute(k_text_gemm_bf16,
                             cudaFuncAttributeMaxDynamicSharedMemorySize, GEMM_SMEM_BYTES);
        cudaFuncSetAttribute(k_text_rec_b,
                             cudaFuncAttributeMaxDynamicSharedMemorySize, TRB_SMEM);
        cudaFuncSetAttribute((const void*)k_gru_pool<HH, ND, 1>,
                             cudaFuncAttributeMaxDynamicSharedMemorySize, smem_gru64);
        cudaFuncSetAttribute((const void*)k_gru_pool<FP, ND, 0>,
                             cudaFuncAttributeMaxDynamicSharedMemorySize, smem_gru3);
        smem_set = true;
    }

    // 1) bf16 tensor-core batched GEMM: text GRU input projections (bf16 out)
    k_text_gemm_bf16<<<dim3(5, NS), 256, GEMM_SMEM_BYTES>>>(text, tg_Wih, tg_bih);
    // price path (independent)
    k_gru_pool<FP, ND, 0><<<NS, 192, smem_gru3>>>(price, pg_Wih, pg_Whh, pg_bih, pg_bhh, pa_W);
    // 2a) batched text GRU recurrences (20 days/block) -> g_outs
    k_text_rec_b<<<NS, 192, TRB_SMEM>>>(tg_Whh, tg_bhh);
    // 2b) text attention pooling -> g_news
    k_text_pool<<<NS * ND, 192>>>(ta_W);
    // 3) day-sequence GRU over g_news + pool -> g_tvec
    k_gru_pool<HH, ND, 1><<<NS, 192, smem_gru64>>>(nullptr, sg_Wih, sg_Whh, sg_bih, sg_bhh, sa_W);
    // 4) bilinear fusion -> g_feat
    k_bilinear<<<dim3(HH, NS), 128>>>(bil_B, bil_b);
    // 5) GAT heads
    k_gat_proj<<<dim3(NS, NHD), 64>>>(gat_W, gat_a);
    k_gat_attn<<<dim3(NS, NHD), 128>>>(adj);
    // 6) output GAT layer + blend + softmax + loss
    k_final<<<1, 128>>>(bl_W, bl_b, out_W, out_a, adj, label, (float*)d_out, out_size);
}